// round 10
// baseline (speedup 1.0000x reference)
#include <cuda_runtime.h>
#include <cuda_bf16.h>
#include <math.h>
#include <stdint.h>

#define NN 170
#define NKP 176            // padded node dim (K of spatial GEMM, multiple of 16)
#define NROWP 192          // padded L rows (3 x 64 col tiles)
#define TT 12
#define BB 32
#define DD 120
#define HH 8
#define HD 15
#define FF 2048
#define BT (BB*TT)          // 384
#define MTOK (BB*TT*NN)     // 65280 = 510*128
#define MSP (BT*DD)         // 46080 = 360*128
#define XK 368              // padded xcat K (360 -> 368)

#define FLAG_BIAS  1
#define FLAG_RELU  2
#define FLAG_T2    4        // epilogue: v = 2*acc - (Xh+Xl)

// ------------------------- static device scratch (zero-initialized) --------
__device__ float g_A[3*NN*NN];
__device__ float g_rs0[3*NN];
__device__ float g_rs1[3*NN];

__device__ __align__(16) __nv_bfloat16 g_Lh[3*NROWP*NKP];
__device__ __align__(16) __nv_bfloat16 g_Ll[3*NROWP*NKP];
__device__ __align__(16) __nv_bfloat16 g_xth[(size_t)MSP*NKP];
__device__ __align__(16) __nv_bfloat16 g_xtl[(size_t)MSP*NKP];
__device__ __align__(16) __nv_bfloat16 g_t1h[(size_t)3*MSP*NKP];   // per-branch
__device__ __align__(16) __nv_bfloat16 g_t1l[(size_t)3*MSP*NKP];
__device__ __align__(16) __nv_bfloat16 g_xcath[(size_t)3*MTOK*XK]; // per-branch
__device__ __align__(16) __nv_bfloat16 g_xcatl[(size_t)3*MTOK*XK];
__device__ __align__(16) __nv_bfloat16 g_oah[(size_t)MTOK*128];
__device__ __align__(16) __nv_bfloat16 g_oal[(size_t)MTOK*128];
__device__ __align__(16) __nv_bfloat16 g_o1h[(size_t)MTOK*128];
__device__ __align__(16) __nv_bfloat16 g_o1l[(size_t)MTOK*128];
__device__ __align__(16) __nv_bfloat16 g_hidh[(size_t)MTOK*FF];
__device__ __align__(16) __nv_bfloat16 g_hidl[(size_t)MTOK*FF];
// B-operand weights, rows padded to tile boundary
__device__ __align__(16) __nv_bfloat16 g_wqh[3*128*XK];
__device__ __align__(16) __nv_bfloat16 g_wql[3*128*XK];
__device__ __align__(16) __nv_bfloat16 g_owh[128*128];
__device__ __align__(16) __nv_bfloat16 g_owl[128*128];
__device__ __align__(16) __nv_bfloat16 g_w1h[(size_t)FF*128];
__device__ __align__(16) __nv_bfloat16 g_w1l[(size_t)FF*128];
__device__ __align__(16) __nv_bfloat16 g_w2h[(size_t)128*FF];
__device__ __align__(16) __nv_bfloat16 g_w2l[(size_t)128*FF];
__device__ float g_qkv[(size_t)3*MTOK*DD];
__device__ float g_oproj[(size_t)MTOK*DD];
__device__ float g_out1f[(size_t)MTOK*DD];
__device__ float g_ffnf[(size_t)MTOK*DD];

// ------------------------- helpers -------------------------
__device__ __forceinline__ void bsplit(float v, __nv_bfloat16 &h, __nv_bfloat16 &l) {
    h = __float2bfloat16_rn(v);
    l = __float2bfloat16_rn(v - __bfloat162float(h));
}
__device__ __forceinline__ uint32_t smem_u32(const void* p) {
    uint32_t a;
    asm("{ .reg .u64 t; cvta.to.shared.u64 t, %1; cvt.u32.u64 %0, t; }" : "=r"(a) : "l"(p));
    return a;
}
__device__ __forceinline__ void cpa16(uint32_t dst, const void* src) {
    asm volatile("cp.async.cg.shared.global [%0], [%1], 16;"
                 :: "r"(dst), "l"(src) : "memory");
}
__device__ __forceinline__ void cp_commit() {
    asm volatile("cp.async.commit_group;" ::: "memory");
}
__device__ __forceinline__ void cp_wait0() {
    asm volatile("cp.async.wait_group 0;" ::: "memory");
}
__device__ __forceinline__ void ldm4(uint32_t (&d)[4], uint32_t addr) {
    asm volatile("ldmatrix.sync.aligned.m8n8.x4.shared.b16 {%0,%1,%2,%3}, [%4];"
                 : "=r"(d[0]), "=r"(d[1]), "=r"(d[2]), "=r"(d[3]) : "r"(addr));
}
__device__ __forceinline__ void mma16816(float (&c)[4], const uint32_t (&a)[4],
                                         uint32_t b0, uint32_t b1) {
    asm volatile("mma.sync.aligned.m16n8k16.row.col.f32.bf16.bf16.f32 "
                 "{%0,%1,%2,%3}, {%4,%5,%6,%7}, {%8,%9}, {%0,%1,%2,%3};"
                 : "+f"(c[0]), "+f"(c[1]), "+f"(c[2]), "+f"(c[3])
                 : "r"(a[0]), "r"(a[1]), "r"(a[2]), "r"(a[3]), "r"(b0), "r"(b1));
}

// ------------------------- HMMA bf16x3 GEMM (BK=16, cp.async, 1 sync/chunk) -
// D[M,N] = sum_k A[m,k]*B[n,k]; A: M x K (lda), B rows padded to tile bound (ldb).
// K%16==0, M%128==0. Batched over blockIdx.z via strides (0 = shared).
template<int BN>
__global__ __launch_bounds__(256, 2) void hmma_bf16x3(
        const __nv_bfloat16* __restrict__ Ah, const __nv_bfloat16* __restrict__ Al, int lda,
        const __nv_bfloat16* __restrict__ Bh, const __nv_bfloat16* __restrict__ Bl, int ldb,
        int K,
        float* __restrict__ Cf, __nv_bfloat16* __restrict__ Ch, __nv_bfloat16* __restrict__ Cl,
        int ldc, int Nout,
        const float* __restrict__ bias, int flags,
        const __nv_bfloat16* __restrict__ Xh, const __nv_bfloat16* __restrict__ Xl,
        __nv_bfloat16* __restrict__ XCh, __nv_bfloat16* __restrict__ XCl, int xoff,
        long astride, long bstride, long cstride, int biasstride, long xcstride)
{
    constexpr int A16 = 128*3;              // 16B units per A matrix (48B row pitch)
    constexpr int B16 = BN*3;
    constexpr int STAGE_BYTES = (2*A16 + 2*B16) * 16;
    constexpr int NB = (BN*4)/256;
    constexpr int WN = BN / 2;
    constexpr int NP = WN / 16;
    constexpr int BH = BN * 2;

    extern __shared__ __align__(16) char smem[];
    const uint32_t sbase = smem_u32(smem);
    const int tid = threadIdx.x;
    const int lane = tid & 31;
    const int wid = tid >> 5;
    const int wm = wid & 3, wn = wid >> 2;
    const int row0 = blockIdx.x * 128;
    const int col0 = blockIdx.y * BN;
    {   // batch offsets
        const int bz = blockIdx.z;
        Ah += (size_t)bz * astride;  Al += (size_t)bz * astride;
        Bh += (size_t)bz * bstride;  Bl += (size_t)bz * bstride;
        if (Cf) Cf += (size_t)bz * cstride;
        if (Ch) { Ch += (size_t)bz * cstride; Cl += (size_t)bz * cstride; }
        if (bias) bias += bz * biasstride;
        if (XCh) { XCh += (size_t)bz * xcstride; XCl += (size_t)bz * xcstride; }
    }

    float acc[2][2*NP][4];
    #pragma unroll
    for (int i = 0; i < 2; i++)
        #pragma unroll
        for (int j = 0; j < 2*NP; j++)
            #pragma unroll
            for (int e = 0; e < 4; e++) acc[i][j][e] = 0.f;

    const int arow = wm*32 + (lane & 15);
    const int akc  = lane >> 4;
    const uint32_t aoff = (uint32_t)(arow*3 + akc) * 16;
    const int brow = wn*WN + (lane & 7) + ((lane >> 4) & 1)*8;
    const int bkc  = (lane >> 3) & 1;
    const uint32_t boff = (uint32_t)(2*A16 + brow*3 + bkc) * 16;

    auto cpload = [&](int c, int st) {
        const int k0 = c * 16;
        const uint32_t sb = sbase + (uint32_t)st * STAGE_BYTES;
        #pragma unroll
        for (int t = 0; t < 2; t++) {
            int i = tid + t*256;
            int mat = i >> 8, u = i & 255, r = u >> 1, kc = u & 1;
            cpa16(sb + (uint32_t)(mat*A16 + r*3 + kc)*16,
                  (mat ? Al : Ah) + (size_t)(row0 + r)*lda + k0 + kc*8);
        }
        #pragma unroll
        for (int t = 0; t < NB; t++) {
            int i = tid + t*256;
            int mat = i / BH, u = i % BH, r = u >> 1, kc = u & 1;
            cpa16(sb + (uint32_t)(2*A16 + mat*B16 + r*3 + kc)*16,
                  (mat ? Bl : Bh) + (size_t)(col0 + r)*ldb + k0 + kc*8);
        }
        cp_commit();
    };

    const int nch = K >> 4;
    cpload(0, 0);

    for (int c = 0; c < nch; c++) {
        cp_wait0();                      // stage (c&1) arrived
        __syncthreads();                 // publish; all compute(c-1) done
        if (c + 1 < nch) cpload(c + 1, (c + 1) & 1);  // overwrites stage read by c-1: safe

        const uint32_t sb = sbase + (uint32_t)(c & 1) * STAGE_BYTES;
        uint32_t ahf[2][4], alf[2][4];
        #pragma unroll
        for (int mi = 0; mi < 2; mi++) {
            uint32_t ad = sb + aoff + (uint32_t)mi * 768;
            ldm4(ahf[mi], ad);
            ldm4(alf[mi], ad + A16*16);
        }
        uint32_t bhf[NP][4], blf[NP][4];
        #pragma unroll
        for (int np = 0; np < NP; np++) {
            uint32_t bd = sb + boff + (uint32_t)np * 768;
            ldm4(bhf[np], bd);
            ldm4(blf[np], bd + B16*16);
        }
        #pragma unroll
        for (int mi = 0; mi < 2; mi++)
            #pragma unroll
            for (int np = 0; np < NP; np++)
                #pragma unroll
                for (int hf = 0; hf < 2; hf++) {
                    int na = np*2 + hf;
                    mma16816(acc[mi][na], ahf[mi], bhf[np][2*hf], bhf[np][2*hf+1]);
                    mma16816(acc[mi][na], ahf[mi], blf[np][2*hf], blf[np][2*hf+1]);
                    mma16816(acc[mi][na], alf[mi], bhf[np][2*hf], bhf[np][2*hf+1]);
                }
    }

    // ---- epilogue
    float* smemf = (float*)smem;   // BN x 128 fp32 staging (pitch 132), spatial only
    if (XCh) __syncthreads();      // all ldmatrix reads of final stage complete

    const int lr = lane >> 2, lc = (lane & 3) * 2;
    #pragma unroll
    for (int mi = 0; mi < 2; mi++) {
        #pragma unroll
        for (int na = 0; na < 2*NP; na++) {
            int gr0 = row0 + wm*32 + mi*16 + lr;
            int gc0l = wn*WN + na*8 + lc;
            #pragma unroll
            for (int e = 0; e < 4; e++) {
                int gr = gr0 + (e >> 1) * 8;
                int gcl = gc0l + (e & 1);
                int gc = col0 + gcl;
                if (gc >= Nout) continue;
                float v = acc[mi][na][e];
                size_t ci = (size_t)gr * ldc + gc;
                if (flags & FLAG_T2)
                    v = 2.f*v - (__bfloat162float(Xh[ci]) + __bfloat162float(Xl[ci]));
                if (flags & FLAG_BIAS) v += bias[gc];
                if (flags & FLAG_RELU) v = fmaxf(v, 0.f);
                if (Cf) Cf[ci] = v;
                if (Ch) { __nv_bfloat16 h, l; bsplit(v, h, l); Ch[ci] = h; Cl[ci] = l; }
                if (XCh) smemf[gcl*132 + (gr - row0)] = v;
            }
        }
    }

    if (XCh) {
        __syncthreads();
        for (int i = tid; i < BN*128; i += 256) {
            int gcl = i >> 7, grl = i & 127;
            int n = col0 + gcl;
            if (n >= Nout) continue;
            float v = smemf[gcl*132 + grl];
            int gr = row0 + grl;
            int bt = gr / DD, d = gr - bt*DD;
            __nv_bfloat16 h, l; bsplit(v, h, l);
            size_t idx = ((size_t)bt*NN + n)*XK + xoff + d;
            XCh[idx] = h; XCl[idx] = l;
        }
    }
}

// ------------------------- graph learning -------------------------
__global__ void gk1(const float* __restrict__ w1, const float* __restrict__ w2,
                    const float* __restrict__ beta, const float* __restrict__ cw,
                    const float* __restrict__ cb, const float* __restrict__ adj) {
    int r = blockIdx.x, br = blockIdx.y;
    __shared__ float w1r[DD], w2r[DD];
    __shared__ float red[256];
    const float* W1 = w1 + (size_t)br*NN*DD;
    const float* W2 = w2 + (size_t)br*NN*DD;
    for (int i = threadIdx.x; i < DD; i += blockDim.x) { w1r[i] = W1[r*DD+i]; w2r[i] = W2[r*DD+i]; }
    __syncthreads();
    float cw0 = cw[br*2+0], cw1 = cw[br*2+1], cbv = cb[br];
    float mysum = 0.f;
    for (int c = threadIdx.x; c < NN; c += blockDim.x) {
        const float* w1c = W1 + c*DD;
        const float* w2c = W2 + c*DD;
        float d1 = 0.f, d2 = 0.f;
        for (int e = 0; e < DD; e++) { d1 += w1r[e]*w2c[e]; d2 += w2r[e]*w1c[e]; }
        float nw = d1 - d2;
        if (r == c) nw += beta[br*NN + r];
        nw = fmaxf(nw, 0.f);
        float ad = adj[r*NN + c];
        float gate = 1.f / (1.f + expf(-(cw0*nw + cw1*ad + cbv)));
        float a = gate*nw + (1.f - gate)*ad;
        g_A[(size_t)br*NN*NN + (size_t)r*NN + c] = a;
        mysum += a;
    }
    red[threadIdx.x] = mysum; __syncthreads();
    for (int s = 128; s > 0; s >>= 1) { if (threadIdx.x < s) red[threadIdx.x] += red[threadIdx.x+s]; __syncthreads(); }
    if (threadIdx.x == 0) g_rs0[br*NN + r] = red[0];
}
__global__ void gk2() {
    int r = blockIdx.x, br = blockIdx.y;
    __shared__ float red[256];
    float dr = rsqrtf(g_rs0[br*NN + r]);
    const float eps = 0.5f / (float)NN;
    float mysum = 0.f;
    for (int c = threadIdx.x; c < NN; c += blockDim.x) {
        float dc = rsqrtf(g_rs0[br*NN + c]);
        size_t idx = (size_t)br*NN*NN + (size_t)r*NN + c;
        float a = fmaxf(dr * g_A[idx] * dc - eps, 0.f);
        g_A[idx] = a; mysum += a;
    }
    red[threadIdx.x] = mysum; __syncthreads();
    for (int s = 128; s > 0; s >>= 1) { if (threadIdx.x < s) red[threadIdx.x] += red[threadIdx.x+s]; __syncthreads(); }
    if (threadIdx.x == 0) g_rs1[br*NN + r] = red[0];
}
__global__ void gk3() {
    int r = blockIdx.x, br = blockIdx.y;
    __shared__ float red[256];
    float dr = rsqrtf(g_rs1[br*NN + r]);
    float mysum = 0.f;
    for (int c = threadIdx.x; c < NN; c += blockDim.x) {
        float dc = rsqrtf(g_rs1[br*NN + c]);
        size_t idx = (size_t)br*NN*NN + (size_t)r*NN + c;
        float g = dr * g_A[idx] * dc;
        g_A[idx] = g; mysum += g;
    }
    red[threadIdx.x] = mysum; __syncthreads();
    for (int s = 128; s > 0; s >>= 1) { if (threadIdx.x < s) red[threadIdx.x] += red[threadIdx.x+s]; __syncthreads(); }
    if (threadIdx.x == 0) g_rs0[br*NN + r] = red[0];
}
__global__ void gk4() {
    int r = blockIdx.x, br = blockIdx.y;
    float er = rsqrtf(g_rs0[br*NN + r]);
    for (int c = threadIdx.x; c < NKP; c += blockDim.x) {
        float L = 0.f;
        if (c < NN) {
            float ec = rsqrtf(g_rs0[br*NN + c]);
            L = ((r == c) ? 1.f : 0.f) - er * g_A[(size_t)br*NN*NN + (size_t)r*NN + c] * ec;
        }
        __nv_bfloat16 h, l; bsplit(L, h, l);
        size_t idx = (size_t)br*NROWP*NKP + (size_t)r*NKP + c;
        g_Lh[idx] = h; g_Ll[idx] = l;
    }
}

// ------------------------- layout / split kernels -------------------------
__global__ void xsplitT(const float* __restrict__ x) {
    __shared__ float s[64*121];
    int bt = blockIdx.x;
    for (int n0 = 0; n0 < NN; n0 += 64) {
        int nrows = (NN - n0 < 64) ? (NN - n0) : 64;
        for (int i = threadIdx.x; i < nrows*DD; i += 256) {
            int nn = i / DD, d = i - nn*DD;
            s[nn*121 + d] = x[((size_t)bt*NN + n0 + nn)*DD + d];
        }
        __syncthreads();
        for (int i = threadIdx.x; i < DD*64; i += 256) {
            int d = i >> 6, nn = i & 63;
            int n = n0 + nn;
            if (nn < nrows) {
                __nv_bfloat16 h, l; bsplit(s[nn*121 + d], h, l);
                size_t idx = ((size_t)bt*DD + d)*NKP + n;
                g_xth[idx] = h; g_xtl[idx] = l;
            }
        }
        __syncthreads();
    }
}
// x -> cols [0,120) of all three branch xcat buffers
__global__ void pack_x(const float* __restrict__ x) {
    size_t r = blockIdx.x;
    int d = threadIdx.x;
    if (d < DD) {
        __nv_bfloat16 h, l; bsplit(x[r*DD + d], h, l);
        #pragma unroll
        for (int br = 0; br < 3; br++) {
            size_t idx = (size_t)br*MTOK*XK + r*XK + d;
            g_xcath[idx] = h;
            g_xcatl[idx] = l;
        }
    }
}
__global__ void wsplit(const float* __restrict__ src, __nv_bfloat16* __restrict__ dh,
                       __nv_bfloat16* __restrict__ dl, int K, int N, int ldk,
                       long src_bstride, long dst_bstride) {
    int n = blockIdx.x;
    int br = blockIdx.y;
    src += (size_t)br * src_bstride;
    dh  += (size_t)br * dst_bstride;
    dl  += (size_t)br * dst_bstride;
    for (int k = threadIdx.x; k < K; k += blockDim.x) {
        __nv_bfloat16 h, l; bsplit(src[(size_t)k*N + n], h, l);
        dh[(size_t)n*ldk + k] = h;
        dl[(size_t)n*ldk + k] = l;
    }
}

// ------------------------- attention -------------------------
__global__ void attn_kernel(const float* __restrict__ q, const float* __restrict__ k,
                            const float* __restrict__ v) {
    int bn = blockIdx.x;
    int b = bn / NN, n = bn % NN;
    __shared__ float qs[TT][DD], ks[TT][DD], vs[TT][DD];
    for (int i = threadIdx.x; i < TT*DD; i += blockDim.x) {
        int t = i / DD, d = i % DD;
        size_t gi = (((size_t)(b*TT + t))*NN + n)*DD + d;
        qs[t][d] = q[gi]; ks[t][d] = k[gi]; vs[t][d] = v[gi];
    }
    __syncthreads();
    int tid = threadIdx.x;
    if (tid < HH*TT) {
        int h = tid / TT, qi = tid % TT;
        const float scale = rsqrtf((float)HD);
        float s[TT]; float mx = -1e30f;
        #pragma unroll
        for (int j = 0; j < TT; j++) {
            float acc = 0.f;
            #pragma unroll
            for (int e = 0; e < HD; e++) acc += qs[qi][h*HD+e] * ks[j][h*HD+e];
            acc *= scale; s[j] = acc; mx = fmaxf(mx, acc);
        }
        float sum = 0.f;
        #pragma unroll
        for (int j = 0; j < TT; j++) { s[j] = expf(s[j]-mx); sum += s[j]; }
        float inv = 1.f / sum;
        size_t orow = ((size_t)(b*TT + qi))*NN + n;
        #pragma unroll
        for (int e = 0; e < HD; e++) {
            float acc = 0.f;
            #pragma unroll
            for (int j = 0; j < TT; j++) acc += s[j] * vs[j][h*HD+e];
            __nv_bfloat16 hh, ll; bsplit(acc*inv, hh, ll);
            g_oah[orow*128 + h*HD + e] = hh;
            g_oal[orow*128 + h*HD + e] = ll;
        }
    }
}

// ------------------------- residual + layernorm -------------------------
__global__ void ln_kernel(const float* __restrict__ xa, const float* __restrict__ xb,
                          const float* __restrict__ gg, const float* __restrict__ bb,
                          float* __restrict__ outp, __nv_bfloat16* __restrict__ oh,
                          __nv_bfloat16* __restrict__ ol) {
    int warp = threadIdx.x >> 5, lane = threadIdx.x & 31;
    size_t m = (size_t)blockIdx.x * 4 + warp;
    if (m >= MTOK) return;
    size_t ia = m * DD;
    float v[4]; float s = 0.f;
    #pragma unroll
    for (int i = 0; i < 4; i++) {
        int d = lane + 32*i;
        float val = (d < DD) ? (xa[ia+d] + xb[ia+d]) : 0.f;
        v[i] = val; s += val;
    }
    #pragma unroll
    for (int o = 16; o > 0; o >>= 1) s += __shfl_xor_sync(0xffffffffu, s, o);
    float mean = s * (1.f / DD);
    float vsum = 0.f;
    #pragma unroll
    for (int i = 0; i < 4; i++) {
        int d = lane + 32*i;
        if (d < DD) { float df = v[i]-mean; vsum += df*df; }
    }
    #pragma unroll
    for (int o = 16; o > 0; o >>= 1) vsum += __shfl_xor_sync(0xffffffffu, vsum, o);
    float inv = rsqrtf(vsum * (1.f / DD) + 1e-5f);
    #pragma unroll
    for (int i = 0; i < 4; i++) {
        int d = lane + 32*i;
        if (d < DD) {
            float o = (v[i]-mean)*inv*gg[d] + bb[d];
            if (outp) outp[ia + d] = o;
            if (oh) { __nv_bfloat16 h, l; bsplit(o, h, l); oh[m*128 + d] = h; ol[m*128 + d] = l; }
        }
    }
}

// ------------------------- launch -------------------------
extern "C" void kernel_launch(void* const* d_in, const int* in_sizes, int n_in,
                              void* d_out, int out_size) {
    const float* x       = (const float*)d_in[0];
    const float* adj     = (const float*)d_in[1];
    const float* gl_beta = (const float*)d_in[2];
    const float* gl_w1   = (const float*)d_in[3];
    const float* gl_w2   = (const float*)d_in[4];
    const float* gl_cw   = (const float*)d_in[5];
    const float* gl_cb   = (const float*)d_in[6];
    const float* cheb_w  = (const float*)d_in[7];
    const float* cheb_b  = (const float*)d_in[8];
    const float* out_w   = (const float*)d_in[9];
    const float* out_b   = (const float*)d_in[10];
    const float* ff_w1   = (const float*)d_in[11];
    const float* ff_b1   = (const float*)d_in[12];
    const float* ff_w2   = (const float*)d_in[13];
    const float* ff_b2   = (const float*)d_in[14];
    const float* ln1_g   = (const float*)d_in[15];
    const float* ln1_b   = (const float*)d_in[16];
    const float* ln2_g   = (const float*)d_in[17];
    const float* ln2_b   = (const float*)d_in[18];
    float* outp = (float*)d_out;

    const int SMEM128 = 2 * (2*(128*3) + 2*(128*3)) * 16;   // 49152
    const int SMEM64  = 2 * (2*(128*3) + 2*(64*3)) * 16;    // 36864
    cudaFuncSetAttribute(hmma_bf16x3<128>, cudaFuncAttributeMaxDynamicSharedMemorySize, SMEM128);
    cudaFuncSetAttribute(hmma_bf16x3<64>,  cudaFuncAttributeMaxDynamicSharedMemorySize, SMEM64);

    __nv_bfloat16 *pLh, *pLl, *pxth, *pxtl, *pt1h, *pt1l;
    __nv_bfloat16 *pxch, *pxcl, *poah, *poal, *po1h, *po1l, *phh, *phl;
    __nv_bfloat16 *pwqh, *pwql, *powh, *powl, *pw1h, *pw1l, *pw2h, *pw2l;
    float *pqkv, *poproj, *pout1f, *pffnf;
    cudaGetSymbolAddress((void**)&pLh, g_Lh);   cudaGetSymbolAddress((void**)&pLl, g_Ll);
    cudaGetSymbolAddress((void**)&pxth, g_xth); cudaGetSymbolAddress((void**)&pxtl, g_xtl);
    cudaGetSymbolAddress((void**)&pt1h, g_t1h); cudaGetSymbolAddress((void**)&pt1l, g_t1l);
    cudaGetSymbolAddress((void**)&pxch, g_xcath); cudaGetSymbolAddress((void**)&pxcl, g_xcatl);
    cudaGetSymbolAddress((void**)&poah, g_oah); cudaGetSymbolAddress((void**)&poal, g_oal);
    cudaGetSymbolAddress((void**)&po1h, g_o1h); cudaGetSymbolAddress((void**)&po1l, g_o1l);
    cudaGetSymbolAddress((void**)&phh, g_hidh); cudaGetSymbolAddress((void**)&phl, g_hidl);
    cudaGetSymbolAddress((void**)&pwqh, g_wqh); cudaGetSymbolAddress((void**)&pwql, g_wql);
    cudaGetSymbolAddress((void**)&powh, g_owh); cudaGetSymbolAddress((void**)&powl, g_owl);
    cudaGetSymbolAddress((void**)&pw1h, g_w1h); cudaGetSymbolAddress((void**)&pw1l, g_w1l);
    cudaGetSymbolAddress((void**)&pw2h, g_w2h); cudaGetSymbolAddress((void**)&pw2l, g_w2l);
    cudaGetSymbolAddress((void**)&pqkv, g_qkv); cudaGetSymbolAddress((void**)&poproj, g_oproj);
    cudaGetSymbolAddress((void**)&pout1f, g_out1f); cudaGetSymbolAddress((void**)&pffnf, g_ffnf);

    // graph learning (launches 0-3)
    dim3 gG(NN, 3);
    gk1<<<gG, 256>>>(gl_w1, gl_w2, gl_beta, gl_cw, gl_cb, adj);
    gk2<<<gG, 256>>>();
    gk3<<<gG, 256>>>();
    gk4<<<gG, 256>>>();

    // launch 4: x transpose/split
    xsplitT<<<BT, 256>>>(x);

    const long t1s = (long)MSP*NKP;
    const long xcs = (long)MTOK*XK;
    const long Ls  = (long)NROWP*NKP;

    // launch 5: t1 = L_br @ x (all branches) -> t1_br (t-layout) + xcat_br[120..239]
    dim3 gsp(MSP/128, 3, 3);
    hmma_bf16x3<64><<<gsp, 256, SMEM64>>>(pxth, pxtl, NKP, pLh, pLl, NKP, NKP,
                                          nullptr, pt1h, pt1l, NKP, NN,
                                          nullptr, 0, nullptr, nullptr,
                                          pxch, pxcl, 120,
                                          0, Ls, t1s, 0, xcs);
    // launch 6: t2 = 2*(L_br @ t1_br) - x -> xcat_br[240..359]
    hmma_bf16x3<64><<<gsp, 256, SMEM64>>>(pt1h, pt1l, NKP, pLh, pLl, NKP, NKP,
                                          nullptr, nullptr, nullptr, NKP, NN,
                                          nullptr, FLAG_T2, pxth, pxtl,
                                          pxch, pxcl, 240,
                                          t1s, Ls, 0, 0, xcs);

    // prep that only QKV needs (overlappable with nothing, but off the critical profile slots)
    pack_x<<<MTOK, 128>>>(x);
    wsplit<<<dim3(120,3), 256>>>(cheb_w, pwqh, pwql, 360, 120, XK, (long)360*120, (long)128*XK);
    wsplit<<<dim3(120,1), 256>>>(out_w, powh, powl, 120, 120, 128, 0, 0);
    wsplit<<<dim3(FF,1),  256>>>(ff_w1, pw1h, pw1l, 120, FF, 128, 0, 0);
    wsplit<<<dim3(120,1), 256>>>(ff_w2, pw2h, pw2l, FF, 120, FF, 0, 0);

    // batched QKV: relu(xcat_br @ W_br + b_br)
    dim3 gqkv(MTOK/128, 1, 3);
    hmma_bf16x3<128><<<gqkv, 256, SMEM128>>>(pxch, pxcl, XK, pwqh, pwql, XK, XK,
                                             pqkv, nullptr, nullptr, DD, DD,
                                             cheb_b, FLAG_BIAS | FLAG_RELU,
                                             nullptr, nullptr, nullptr, nullptr, 0,
                                             xcs, (long)128*XK, (long)MTOK*DD, DD, 0);

    attn_kernel<<<BB*NN, 128>>>(pqkv, pqkv + (size_t)MTOK*DD, pqkv + (size_t)2*MTOK*DD);

    dim3 gch(MTOK/128, 1, 1);
    // output projection
    hmma_bf16x3<128><<<gch, 256, SMEM128>>>(poah, poal, 128, powh, powl, 128, 128,
                                            poproj, nullptr, nullptr, DD, DD,
                                            out_b, FLAG_BIAS, nullptr, nullptr,
                                            nullptr, nullptr, 0, 0, 0, 0, 0, 0);
    // LN1
    ln_kernel<<<MTOK/4, 128>>>(x, poproj, ln1_g, ln1_b, pout1f, po1h, po1l);

    // FFN1 -> bf16 h/l hidden
    dim3 gf1(MTOK/128, FF/128, 1);
    hmma_bf16x3<128><<<gf1, 256, SMEM128>>>(po1h, po1l, 128, pw1h, pw1l, 128, 128,
                                            nullptr, phh, phl, FF, FF,
                                            ff_b1, FLAG_BIAS | FLAG_RELU, nullptr, nullptr,
                                            nullptr, nullptr, 0, 0, 0, 0, 0, 0);
    // FFN2
    hmma_bf16x3<128><<<gch, 256, SMEM128>>>(phh, phl, FF, pw2h, pw2l, FF, FF,
                                            pffnf, nullptr, nullptr, DD, DD,
                                            ff_b2, FLAG_BIAS, nullptr, nullptr,
                                            nullptr, nullptr, 0, 0, 0, 0, 0, 0);
    // LN2 -> output
    ln_kernel<<<MTOK/4, 128>>>(pout1f, pffnf, ln2_g, ln2_b, outp, nullptr, nullptr);
}

// round 11
// speedup vs baseline: 1.0197x; 1.0197x over previous
#include <cuda_runtime.h>
#include <cuda_bf16.h>
#include <math.h>
#include <stdint.h>

#define NN 170
#define NKP 176            // padded node dim (K of spatial GEMM, multiple of 16)
#define NROWP 192          // padded L rows (3 x 64 col tiles)
#define TT 12
#define BB 32
#define DD 120
#define HH 8
#define HD 15
#define FF 2048
#define BT (BB*TT)          // 384
#define MTOK (BB*TT*NN)     // 65280 = 510*128
#define MSP (BT*DD)         // 46080 = 360*128
#define XK 368              // padded xcat K (360 -> 368)

#define FLAG_BIAS  1
#define FLAG_RELU  2
#define FLAG_T2    4        // epilogue: v = 2*acc - (Xh+Xl)

// ------------------------- static device scratch (zero-initialized) --------
__device__ float g_A[3*NN*NN];
__device__ float g_rs0[3*NN];
__device__ float g_rs1[3*NN];

__device__ __align__(16) __nv_bfloat16 g_Lh[3*NROWP*NKP];
__device__ __align__(16) __nv_bfloat16 g_Ll[3*NROWP*NKP];
__device__ __align__(16) __nv_bfloat16 g_xth[(size_t)MSP*NKP];
__device__ __align__(16) __nv_bfloat16 g_xtl[(size_t)MSP*NKP];
__device__ __align__(16) __nv_bfloat16 g_t1h[(size_t)3*MSP*NKP];   // per-branch
__device__ __align__(16) __nv_bfloat16 g_t1l[(size_t)3*MSP*NKP];
__device__ __align__(16) __nv_bfloat16 g_xcath[(size_t)3*MTOK*XK]; // per-branch
__device__ __align__(16) __nv_bfloat16 g_xcatl[(size_t)3*MTOK*XK];
__device__ __align__(16) __nv_bfloat16 g_oah[(size_t)MTOK*128];
__device__ __align__(16) __nv_bfloat16 g_oal[(size_t)MTOK*128];
__device__ __align__(16) __nv_bfloat16 g_o1h[(size_t)MTOK*128];
__device__ __align__(16) __nv_bfloat16 g_o1l[(size_t)MTOK*128];
__device__ __align__(16) __nv_bfloat16 g_hidh[(size_t)MTOK*FF];
__device__ __align__(16) __nv_bfloat16 g_hidl[(size_t)MTOK*FF];
// B-operand weights, rows padded to tile boundary
__device__ __align__(16) __nv_bfloat16 g_wqh[3*128*XK];
__device__ __align__(16) __nv_bfloat16 g_wql[3*128*XK];
__device__ __align__(16) __nv_bfloat16 g_owh[128*128];
__device__ __align__(16) __nv_bfloat16 g_owl[128*128];
__device__ __align__(16) __nv_bfloat16 g_w1h[(size_t)FF*128];
__device__ __align__(16) __nv_bfloat16 g_w1l[(size_t)FF*128];
__device__ __align__(16) __nv_bfloat16 g_w2h[(size_t)128*FF];
__device__ __align__(16) __nv_bfloat16 g_w2l[(size_t)128*FF];
__device__ float g_qkv[(size_t)3*MTOK*DD];
__device__ float g_oproj[(size_t)MTOK*DD];
__device__ float g_out1f[(size_t)MTOK*DD];
__device__ float g_ffnf[(size_t)MTOK*DD];

// ------------------------- helpers -------------------------
__device__ __forceinline__ void bsplit(float v, __nv_bfloat16 &h, __nv_bfloat16 &l) {
    h = __float2bfloat16_rn(v);
    l = __float2bfloat16_rn(v - __bfloat162float(h));
}
__device__ __forceinline__ uint32_t smem_u32(const void* p) {
    uint32_t a;
    asm("{ .reg .u64 t; cvta.to.shared.u64 t, %1; cvt.u32.u64 %0, t; }" : "=r"(a) : "l"(p));
    return a;
}
__device__ __forceinline__ void ldm4(uint32_t (&d)[4], uint32_t addr) {
    asm volatile("ldmatrix.sync.aligned.m8n8.x4.shared.b16 {%0,%1,%2,%3}, [%4];"
                 : "=r"(d[0]), "=r"(d[1]), "=r"(d[2]), "=r"(d[3]) : "r"(addr));
}
__device__ __forceinline__ void mma16816(float (&c)[4], const uint32_t (&a)[4],
                                         uint32_t b0, uint32_t b1) {
    asm volatile("mma.sync.aligned.m16n8k16.row.col.f32.bf16.bf16.f32 "
                 "{%0,%1,%2,%3}, {%4,%5,%6,%7}, {%8,%9}, {%0,%1,%2,%3};"
                 : "+f"(c[0]), "+f"(c[1]), "+f"(c[2]), "+f"(c[3])
                 : "r"(a[0]), "r"(a[1]), "r"(a[2]), "r"(a[3]), "r"(b0), "r"(b1));
}

// ------------------------- HMMA bf16x3 GEMM (BK=16, LDG double-buffer) -----
// D[M,N] = sum_k A[m,k]*B[n,k]; A: M x K (lda), B rows padded to tile bound (ldb).
// K%16==0, M%128==0. Batched over blockIdx.z via strides (0 = shared).
// swapxy: 0 -> row0=bx*128, col0=by*BN ; 1 -> row0=by*128, col0=bx*BN.
template<int BN>
__global__ __launch_bounds__(256) void hmma_bf16x3(
        const __nv_bfloat16* __restrict__ Ah, const __nv_bfloat16* __restrict__ Al, int lda,
        const __nv_bfloat16* __restrict__ Bh, const __nv_bfloat16* __restrict__ Bl, int ldb,
        int K,
        float* __restrict__ Cf, __nv_bfloat16* __restrict__ Ch, __nv_bfloat16* __restrict__ Cl,
        int ldc, int Nout,
        const float* __restrict__ bias, int flags,
        const __nv_bfloat16* __restrict__ Xh, const __nv_bfloat16* __restrict__ Xl,
        __nv_bfloat16* __restrict__ XCh, __nv_bfloat16* __restrict__ XCl, int xoff,
        long astride, long bstride, long cstride, int biasstride, long xcstride,
        int swapxy)
{
    constexpr int A16 = 128*3;              // 16B units per A matrix (48B row pitch)
    constexpr int B16 = BN*3;
    constexpr int STAGE_BYTES = (2*A16 + 2*B16) * 16;
    constexpr int NB = (BN*4)/256;
    constexpr int WN = BN / 2;
    constexpr int NP = WN / 16;
    constexpr int BH = BN * 2;

    extern __shared__ __align__(16) char smem[];
    const uint32_t sbase = smem_u32(smem);
    const int tid = threadIdx.x;
    const int lane = tid & 31;
    const int wid = tid >> 5;
    const int wm = wid & 3, wn = wid >> 2;
    const int row0 = (swapxy ? blockIdx.y : blockIdx.x) * 128;
    const int col0 = (swapxy ? blockIdx.x : blockIdx.y) * BN;
    {   // batch offsets
        const int bz = blockIdx.z;
        Ah += (size_t)bz * astride;  Al += (size_t)bz * astride;
        Bh += (size_t)bz * bstride;  Bl += (size_t)bz * bstride;
        if (Cf) Cf += (size_t)bz * cstride;
        if (Ch) { Ch += (size_t)bz * cstride; Cl += (size_t)bz * cstride; }
        if (bias) bias += bz * biasstride;
        if (XCh) { XCh += (size_t)bz * xcstride; XCl += (size_t)bz * xcstride; }
    }

    float acc[2][2*NP][4];
    #pragma unroll
    for (int i = 0; i < 2; i++)
        #pragma unroll
        for (int j = 0; j < 2*NP; j++)
            #pragma unroll
            for (int e = 0; e < 4; e++) acc[i][j][e] = 0.f;

    const int arow = wm*32 + (lane & 15);
    const int akc  = lane >> 4;
    const uint32_t aoff = (uint32_t)(arow*3 + akc) * 16;
    const int brow = wn*WN + (lane & 7) + ((lane >> 4) & 1)*8;
    const int bkc  = (lane >> 3) & 1;
    const uint32_t boff = (uint32_t)(2*A16 + brow*3 + bkc) * 16;

    uint4 ra[2], rb[NB];

    auto gload = [&](int c) {
        const int k0 = c * 16;
        #pragma unroll
        for (int t = 0; t < 2; t++) {
            int i = tid + t*256;
            int mat = i >> 8, u = i & 255, r = u >> 1, kc = u & 1;
            ra[t] = *(const uint4*)((mat ? Al : Ah) + (size_t)(row0 + r)*lda + k0 + kc*8);
        }
        #pragma unroll
        for (int t = 0; t < NB; t++) {
            int i = tid + t*256;
            int mat = i / BH, u = i % BH, r = u >> 1, kc = u & 1;
            rb[t] = *(const uint4*)((mat ? Bl : Bh) + (size_t)(col0 + r)*ldb + k0 + kc*8);
        }
    };
    auto sstore = [&](int st) {
        char* sb = smem + st * STAGE_BYTES;
        #pragma unroll
        for (int t = 0; t < 2; t++) {
            int i = tid + t*256;
            int mat = i >> 8, u = i & 255, r = u >> 1, kc = u & 1;
            *(uint4*)(sb + (uint32_t)(mat*A16 + r*3 + kc)*16) = ra[t];
        }
        #pragma unroll
        for (int t = 0; t < NB; t++) {
            int i = tid + t*256;
            int mat = i / BH, u = i % BH, r = u >> 1, kc = u & 1;
            *(uint4*)(sb + (uint32_t)(2*A16 + mat*B16 + r*3 + kc)*16) = rb[t];
        }
    };

    const int nch = K >> 4;
    gload(0);
    sstore(0);

    for (int c = 0; c < nch; c++) {
        if (c + 1 < nch) gload(c + 1);   // prefetch into regs
        __syncthreads();                 // stage (c&1) stores visible; prev compute done

        const uint32_t sb = sbase + (uint32_t)(c & 1) * STAGE_BYTES;
        uint32_t ahf[2][4], alf[2][4];
        #pragma unroll
        for (int mi = 0; mi < 2; mi++) {
            uint32_t ad = sb + aoff + (uint32_t)mi * 768;
            ldm4(ahf[mi], ad);
            ldm4(alf[mi], ad + A16*16);
        }
        uint32_t bhf[NP][4], blf[NP][4];
        #pragma unroll
        for (int np = 0; np < NP; np++) {
            uint32_t bd = sb + boff + (uint32_t)np * 768;
            ldm4(bhf[np], bd);
            ldm4(blf[np], bd + B16*16);
        }
        #pragma unroll
        for (int mi = 0; mi < 2; mi++)
            #pragma unroll
            for (int np = 0; np < NP; np++)
                #pragma unroll
                for (int hf = 0; hf < 2; hf++) {
                    int na = np*2 + hf;
                    mma16816(acc[mi][na], ahf[mi], bhf[np][2*hf], bhf[np][2*hf+1]);
                    mma16816(acc[mi][na], ahf[mi], blf[np][2*hf], blf[np][2*hf+1]);
                    mma16816(acc[mi][na], alf[mi], bhf[np][2*hf], bhf[np][2*hf+1]);
                }

        if (c + 1 < nch) sstore((c + 1) & 1);   // opposite stage; ordered by next sync
    }

    // ---- epilogue
    float* smemf = (float*)smem;   // BN x 128 fp32 staging (pitch 132), spatial only
    if (XCh) __syncthreads();      // all ldmatrix reads of final stage complete

    const int lr = lane >> 2, lc = (lane & 3) * 2;
    #pragma unroll
    for (int mi = 0; mi < 2; mi++) {
        #pragma unroll
        for (int na = 0; na < 2*NP; na++) {
            int gr0 = row0 + wm*32 + mi*16 + lr;
            int gc0l = wn*WN + na*8 + lc;
            #pragma unroll
            for (int e = 0; e < 4; e++) {
                int gr = gr0 + (e >> 1) * 8;
                int gcl = gc0l + (e & 1);
                int gc = col0 + gcl;
                if (gc >= Nout) continue;
                float v = acc[mi][na][e];
                size_t ci = (size_t)gr * ldc + gc;
                if (flags & FLAG_T2)
                    v = 2.f*v - (__bfloat162float(Xh[ci]) + __bfloat162float(Xl[ci]));
                if (flags & FLAG_BIAS) v += bias[gc];
                if (flags & FLAG_RELU) v = fmaxf(v, 0.f);
                if (Cf) Cf[ci] = v;
                if (Ch) { __nv_bfloat16 h, l; bsplit(v, h, l); Ch[ci] = h; Cl[ci] = l; }
                if (XCh) smemf[gcl*132 + (gr - row0)] = v;
            }
        }
    }

    if (XCh) {
        __syncthreads();
        for (int i = tid; i < BN*128; i += 256) {
            int gcl = i >> 7, grl = i & 127;
            int n = col0 + gcl;
            if (n >= Nout) continue;
            float v = smemf[gcl*132 + grl];
            int gr = row0 + grl;
            int bt = gr / DD, d = gr - bt*DD;
            __nv_bfloat16 h, l; bsplit(v, h, l);
            size_t idx = ((size_t)bt*NN + n)*XK + xoff + d;
            XCh[idx] = h; XCl[idx] = l;
        }
    }
}

// ------------------------- graph learning -------------------------
__global__ void gk1(const float* __restrict__ w1, const float* __restrict__ w2,
                    const float* __restrict__ beta, const float* __restrict__ cw,
                    const float* __restrict__ cb, const float* __restrict__ adj) {
    int r = blockIdx.x, br = blockIdx.y;
    __shared__ float w1r[DD], w2r[DD];
    __shared__ float red[256];
    const float* W1 = w1 + (size_t)br*NN*DD;
    const float* W2 = w2 + (size_t)br*NN*DD;
    for (int i = threadIdx.x; i < DD; i += blockDim.x) { w1r[i] = W1[r*DD+i]; w2r[i] = W2[r*DD+i]; }
    __syncthreads();
    float cw0 = cw[br*2+0], cw1 = cw[br*2+1], cbv = cb[br];
    float mysum = 0.f;
    for (int c = threadIdx.x; c < NN; c += blockDim.x) {
        const float* w1c = W1 + c*DD;
        const float* w2c = W2 + c*DD;
        float d1 = 0.f, d2 = 0.f;
        for (int e = 0; e < DD; e++) { d1 += w1r[e]*w2c[e]; d2 += w2r[e]*w1c[e]; }
        float nw = d1 - d2;
        if (r == c) nw += beta[br*NN + r];
        nw = fmaxf(nw, 0.f);
        float ad = adj[r*NN + c];
        float gate = 1.f / (1.f + expf(-(cw0*nw + cw1*ad + cbv)));
        float a = gate*nw + (1.f - gate)*ad;
        g_A[(size_t)br*NN*NN + (size_t)r*NN + c] = a;
        mysum += a;
    }
    red[threadIdx.x] = mysum; __syncthreads();
    for (int s = 128; s > 0; s >>= 1) { if (threadIdx.x < s) red[threadIdx.x] += red[threadIdx.x+s]; __syncthreads(); }
    if (threadIdx.x == 0) g_rs0[br*NN + r] = red[0];
}
__global__ void gk2() {
    int r = blockIdx.x, br = blockIdx.y;
    __shared__ float red[256];
    float dr = rsqrtf(g_rs0[br*NN + r]);
    const float eps = 0.5f / (float)NN;
    float mysum = 0.f;
    for (int c = threadIdx.x; c < NN; c += blockDim.x) {
        float dc = rsqrtf(g_rs0[br*NN + c]);
        size_t idx = (size_t)br*NN*NN + (size_t)r*NN + c;
        float a = fmaxf(dr * g_A[idx] * dc - eps, 0.f);
        g_A[idx] = a; mysum += a;
    }
    red[threadIdx.x] = mysum; __syncthreads();
    for (int s = 128; s > 0; s >>= 1) { if (threadIdx.x < s) red[threadIdx.x] += red[threadIdx.x+s]; __syncthreads(); }
    if (threadIdx.x == 0) g_rs1[br*NN + r] = red[0];
}
__global__ void gk3() {
    int r = blockIdx.x, br = blockIdx.y;
    __shared__ float red[256];
    float dr = rsqrtf(g_rs1[br*NN + r]);
    float mysum = 0.f;
    for (int c = threadIdx.x; c < NN; c += blockDim.x) {
        float dc = rsqrtf(g_rs1[br*NN + c]);
        size_t idx = (size_t)br*NN*NN + (size_t)r*NN + c;
        float g = dr * g_A[idx] * dc;
        g_A[idx] = g; mysum += g;
    }
    red[threadIdx.x] = mysum; __syncthreads();
    for (int s = 128; s > 0; s >>= 1) { if (threadIdx.x < s) red[threadIdx.x] += red[threadIdx.x+s]; __syncthreads(); }
    if (threadIdx.x == 0) g_rs0[br*NN + r] = red[0];
}
__global__ void gk4() {
    int r = blockIdx.x, br = blockIdx.y;
    float er = rsqrtf(g_rs0[br*NN + r]);
    for (int c = threadIdx.x; c < NKP; c += blockDim.x) {
        float L = 0.f;
        if (c < NN) {
            float ec = rsqrtf(g_rs0[br*NN + c]);
            L = ((r == c) ? 1.f : 0.f) - er * g_A[(size_t)br*NN*NN + (size_t)r*NN + c] * ec;
        }
        __nv_bfloat16 h, l; bsplit(L, h, l);
        size_t idx = (size_t)br*NROWP*NKP + (size_t)r*NKP + c;
        g_Lh[idx] = h; g_Ll[idx] = l;
    }
}

// ------------------------- layout / split kernels -------------------------
__global__ void xsplitT(const float* __restrict__ x) {
    __shared__ float s[64*121];
    int bt = blockIdx.x;
    for (int n0 = 0; n0 < NN; n0 += 64) {
        int nrows = (NN - n0 < 64) ? (NN - n0) : 64;
        for (int i = threadIdx.x; i < nrows*DD; i += 256) {
            int nn = i / DD, d = i - nn*DD;
            s[nn*121 + d] = x[((size_t)bt*NN + n0 + nn)*DD + d];
        }
        __syncthreads();
        for (int i = threadIdx.x; i < DD*64; i += 256) {
            int d = i >> 6, nn = i & 63;
            int n = n0 + nn;
            if (nn < nrows) {
                __nv_bfloat16 h, l; bsplit(s[nn*121 + d], h, l);
                size_t idx = ((size_t)bt*DD + d)*NKP + n;
                g_xth[idx] = h; g_xtl[idx] = l;
            }
        }
        __syncthreads();
    }
}
// x -> cols [0,120) of all three branch xcat buffers
__global__ void pack_x(const float* __restrict__ x) {
    size_t r = blockIdx.x;
    int d = threadIdx.x;
    if (d < DD) {
        __nv_bfloat16 h, l; bsplit(x[r*DD + d], h, l);
        #pragma unroll
        for (int br = 0; br < 3; br++) {
            size_t idx = (size_t)br*MTOK*XK + r*XK + d;
            g_xcath[idx] = h;
            g_xcatl[idx] = l;
        }
    }
}
__global__ void wsplit(const float* __restrict__ src, __nv_bfloat16* __restrict__ dh,
                       __nv_bfloat16* __restrict__ dl, int K, int N, int ldk,
                       long src_bstride, long dst_bstride) {
    int n = blockIdx.x;
    int br = blockIdx.y;
    src += (size_t)br * src_bstride;
    dh  += (size_t)br * dst_bstride;
    dl  += (size_t)br * dst_bstride;
    for (int k = threadIdx.x; k < K; k += blockDim.x) {
        __nv_bfloat16 h, l; bsplit(src[(size_t)k*N + n], h, l);
        dh[(size_t)n*ldk + k] = h;
        dl[(size_t)n*ldk + k] = l;
    }
}

// ------------------------- attention -------------------------
__global__ void attn_kernel(const float* __restrict__ q, const float* __restrict__ k,
                            const float* __restrict__ v) {
    int bn = blockIdx.x;
    int b = bn / NN, n = bn % NN;
    __shared__ float qs[TT][DD], ks[TT][DD], vs[TT][DD];
    for (int i = threadIdx.x; i < TT*DD; i += blockDim.x) {
        int t = i / DD, d = i % DD;
        size_t gi = (((size_t)(b*TT + t))*NN + n)*DD + d;
        qs[t][d] = q[gi]; ks[t][d] = k[gi]; vs[t][d] = v[gi];
    }
    __syncthreads();
    int tid = threadIdx.x;
    if (tid < HH*TT) {
        int h = tid / TT, qi = tid % TT;
        const float scale = rsqrtf((float)HD);
        float s[TT]; float mx = -1e30f;
        #pragma unroll
        for (int j = 0; j < TT; j++) {
            float acc = 0.f;
            #pragma unroll
            for (int e = 0; e < HD; e++) acc += qs[qi][h*HD+e] * ks[j][h*HD+e];
            acc *= scale; s[j] = acc; mx = fmaxf(mx, acc);
        }
        float sum = 0.f;
        #pragma unroll
        for (int j = 0; j < TT; j++) { s[j] = expf(s[j]-mx); sum += s[j]; }
        float inv = 1.f / sum;
        size_t orow = ((size_t)(b*TT + qi))*NN + n;
        #pragma unroll
        for (int e = 0; e < HD; e++) {
            float acc = 0.f;
            #pragma unroll
            for (int j = 0; j < TT; j++) acc += s[j] * vs[j][h*HD+e];
            __nv_bfloat16 hh, ll; bsplit(acc*inv, hh, ll);
            g_oah[orow*128 + h*HD + e] = hh;
            g_oal[orow*128 + h*HD + e] = ll;
        }
    }
}

// ------------------------- residual + layernorm -------------------------
__global__ void ln_kernel(const float* __restrict__ xa, const float* __restrict__ xb,
                          const float* __restrict__ gg, const float* __restrict__ bb,
                          float* __restrict__ outp, __nv_bfloat16* __restrict__ oh,
                          __nv_bfloat16* __restrict__ ol) {
    int warp = threadIdx.x >> 5, lane = threadIdx.x & 31;
    size_t m = (size_t)blockIdx.x * 4 + warp;
    if (m >= MTOK) return;
    size_t ia = m * DD;
    float v[4]; float s = 0.f;
    #pragma unroll
    for (int i = 0; i < 4; i++) {
        int d = lane + 32*i;
        float val = (d < DD) ? (xa[ia+d] + xb[ia+d]) : 0.f;
        v[i] = val; s += val;
    }
    #pragma unroll
    for (int o = 16; o > 0; o >>= 1) s += __shfl_xor_sync(0xffffffffu, s, o);
    float mean = s * (1.f / DD);
    float vsum = 0.f;
    #pragma unroll
    for (int i = 0; i < 4; i++) {
        int d = lane + 32*i;
        if (d < DD) { float df = v[i]-mean; vsum += df*df; }
    }
    #pragma unroll
    for (int o = 16; o > 0; o >>= 1) vsum += __shfl_xor_sync(0xffffffffu, vsum, o);
    float inv = rsqrtf(vsum * (1.f / DD) + 1e-5f);
    #pragma unroll
    for (int i = 0; i < 4; i++) {
        int d = lane + 32*i;
        if (d < DD) {
            float o = (v[i]-mean)*inv*gg[d] + bb[d];
            if (outp) outp[ia + d] = o;
            if (oh) { __nv_bfloat16 h, l; bsplit(o, h, l); oh[m*128 + d] = h; ol[m*128 + d] = l; }
        }
    }
}

// ------------------------- launch -------------------------
extern "C" void kernel_launch(void* const* d_in, const int* in_sizes, int n_in,
                              void* d_out, int out_size) {
    const float* x       = (const float*)d_in[0];
    const float* adj     = (const float*)d_in[1];
    const float* gl_beta = (const float*)d_in[2];
    const float* gl_w1   = (const float*)d_in[3];
    const float* gl_w2   = (const float*)d_in[4];
    const float* gl_cw   = (const float*)d_in[5];
    const float* gl_cb   = (const float*)d_in[6];
    const float* cheb_w  = (const float*)d_in[7];
    const float* cheb_b  = (const float*)d_in[8];
    const float* out_w   = (const float*)d_in[9];
    const float* out_b   = (const float*)d_in[10];
    const float* ff_w1   = (const float*)d_in[11];
    const float* ff_b1   = (const float*)d_in[12];
    const float* ff_w2   = (const float*)d_in[13];
    const float* ff_b2   = (const float*)d_in[14];
    const float* ln1_g   = (const float*)d_in[15];
    const float* ln1_b   = (const float*)d_in[16];
    const float* ln2_g   = (const float*)d_in[17];
    const float* ln2_b   = (const float*)d_in[18];
    float* outp = (float*)d_out;

    const int SMEM128 = 2 * (2*(128*3) + 2*(128*3)) * 16;   // 49152
    const int SMEM64  = 2 * (2*(128*3) + 2*(64*3)) * 16;    // 36864
    cudaFuncSetAttribute(hmma_bf16x3<128>, cudaFuncAttributeMaxDynamicSharedMemorySize, SMEM128);
    cudaFuncSetAttribute(hmma_bf16x3<64>,  cudaFuncAttributeMaxDynamicSharedMemorySize, SMEM64);

    __nv_bfloat16 *pLh, *pLl, *pxth, *pxtl, *pt1h, *pt1l;
    __nv_bfloat16 *pxch, *pxcl, *poah, *poal, *po1h, *po1l, *phh, *phl;
    __nv_bfloat16 *pwqh, *pwql, *powh, *powl, *pw1h, *pw1l, *pw2h, *pw2l;
    float *pqkv, *poproj, *pout1f, *pffnf;
    cudaGetSymbolAddress((void**)&pLh, g_Lh);   cudaGetSymbolAddress((void**)&pLl, g_Ll);
    cudaGetSymbolAddress((void**)&pxth, g_xth); cudaGetSymbolAddress((void**)&pxtl, g_xtl);
    cudaGetSymbolAddress((void**)&pt1h, g_t1h); cudaGetSymbolAddress((void**)&pt1l, g_t1l);
    cudaGetSymbolAddress((void**)&pxch, g_xcath); cudaGetSymbolAddress((void**)&pxcl, g_xcatl);
    cudaGetSymbolAddress((void**)&poah, g_oah); cudaGetSymbolAddress((void**)&poal, g_oal);
    cudaGetSymbolAddress((void**)&po1h, g_o1h); cudaGetSymbolAddress((void**)&po1l, g_o1l);
    cudaGetSymbolAddress((void**)&phh, g_hidh); cudaGetSymbolAddress((void**)&phl, g_hidl);
    cudaGetSymbolAddress((void**)&pwqh, g_wqh); cudaGetSymbolAddress((void**)&pwql, g_wql);
    cudaGetSymbolAddress((void**)&powh, g_owh); cudaGetSymbolAddress((void**)&powl, g_owl);
    cudaGetSymbolAddress((void**)&pw1h, g_w1h); cudaGetSymbolAddress((void**)&pw1l, g_w1l);
    cudaGetSymbolAddress((void**)&pw2h, g_w2h); cudaGetSymbolAddress((void**)&pw2l, g_w2l);
    cudaGetSymbolAddress((void**)&pqkv, g_qkv); cudaGetSymbolAddress((void**)&poproj, g_oproj);
    cudaGetSymbolAddress((void**)&pout1f, g_out1f); cudaGetSymbolAddress((void**)&pffnf, g_ffnf);

    // graph learning
    dim3 gG(NN, 3);
    gk1<<<gG, 256>>>(gl_w1, gl_w2, gl_beta, gl_cw, gl_cb, adj);
    gk2<<<gG, 256>>>();
    gk3<<<gG, 256>>>();
    gk4<<<gG, 256>>>();

    // layout + weight prep
    xsplitT<<<BT, 256>>>(x);
    pack_x<<<MTOK, 128>>>(x);
    wsplit<<<dim3(120,3), 256>>>(cheb_w, pwqh, pwql, 360, 120, XK, (long)360*120, (long)128*XK);
    wsplit<<<dim3(120,1), 256>>>(out_w, powh, powl, 120, 120, 128, 0, 0);
    wsplit<<<dim3(FF,1),  256>>>(ff_w1, pw1h, pw1l, 120, FF, 128, 0, 0);
    wsplit<<<dim3(120,1), 256>>>(ff_w2, pw2h, pw2l, FF, 120, FF, 0, 0);

    const long t1s = (long)MSP*NKP;
    const long xcs = (long)MTOK*XK;
    const long Ls  = (long)NROWP*NKP;

    // batched spatial t1 = L_br @ x (all branches) -> t1_br + xcat_br[120..239]
    dim3 gsp(MSP/128, 3, 3);
    hmma_bf16x3<64><<<gsp, 256, SMEM64>>>(pxth, pxtl, NKP, pLh, pLl, NKP, NKP,
                                          nullptr, pt1h, pt1l, NKP, NN,
                                          nullptr, 0, nullptr, nullptr,
                                          pxch, pxcl, 120,
                                          0, Ls, t1s, 0, xcs, 0);
    // batched spatial t2 = 2*(L_br @ t1_br) - x -> xcat_br[240..359]
    hmma_bf16x3<64><<<gsp, 256, SMEM64>>>(pt1h, pt1l, NKP, pLh, pLl, NKP, NKP,
                                          nullptr, nullptr, nullptr, NKP, NN,
                                          nullptr, FLAG_T2, pxth, pxtl,
                                          pxch, pxcl, 240,
                                          t1s, Ls, 0, 0, xcs, 0);

    // batched QKV: relu(xcat_br @ W_br + b_br)
    dim3 gqkv(MTOK/128, 1, 3);
    hmma_bf16x3<128><<<gqkv, 256, SMEM128>>>(pxch, pxcl, XK, pwqh, pwql, XK, XK,
                                             pqkv, nullptr, nullptr, DD, DD,
                                             cheb_b, FLAG_BIAS | FLAG_RELU,
                                             nullptr, nullptr, nullptr, nullptr, 0,
                                             xcs, (long)128*XK, (long)MTOK*DD, DD, 0, 0);

    attn_kernel<<<BB*NN, 128>>>(pqkv, pqkv + (size_t)MTOK*DD, pqkv + (size_t)2*MTOK*DD);

    dim3 gch(MTOK/128, 1, 1);
    // output projection
    hmma_bf16x3<128><<<gch, 256, SMEM128>>>(poah, poal, 128, powh, powl, 128, 128,
                                            poproj, nullptr, nullptr, DD, DD,
                                            out_b, FLAG_BIAS, nullptr, nullptr,
                                            nullptr, nullptr, 0, 0, 0, 0, 0, 0, 0);
    // LN1
    ln_kernel<<<MTOK/4, 128>>>(x, poproj, ln1_g, ln1_b, pout1f, po1h, po1l);

    // FFN1 -> bf16 h/l hidden; swapped grid: col tiles fastest for A L2/L1 reuse
    dim3 gf1(FF/128, MTOK/128, 1);
    hmma_bf16x3<128><<<gf1, 256, SMEM128>>>(po1h, po1l, 128, pw1h, pw1l, 128, 128,
                                            nullptr, phh, phl, FF, FF,
                                            ff_b1, FLAG_BIAS | FLAG_RELU, nullptr, nullptr,
                                            nullptr, nullptr, 0, 0, 0, 0, 0, 0, 1);
    // FFN2
    hmma_bf16x3<128><<<gch, 256, SMEM128>>>(phh, phl, FF, pw2h, pw2l, FF, FF,
                                            pffnf, nullptr, nullptr, DD, DD,
                                            ff_b2, FLAG_BIAS, nullptr, nullptr,
                                            nullptr, nullptr, 0, 0, 0, 0, 0, 0, 0);
    // LN2 -> output
    ln_kernel<<<MTOK/4, 128>>>(pout1f, pffnf, ln2_g, ln2_b, outp, nullptr, nullptr);
}

// round 12
// speedup vs baseline: 1.3127x; 1.2873x over previous
#include <cuda_runtime.h>
#include <cuda_fp16.h>
#include <math.h>
#include <stdint.h>

#define NN 170
#define NKP 176            // padded node dim (K of spatial GEMM, multiple of 16)
#define NROWP 192          // padded L rows (3 x 64 col tiles)
#define TT 12
#define BB 32
#define DD 120
#define HH 8
#define HD 15
#define FF 2048
#define BT (BB*TT)          // 384
#define MTOK (BB*TT*NN)     // 65280 = 510*128
#define MSP (BT*DD)         // 46080 = 360*128
#define XK 368              // padded xcat K (360 -> 368)

#define FLAG_BIAS  1
#define FLAG_RELU  2
#define FLAG_T2    4        // epilogue: v = 2*acc - (Xh+Xl)

// ------------------------- static device scratch (zero-initialized) --------
__device__ float g_A[3*NN*NN];
__device__ float g_rs0[3*NN];
__device__ float g_rs1[3*NN];

__device__ __align__(16) __half g_Lh[3*NROWP*NKP];
__device__ __align__(16) __half g_Ll[3*NROWP*NKP];
__device__ __align__(16) __half g_xth[(size_t)MSP*NKP];
__device__ __align__(16) __half g_xtl[(size_t)MSP*NKP];
__device__ __align__(16) __half g_t1h[(size_t)3*MSP*NKP];   // per-branch
__device__ __align__(16) __half g_t1l[(size_t)3*MSP*NKP];
__device__ __align__(16) __half g_xcath[(size_t)3*MTOK*XK]; // per-branch
__device__ __align__(16) __half g_xcatl[(size_t)3*MTOK*XK];
__device__ __align__(16) __half g_oah[(size_t)MTOK*128];    // hi only (2-pass oproj)
__device__ __align__(16) __half g_o1h[(size_t)MTOK*128];    // hi only (2-pass FFN1)
__device__ __align__(16) __half g_hidh[(size_t)MTOK*FF];    // hi only (2-pass FFN2)
// B-operand weights, rows padded to tile boundary (always hi+lo)
__device__ __align__(16) __half g_wqh[3*128*XK];
__device__ __align__(16) __half g_wql[3*128*XK];
__device__ __align__(16) __half g_owh[128*128];
__device__ __align__(16) __half g_owl[128*128];
__device__ __align__(16) __half g_w1h[(size_t)FF*128];
__device__ __align__(16) __half g_w1l[(size_t)FF*128];
__device__ __align__(16) __half g_w2h[(size_t)128*FF];
__device__ __align__(16) __half g_w2l[(size_t)128*FF];
__device__ float g_qkv[(size_t)3*MTOK*DD];
__device__ float g_oproj[(size_t)MTOK*DD];
__device__ float g_out1f[(size_t)MTOK*DD];
__device__ float g_ffnf[(size_t)MTOK*DD];

// ------------------------- helpers -------------------------
__device__ __forceinline__ void hsplit(float v, __half &h, __half &l) {
    h = __float2half_rn(v);
    l = __float2half_rn(v - __half2float(h));
}
__device__ __forceinline__ uint32_t smem_u32(const void* p) {
    uint32_t a;
    asm("{ .reg .u64 t; cvta.to.shared.u64 t, %1; cvt.u32.u64 %0, t; }" : "=r"(a) : "l"(p));
    return a;
}
__device__ __forceinline__ void ldm4(uint32_t (&d)[4], uint32_t addr) {
    asm volatile("ldmatrix.sync.aligned.m8n8.x4.shared.b16 {%0,%1,%2,%3}, [%4];"
                 : "=r"(d[0]), "=r"(d[1]), "=r"(d[2]), "=r"(d[3]) : "r"(addr));
}
__device__ __forceinline__ void mma16816(float (&c)[4], const uint32_t (&a)[4],
                                         uint32_t b0, uint32_t b1) {
    asm volatile("mma.sync.aligned.m16n8k16.row.col.f32.f16.f16.f32 "
                 "{%0,%1,%2,%3}, {%4,%5,%6,%7}, {%8,%9}, {%0,%1,%2,%3};"
                 : "+f"(c[0]), "+f"(c[1]), "+f"(c[2]), "+f"(c[3])
                 : "r"(a[0]), "r"(a[1]), "r"(a[2]), "r"(a[3]), "r"(b0), "r"(b1));
}

// ------------------------- HMMA fp16 split GEMM ------------------------
// D[M,N] = sum_k A[m,k]*B[n,k]; A: M x K (lda), B rows padded to tile bound.
// NPASS=3: AhBh + AhBl + AlBh.  NPASS=2: AhBh + AhBl (A hi-only; Al unused).
// Batched over blockIdx.z via strides (0 = shared).
template<int BN, int NPASS>
__global__ __launch_bounds__(256) void hmma_fp16(
        const __half* __restrict__ Ah, const __half* __restrict__ Al, int lda,
        const __half* __restrict__ Bh, const __half* __restrict__ Bl, int ldb,
        int K,
        float* __restrict__ Cf, __half* __restrict__ Ch, __half* __restrict__ Cl,
        int ldc, int Nout,
        const float* __restrict__ bias, int flags,
        const __half* __restrict__ Xh, const __half* __restrict__ Xl,
        __half* __restrict__ XCh, __half* __restrict__ XCl, int xoff,
        long astride, long bstride, long cstride, int biasstride, long xcstride,
        int swapxy)
{
    constexpr int AMATS = NPASS - 1;        // 2 (hi+lo) or 1 (hi only)
    constexpr int A16 = 128*3;              // 16B units per A matrix (48B row pitch)
    constexpr int B16 = BN*3;
    constexpr int STAGE_BYTES = (AMATS*A16 + 2*B16) * 16;
    constexpr int NB = (BN*4)/256;          // B 16B transfers per thread
    constexpr int WN = BN / 2;
    constexpr int NP = WN / 16;
    constexpr int BH = BN * 2;

    extern __shared__ __align__(16) char smem[];
    const uint32_t sbase = smem_u32(smem);
    const int tid = threadIdx.x;
    const int lane = tid & 31;
    const int wid = tid >> 5;
    const int wm = wid & 3, wn = wid >> 2;
    const int row0 = (swapxy ? blockIdx.y : blockIdx.x) * 128;
    const int col0 = (swapxy ? blockIdx.x : blockIdx.y) * BN;
    {   // batch offsets
        const int bz = blockIdx.z;
        Ah += (size_t)bz * astride;  if (AMATS == 2) Al += (size_t)bz * astride;
        Bh += (size_t)bz * bstride;  Bl += (size_t)bz * bstride;
        if (Cf) Cf += (size_t)bz * cstride;
        if (Ch) Ch += (size_t)bz * cstride;
        if (Cl) Cl += (size_t)bz * cstride;
        if (bias) bias += bz * biasstride;
        if (XCh) { XCh += (size_t)bz * xcstride; XCl += (size_t)bz * xcstride; }
    }

    float acc[2][2*NP][4];
    #pragma unroll
    for (int i = 0; i < 2; i++)
        #pragma unroll
        for (int j = 0; j < 2*NP; j++)
            #pragma unroll
            for (int e = 0; e < 4; e++) acc[i][j][e] = 0.f;

    const int arow = wm*32 + (lane & 15);
    const int akc  = lane >> 4;
    const uint32_t aoff = (uint32_t)(arow*3 + akc) * 16;
    const int brow = wn*WN + (lane & 7) + ((lane >> 4) & 1)*8;
    const int bkc  = (lane >> 3) & 1;
    const uint32_t boff = (uint32_t)(AMATS*A16 + brow*3 + bkc) * 16;

    uint4 ra[AMATS], rb[NB];

    auto gload = [&](int c) {
        const int k0 = c * 16;
        #pragma unroll
        for (int t = 0; t < AMATS; t++) {
            int i = tid + t*256;
            int mat = i >> 8, u = i & 255, r = u >> 1, kc = u & 1;
            ra[t] = *(const uint4*)((mat ? Al : Ah) + (size_t)(row0 + r)*lda + k0 + kc*8);
        }
        #pragma unroll
        for (int t = 0; t < NB; t++) {
            int i = tid + t*256;
            int mat = i / BH, u = i % BH, r = u >> 1, kc = u & 1;
            rb[t] = *(const uint4*)((mat ? Bl : Bh) + (size_t)(col0 + r)*ldb + k0 + kc*8);
        }
    };
    auto sstore = [&](int st) {
        char* sb = smem + st * STAGE_BYTES;
        #pragma unroll
        for (int t = 0; t < AMATS; t++) {
            int i = tid + t*256;
            int mat = i >> 8, u = i & 255, r = u >> 1, kc = u & 1;
            *(uint4*)(sb + (uint32_t)(mat*A16 + r*3 + kc)*16) = ra[t];
        }
        #pragma unroll
        for (int t = 0; t < NB; t++) {
            int i = tid + t*256;
            int mat = i / BH, u = i % BH, r = u >> 1, kc = u & 1;
            *(uint4*)(sb + (uint32_t)(AMATS*A16 + mat*B16 + r*3 + kc)*16) = rb[t];
        }
    };

    const int nch = K >> 4;
    gload(0);
    sstore(0);

    for (int c = 0; c < nch; c++) {
        if (c + 1 < nch) gload(c + 1);   // prefetch into regs
        __syncthreads();                 // stage (c&1) stores visible; prev compute done

        const uint32_t sb = sbase + (uint32_t)(c & 1) * STAGE_BYTES;
        uint32_t ahf[2][4], alf[2][4];
        #pragma unroll
        for (int mi = 0; mi < 2; mi++) {
            uint32_t ad = sb + aoff + (uint32_t)mi * 768;
            ldm4(ahf[mi], ad);
            if (NPASS == 3) ldm4(alf[mi], ad + A16*16);
        }
        uint32_t bhf[NP][4], blf[NP][4];
        #pragma unroll
        for (int np = 0; np < NP; np++) {
            uint32_t bd = sb + boff + (uint32_t)np * 768;
            ldm4(bhf[np], bd);
            ldm4(blf[np], bd + B16*16);
        }
        #pragma unroll
        for (int mi = 0; mi < 2; mi++)
            #pragma unroll
            for (int np = 0; np < NP; np++)
                #pragma unroll
                for (int hf = 0; hf < 2; hf++) {
                    int na = np*2 + hf;
                    mma16816(acc[mi][na], ahf[mi], bhf[np][2*hf], bhf[np][2*hf+1]);
                    mma16816(acc[mi][na], ahf[mi], blf[np][2*hf], blf[np][2*hf+1]);
                    if (NPASS == 3)
                        mma16816(acc[mi][na], alf[mi], bhf[np][2*hf], bhf[np][2*hf+1]);
                }

        if (c + 1 < nch) sstore((c + 1) & 1);   // opposite stage; ordered by next sync
    }

    // ---- epilogue
    float* smemf = (float*)smem;   // BN x 128 fp32 staging (pitch 132), spatial only
    if (XCh) __syncthreads();      // all ldmatrix reads of final stage complete

    const int lr = lane >> 2, lc = (lane & 3) * 2;
    #pragma unroll
    for (int mi = 0; mi < 2; mi++) {
        #pragma unroll
        for (int na = 0; na < 2*NP; na++) {
            int gr0 = row0 + wm*32 + mi*16 + lr;
            int gc0l = wn*WN + na*8 + lc;
            #pragma unroll
            for (int e = 0; e < 4; e++) {
                int gr = gr0 + (e >> 1) * 8;
                int gcl = gc0l + (e & 1);
                int gc = col0 + gcl;
                if (gc >= Nout) continue;
                float v = acc[mi][na][e];
                size_t ci = (size_t)gr * ldc + gc;
                if (flags & FLAG_T2)
                    v = 2.f*v - (__half2float(Xh[ci]) + __half2float(Xl[ci]));
                if (flags & FLAG_BIAS) v += bias[gc];
                if (flags & FLAG_RELU) v = fmaxf(v, 0.f);
                if (Cf) Cf[ci] = v;
                if (Ch) {
                    __half h, l; hsplit(v, h, l);
                    Ch[ci] = h;
                    if (Cl) Cl[ci] = l;
                }
                if (XCh) smemf[gcl*132 + (gr - row0)] = v;
            }
        }
    }

    if (XCh) {
        __syncthreads();
        for (int i = tid; i < BN*128; i += 256) {
            int gcl = i >> 7, grl = i & 127;
            int n = col0 + gcl;
            if (n >= Nout) continue;
            float v = smemf[gcl*132 + grl];
            int gr = row0 + grl;
            int bt = gr / DD, d = gr - bt*DD;
            __half h, l; hsplit(v, h, l);
            size_t idx = ((size_t)bt*NN + n)*XK + xoff + d;
            XCh[idx] = h; XCl[idx] = l;
        }
    }
}

// ------------------------- graph learning -------------------------
__global__ void gk1(const float* __restrict__ w1, const float* __restrict__ w2,
                    const float* __restrict__ beta, const float* __restrict__ cw,
                    const float* __restrict__ cb, const float* __restrict__ adj) {
    int r = blockIdx.x, br = blockIdx.y;
    __shared__ float w1r[DD], w2r[DD];
    __shared__ float red[256];
    const float* W1 = w1 + (size_t)br*NN*DD;
    const float* W2 = w2 + (size_t)br*NN*DD;
    for (int i = threadIdx.x; i < DD; i += blockDim.x) { w1r[i] = W1[r*DD+i]; w2r[i] = W2[r*DD+i]; }
    __syncthreads();
    float cw0 = cw[br*2+0], cw1 = cw[br*2+1], cbv = cb[br];
    float mysum = 0.f;
    for (int c = threadIdx.x; c < NN; c += blockDim.x) {
        const float* w1c = W1 + c*DD;
        const float* w2c = W2 + c*DD;
        float d1 = 0.f, d2 = 0.f;
        for (int e = 0; e < DD; e++) { d1 += w1r[e]*w2c[e]; d2 += w2r[e]*w1c[e]; }
        float nw = d1 - d2;
        if (r == c) nw += beta[br*NN + r];
        nw = fmaxf(nw, 0.f);
        float ad = adj[r*NN + c];
        float gate = 1.f / (1.f + expf(-(cw0*nw + cw1*ad + cbv)));
        float a = gate*nw + (1.f - gate)*ad;
        g_A[(size_t)br*NN*NN + (size_t)r*NN + c] = a;
        mysum += a;
    }
    red[threadIdx.x] = mysum; __syncthreads();
    for (int s = 128; s > 0; s >>= 1) { if (threadIdx.x < s) red[threadIdx.x] += red[threadIdx.x+s]; __syncthreads(); }
    if (threadIdx.x == 0) g_rs0[br*NN + r] = red[0];
}
__global__ void gk2() {
    int r = blockIdx.x, br = blockIdx.y;
    __shared__ float red[256];
    float dr = rsqrtf(g_rs0[br*NN + r]);
    const float eps = 0.5f / (float)NN;
    float mysum = 0.f;
    for (int c = threadIdx.x; c < NN; c += blockDim.x) {
        float dc = rsqrtf(g_rs0[br*NN + c]);
        size_t idx = (size_t)br*NN*NN + (size_t)r*NN + c;
        float a = fmaxf(dr * g_A[idx] * dc - eps, 0.f);
        g_A[idx] = a; mysum += a;
    }
    red[threadIdx.x] = mysum; __syncthreads();
    for (int s = 128; s > 0; s >>= 1) { if (threadIdx.x < s) red[threadIdx.x] += red[threadIdx.x+s]; __syncthreads(); }
    if (threadIdx.x == 0) g_rs1[br*NN + r] = red[0];
}
__global__ void gk3() {
    int r = blockIdx.x, br = blockIdx.y;
    __shared__ float red[256];
    float dr = rsqrtf(g_rs1[br*NN + r]);
    float mysum = 0.f;
    for (int c = threadIdx.x; c < NN; c += blockDim.x) {
        float dc = rsqrtf(g_rs1[br*NN + c]);
        size_t idx = (size_t)br*NN*NN + (size_t)r*NN + c;
        float g = dr * g_A[idx] * dc;
        g_A[idx] = g; mysum += g;
    }
    red[threadIdx.x] = mysum; __syncthreads();
    for (int s = 128; s > 0; s >>= 1) { if (threadIdx.x < s) red[threadIdx.x] += red[threadIdx.x+s]; __syncthreads(); }
    if (threadIdx.x == 0) g_rs0[br*NN + r] = red[0];
}
__global__ void gk4() {
    int r = blockIdx.x, br = blockIdx.y;
    float er = rsqrtf(g_rs0[br*NN + r]);
    for (int c = threadIdx.x; c < NKP; c += blockDim.x) {
        float L = 0.f;
        if (c < NN) {
            float ec = rsqrtf(g_rs0[br*NN + c]);
            L = ((r == c) ? 1.f : 0.f) - er * g_A[(size_t)br*NN*NN + (size_t)r*NN + c] * ec;
        }
        __half h, l; hsplit(L, h, l);
        size_t idx = (size_t)br*NROWP*NKP + (size_t)r*NKP + c;
        g_Lh[idx] = h; g_Ll[idx] = l;
    }
}

// ------------------------- layout / split kernels -------------------------
__global__ void xsplitT(const float* __restrict__ x) {
    __shared__ float s[64*121];
    int bt = blockIdx.x;
    for (int n0 = 0; n0 < NN; n0 += 64) {
        int nrows = (NN - n0 < 64) ? (NN - n0) : 64;
        for (int i = threadIdx.x; i < nrows*DD; i += 256) {
            int nn = i / DD, d = i - nn*DD;
            s[nn*121 + d] = x[((size_t)bt*NN + n0 + nn)*DD + d];
        }
        __syncthreads();
        for (int i = threadIdx.x; i < DD*64; i += 256) {
            int d = i >> 6, nn = i & 63;
            int n = n0 + nn;
            if (nn < nrows) {
                __half h, l; hsplit(s[nn*121 + d], h, l);
                size_t idx = ((size_t)bt*DD + d)*NKP + n;
                g_xth[idx] = h; g_xtl[idx] = l;
            }
        }
        __syncthreads();
    }
}
// x -> cols [0,120) of all three branch xcat buffers
__global__ void pack_x(const float* __restrict__ x) {
    size_t r = blockIdx.x;
    int d = threadIdx.x;
    if (d < DD) {
        __half h, l; hsplit(x[r*DD + d], h, l);
        #pragma unroll
        for (int br = 0; br < 3; br++) {
            size_t idx = (size_t)br*MTOK*XK + r*XK + d;
            g_xcath[idx] = h;
            g_xcatl[idx] = l;
        }
    }
}
__global__ void wsplit(const float* __restrict__ src, __half* __restrict__ dh,
                       __half* __restrict__ dl, int K, int N, int ldk,
                       long src_bstride, long dst_bstride) {
    int n = blockIdx.x;
    int br = blockIdx.y;
    src += (size_t)br * src_bstride;
    dh  += (size_t)br * dst_bstride;
    dl  += (size_t)br * dst_bstride;
    for (int k = threadIdx.x; k < K; k += blockDim.x) {
        __half h, l; hsplit(src[(size_t)k*N + n], h, l);
        dh[(size_t)n*ldk + k] = h;
        dl[(size_t)n*ldk + k] = l;
    }
}

// ------------------------- attention -------------------------
__global__ void attn_kernel(const float* __restrict__ q, const float* __restrict__ k,
                            const float* __restrict__ v) {
    int bn = blockIdx.x;
    int b = bn / NN, n = bn % NN;
    __shared__ float qs[TT][DD], ks[TT][DD], vs[TT][DD];
    for (int i = threadIdx.x; i < TT*DD; i += blockDim.x) {
        int t = i / DD, d = i % DD;
        size_t gi = (((size_t)(b*TT + t))*NN + n)*DD + d;
        qs[t][d] = q[gi]; ks[t][d] = k[gi]; vs[t][d] = v[gi];
    }
    __syncthreads();
    int tid = threadIdx.x;
    if (tid < HH*TT) {
        int h = tid / TT, qi = tid % TT;
        const float scale = rsqrtf((float)HD);
        float s[TT]; float mx = -1e30f;
        #pragma unroll
        for (int j = 0; j < TT; j++) {
            float acc = 0.f;
            #pragma unroll
            for (int e = 0; e < HD; e++) acc += qs[qi][h*HD+e] * ks[j][h*HD+e];
            acc *= scale; s[j] = acc; mx = fmaxf(mx, acc);
        }
        float sum = 0.f;
        #pragma unroll
        for (int j = 0; j < TT; j++) { s[j] = expf(s[j]-mx); sum += s[j]; }
        float inv = 1.f / sum;
        size_t orow = ((size_t)(b*TT + qi))*NN + n;
        #pragma unroll
        for (int e = 0; e < HD; e++) {
            float acc = 0.f;
            #pragma unroll
            for (int j = 0; j < TT; j++) acc += s[j] * vs[j][h*HD+e];
            g_oah[orow*128 + h*HD + e] = __float2half_rn(acc * inv);
        }
    }
}

// ------------------------- residual + layernorm -------------------------
__global__ void ln_kernel(const float* __restrict__ xa, const float* __restrict__ xb,
                          const float* __restrict__ gg, const float* __restrict__ bb,
                          float* __restrict__ outp, __half* __restrict__ oh) {
    int warp = threadIdx.x >> 5, lane = threadIdx.x & 31;
    size_t m = (size_t)blockIdx.x * 4 + warp;
    if (m >= MTOK) return;
    size_t ia = m * DD;
    float v[4]; float s = 0.f;
    #pragma unroll
    for (int i = 0; i < 4; i++) {
        int d = lane + 32*i;
        float val = (d < DD) ? (xa[ia+d] + xb[ia+d]) : 0.f;
        v[i] = val; s += val;
    }
    #pragma unroll
    for (int o = 16; o > 0; o >>= 1) s += __shfl_xor_sync(0xffffffffu, s, o);
    float mean = s * (1.f / DD);
    float vsum = 0.f;
    #pragma unroll
    for (int i = 0; i < 4; i++) {
        int d = lane + 32*i;
        if (d < DD) { float df = v[i]-mean; vsum += df*df; }
    }
    #pragma unroll
    for (int o = 16; o > 0; o >>= 1) vsum += __shfl_xor_sync(0xffffffffu, vsum, o);
    float inv = rsqrtf(vsum * (1.f / DD) + 1e-5f);
    #pragma unroll
    for (int i = 0; i < 4; i++) {
        int d = lane + 32*i;
        if (d < DD) {
            float o = (v[i]-mean)*inv*gg[d] + bb[d];
            if (outp) outp[ia + d] = o;
            if (oh) oh[m*128 + d] = __float2half_rn(o);
        }
    }
}

// ------------------------- launch -------------------------
extern "C" void kernel_launch(void* const* d_in, const int* in_sizes, int n_in,
                              void* d_out, int out_size) {
    const float* x       = (const float*)d_in[0];
    const float* adj     = (const float*)d_in[1];
    const float* gl_beta = (const float*)d_in[2];
    const float* gl_w1   = (const float*)d_in[3];
    const float* gl_w2   = (const float*)d_in[4];
    const float* gl_cw   = (const float*)d_in[5];
    const float* gl_cb   = (const float*)d_in[6];
    const float* cheb_w  = (const float*)d_in[7];
    const float* cheb_b  = (const float*)d_in[8];
    const float* out_w   = (const float*)d_in[9];
    const float* out_b   = (const float*)d_in[10];
    const float* ff_w1   = (const float*)d_in[11];
    const float* ff_b1   = (const float*)d_in[12];
    const float* ff_w2   = (const float*)d_in[13];
    const float* ff_b2   = (const float*)d_in[14];
    const float* ln1_g   = (const float*)d_in[15];
    const float* ln1_b   = (const float*)d_in[16];
    const float* ln2_g   = (const float*)d_in[17];
    const float* ln2_b   = (const float*)d_in[18];
    float* outp = (float*)d_out;

    const int SMEM128_3 = 2 * (2*(128*3) + 2*(128*3)) * 16;   // 49152
    const int SMEM128_2 = 2 * (1*(128*3) + 2*(128*3)) * 16;   // 36864
    const int SMEM64_3  = 2 * (2*(128*3) + 2*(64*3)) * 16;    // 36864
    cudaFuncSetAttribute(hmma_fp16<128,3>, cudaFuncAttributeMaxDynamicSharedMemorySize, SMEM128_3);
    cudaFuncSetAttribute(hmma_fp16<128,2>, cudaFuncAttributeMaxDynamicSharedMemorySize, SMEM128_2);
    cudaFuncSetAttribute(hmma_fp16<64,3>,  cudaFuncAttributeMaxDynamicSharedMemorySize, SMEM64_3);

    __half *pLh, *pLl, *pxth, *pxtl, *pt1h, *pt1l;
    __half *pxch, *pxcl, *poah, *po1h, *phh;
    __half *pwqh, *pwql, *powh, *powl, *pw1h, *pw1l, *pw2h, *pw2l;
    float *pqkv, *poproj, *pout1f, *pffnf;
    cudaGetSymbolAddress((void**)&pLh, g_Lh);   cudaGetSymbolAddress((void**)&pLl, g_Ll);
    cudaGetSymbolAddress((void**)&pxth, g_xth); cudaGetSymbolAddress((void**)&pxtl, g_xtl);
    cudaGetSymbolAddress((void**)&pt1h, g_t1h); cudaGetSymbolAddress((void**)&pt1l, g_t1l);
    cudaGetSymbolAddress((void**)&pxch, g_xcath); cudaGetSymbolAddress((void**)&pxcl, g_xcatl);
    cudaGetSymbolAddress((void**)&poah, g_oah);
    cudaGetSymbolAddress((void**)&po1h, g_o1h);
    cudaGetSymbolAddress((void**)&phh, g_hidh);
    cudaGetSymbolAddress((void**)&pwqh, g_wqh); cudaGetSymbolAddress((void**)&pwql, g_wql);
    cudaGetSymbolAddress((void**)&powh, g_owh); cudaGetSymbolAddress((void**)&powl, g_owl);
    cudaGetSymbolAddress((void**)&pw1h, g_w1h); cudaGetSymbolAddress((void**)&pw1l, g_w1l);
    cudaGetSymbolAddress((void**)&pw2h, g_w2h); cudaGetSymbolAddress((void**)&pw2l, g_w2l);
    cudaGetSymbolAddress((void**)&pqkv, g_qkv); cudaGetSymbolAddress((void**)&poproj, g_oproj);
    cudaGetSymbolAddress((void**)&pout1f, g_out1f); cudaGetSymbolAddress((void**)&pffnf, g_ffnf);

    // graph learning
    dim3 gG(NN, 3);
    gk1<<<gG, 256>>>(gl_w1, gl_w2, gl_beta, gl_cw, gl_cb, adj);
    gk2<<<gG, 256>>>();
    gk3<<<gG, 256>>>();
    gk4<<<gG, 256>>>();

    // layout + weight prep
    xsplitT<<<BT, 256>>>(x);
    pack_x<<<MTOK, 128>>>(x);
    wsplit<<<dim3(120,3), 256>>>(cheb_w, pwqh, pwql, 360, 120, XK, (long)360*120, (long)128*XK);
    wsplit<<<dim3(120,1), 256>>>(out_w, powh, powl, 120, 120, 128, 0, 0);
    wsplit<<<dim3(FF,1),  256>>>(ff_w1, pw1h, pw1l, 120, FF, 128, 0, 0);
    wsplit<<<dim3(120,1), 256>>>(ff_w2, pw2h, pw2l, FF, 120, FF, 0, 0);

    const long t1s = (long)MSP*NKP;
    const long xcs = (long)MTOK*XK;
    const long Ls  = (long)NROWP*NKP;

    // batched spatial t1 = L_br @ x (3-pass) -> t1_br + xcat_br[120..239]
    dim3 gsp(MSP/128, 3, 3);
    hmma_fp16<64,3><<<gsp, 256, SMEM64_3>>>(pxth, pxtl, NKP, pLh, pLl, NKP, NKP,
                                            nullptr, pt1h, pt1l, NKP, NN,
                                            nullptr, 0, nullptr, nullptr,
                                            pxch, pxcl, 120,
                                            0, Ls, t1s, 0, xcs, 0);
    // batched spatial t2 = 2*(L_br @ t1_br) - x (3-pass) -> xcat_br[240..359]
    hmma_fp16<64,3><<<gsp, 256, SMEM64_3>>>(pt1h, pt1l, NKP, pLh, pLl, NKP, NKP,
                                            nullptr, nullptr, nullptr, NKP, NN,
                                            nullptr, FLAG_T2, pxth, pxtl,
                                            pxch, pxcl, 240,
                                            t1s, Ls, 0, 0, xcs, 0);

    // batched QKV (3-pass): relu(xcat_br @ W_br + b_br)
    dim3 gqkv(MTOK/128, 1, 3);
    hmma_fp16<128,3><<<gqkv, 256, SMEM128_3>>>(pxch, pxcl, XK, pwqh, pwql, XK, XK,
                                               pqkv, nullptr, nullptr, DD, DD,
                                               cheb_b, FLAG_BIAS | FLAG_RELU,
                                               nullptr, nullptr, nullptr, nullptr, 0,
                                               xcs, (long)128*XK, (long)MTOK*DD, DD, 0, 0);

    attn_kernel<<<BB*NN, 128>>>(pqkv, pqkv + (size_t)MTOK*DD, pqkv + (size_t)2*MTOK*DD);

    dim3 gch(MTOK/128, 1, 1);
    // output projection (2-pass: A = attn output hi only)
    hmma_fp16<128,2><<<gch, 256, SMEM128_2>>>(poah, nullptr, 128, powh, powl, 128, 128,
                                              poproj, nullptr, nullptr, DD, DD,
                                              out_b, FLAG_BIAS, nullptr, nullptr,
                                              nullptr, nullptr, 0, 0, 0, 0, 0, 0, 0);
    // LN1 (fp32 out + fp16 hi)
    ln_kernel<<<MTOK/4, 128>>>(x, poproj, ln1_g, ln1_b, pout1f, po1h);

    // FFN1 (2-pass) -> hidden fp16 hi only; swapped grid for A reuse
    dim3 gf1(FF/128, MTOK/128, 1);
    hmma_fp16<128,2><<<gf1, 256, SMEM128_2>>>(po1h, nullptr, 128, pw1h, pw1l, 128, 128,
                                              nullptr, phh, nullptr, FF, FF,
                                              ff_b1, FLAG_BIAS | FLAG_RELU, nullptr, nullptr,
                                              nullptr, nullptr, 0, 0, 0, 0, 0, 0, 1);
    // FFN2 (2-pass)
    hmma_fp16<128,2><<<gch, 256, SMEM128_2>>>(phh, nullptr, FF, pw2h, pw2l, FF, FF,
                                              pffnf, nullptr, nullptr, DD, DD,
                                              ff_b2, FLAG_BIAS, nullptr, nullptr,
                                              nullptr, nullptr, 0, 0, 0, 0, 0, 0, 0);
    // LN2 -> output
    ln_kernel<<<MTOK/4, 128>>>(pout1f, pffnf, ln2_g, ln2_b, outp, nullptr);
}

// round 13
// speedup vs baseline: 1.5655x; 1.1926x over previous
#include <cuda_runtime.h>
#include <cuda_fp16.h>
#include <math.h>
#include <stdint.h>

#define NN 170
#define NKP 176            // padded node dim (K of spatial GEMM, multiple of 16)
#define NROWP 192          // padded L rows (3 x 64 col tiles)
#define TT 12
#define BB 32
#define DD 120
#define HH 8
#define HD 15
#define FF 2048
#define BT (BB*TT)          // 384
#define MTOK (BB*TT*NN)     // 65280 = 510*128
#define MSP (BT*DD)         // 46080 = 360*128
#define XK 368              // padded xcat K (360 -> 368)

#define FLAG_BIAS  1
#define FLAG_RELU  2
#define FLAG_T2    4        // epilogue: v = 2*acc - (Xh+Xl)

// ------------------------- static device scratch (zero-initialized) --------
__device__ float g_A[3*NN*NN];
__device__ float g_rs0[3*NN];
__device__ float g_rs1[3*NN];

__device__ __align__(16) __half g_Lh[3*NROWP*NKP];
__device__ __align__(16) __half g_Ll[3*NROWP*NKP];
__device__ __align__(16) __half g_xth[(size_t)MSP*NKP];
__device__ __align__(16) __half g_xtl[(size_t)MSP*NKP];     // only for T2 fp32 reconstruction
__device__ __align__(16) __half g_t1h[(size_t)3*MSP*NKP];   // per-branch, hi only
__device__ __align__(16) __half g_xcath[(size_t)3*MTOK*XK]; // per-branch, hi only
__device__ __align__(16) __half g_oah[(size_t)MTOK*128];    // hi only
__device__ __align__(16) __half g_o1h[(size_t)MTOK*128];    // hi only
__device__ __align__(16) __half g_hidh[(size_t)MTOK*FF];    // hi only
// B-operand weights, rows padded to tile boundary (always hi+lo)
__device__ __align__(16) __half g_wqh[3*128*XK];
__device__ __align__(16) __half g_wql[3*128*XK];
__device__ __align__(16) __half g_owh[128*128];
__device__ __align__(16) __half g_owl[128*128];
__device__ __align__(16) __half g_w1h[(size_t)FF*128];
__device__ __align__(16) __half g_w1l[(size_t)FF*128];
__device__ __align__(16) __half g_w2h[(size_t)128*FF];
__device__ __align__(16) __half g_w2l[(size_t)128*FF];
__device__ float g_qkv[(size_t)3*MTOK*DD];
__device__ float g_oproj[(size_t)MTOK*DD];
__device__ float g_out1f[(size_t)MTOK*DD];
__device__ float g_ffnf[(size_t)MTOK*DD];

// ------------------------- helpers -------------------------
__device__ __forceinline__ void hsplit(float v, __half &h, __half &l) {
    h = __float2half_rn(v);
    l = __float2half_rn(v - __half2float(h));
}
__device__ __forceinline__ uint32_t smem_u32(const void* p) {
    uint32_t a;
    asm("{ .reg .u64 t; cvta.to.shared.u64 t, %1; cvt.u32.u64 %0, t; }" : "=r"(a) : "l"(p));
    return a;
}
__device__ __forceinline__ void ldm4(uint32_t (&d)[4], uint32_t addr) {
    asm volatile("ldmatrix.sync.aligned.m8n8.x4.shared.b16 {%0,%1,%2,%3}, [%4];"
                 : "=r"(d[0]), "=r"(d[1]), "=r"(d[2]), "=r"(d[3]) : "r"(addr));
}
__device__ __forceinline__ void mma16816(float (&c)[4], const uint32_t (&a)[4],
                                         uint32_t b0, uint32_t b1) {
    asm volatile("mma.sync.aligned.m16n8k16.row.col.f32.f16.f16.f32 "
                 "{%0,%1,%2,%3}, {%4,%5,%6,%7}, {%8,%9}, {%0,%1,%2,%3};"
                 : "+f"(c[0]), "+f"(c[1]), "+f"(c[2]), "+f"(c[3])
                 : "r"(a[0]), "r"(a[1]), "r"(a[2]), "r"(a[3]), "r"(b0), "r"(b1));
}

// ------------------------- HMMA fp16 2-pass GEMM -----------------------
// D[M,N] = sum_k A[m,k]*B[n,k]; A hi-only (M x K, lda), B hi+lo (rows padded).
// Passes: Ah*Bh + Ah*Bl. K%16==0, M%128==0. Batched over blockIdx.z via strides.
template<int BN>
__global__ __launch_bounds__(256) void hmma_fp16(
        const __half* __restrict__ Ah, int lda,
        const __half* __restrict__ Bh, const __half* __restrict__ Bl, int ldb,
        int K,
        float* __restrict__ Cf, __half* __restrict__ Ch,
        int ldc, int Nout,
        const float* __restrict__ bias, int flags,
        const __half* __restrict__ Xh, const __half* __restrict__ Xl,
        __half* __restrict__ XCh, int xoff,
        long astride, long bstride, long cstride, int biasstride, long xcstride,
        int swapxy)
{
    constexpr int A16 = 128*3;              // 16B units for A (48B row pitch)
    constexpr int B16 = BN*3;
    constexpr int STAGE_BYTES = (A16 + 2*B16) * 16;
    constexpr int NB = (BN*4)/256;          // B 16B transfers per thread
    constexpr int WN = BN / 2;
    constexpr int NP = WN / 16;
    constexpr int BH = BN * 2;

    extern __shared__ __align__(16) char smem[];
    const uint32_t sbase = smem_u32(smem);
    const int tid = threadIdx.x;
    const int lane = tid & 31;
    const int wid = tid >> 5;
    const int wm = wid & 3, wn = wid >> 2;
    const int row0 = (swapxy ? blockIdx.y : blockIdx.x) * 128;
    const int col0 = (swapxy ? blockIdx.x : blockIdx.y) * BN;
    {   // batch offsets
        const int bz = blockIdx.z;
        Ah += (size_t)bz * astride;
        Bh += (size_t)bz * bstride;  Bl += (size_t)bz * bstride;
        if (Cf) Cf += (size_t)bz * cstride;
        if (Ch) Ch += (size_t)bz * cstride;
        if (bias) bias += bz * biasstride;
        if (XCh) XCh += (size_t)bz * xcstride;
    }

    float acc[2][2*NP][4];
    #pragma unroll
    for (int i = 0; i < 2; i++)
        #pragma unroll
        for (int j = 0; j < 2*NP; j++)
            #pragma unroll
            for (int e = 0; e < 4; e++) acc[i][j][e] = 0.f;

    const int arow = wm*32 + (lane & 15);
    const int akc  = lane >> 4;
    const uint32_t aoff = (uint32_t)(arow*3 + akc) * 16;
    const int brow = wn*WN + (lane & 7) + ((lane >> 4) & 1)*8;
    const int bkc  = (lane >> 3) & 1;
    const uint32_t boff = (uint32_t)(A16 + brow*3 + bkc) * 16;

    uint4 ra, rb[NB];

    auto gload = [&](int c) {
        const int k0 = c * 16;
        {
            int u = tid, r = u >> 1, kc = u & 1;
            ra = *(const uint4*)(Ah + (size_t)(row0 + r)*lda + k0 + kc*8);
        }
        #pragma unroll
        for (int t = 0; t < NB; t++) {
            int i = tid + t*256;
            int mat = i / BH, u = i % BH, r = u >> 1, kc = u & 1;
            rb[t] = *(const uint4*)((mat ? Bl : Bh) + (size_t)(col0 + r)*ldb + k0 + kc*8);
        }
    };
    auto sstore = [&](int st) {
        char* sb = smem + st * STAGE_BYTES;
        {
            int u = tid, r = u >> 1, kc = u & 1;
            *(uint4*)(sb + (uint32_t)(r*3 + kc)*16) = ra;
        }
        #pragma unroll
        for (int t = 0; t < NB; t++) {
            int i = tid + t*256;
            int mat = i / BH, u = i % BH, r = u >> 1, kc = u & 1;
            *(uint4*)(sb + (uint32_t)(A16 + mat*B16 + r*3 + kc)*16) = rb[t];
        }
    };

    const int nch = K >> 4;
    gload(0);
    sstore(0);

    for (int c = 0; c < nch; c++) {
        if (c + 1 < nch) gload(c + 1);   // prefetch into regs
        __syncthreads();                 // stage (c&1) stores visible; prev compute done

        const uint32_t sb = sbase + (uint32_t)(c & 1) * STAGE_BYTES;
        uint32_t ahf[2][4];
        #pragma unroll
        for (int mi = 0; mi < 2; mi++)
            ldm4(ahf[mi], sb + aoff + (uint32_t)mi * 768);
        uint32_t bhf[NP][4], blf[NP][4];
        #pragma unroll
        for (int np = 0; np < NP; np++) {
            uint32_t bd = sb + boff + (uint32_t)np * 768;
            ldm4(bhf[np], bd);
            ldm4(blf[np], bd + B16*16);
        }
        #pragma unroll
        for (int mi = 0; mi < 2; mi++)
            #pragma unroll
            for (int np = 0; np < NP; np++)
                #pragma unroll
                for (int hf = 0; hf < 2; hf++) {
                    int na = np*2 + hf;
                    mma16816(acc[mi][na], ahf[mi], bhf[np][2*hf], bhf[np][2*hf+1]);
                    mma16816(acc[mi][na], ahf[mi], blf[np][2*hf], blf[np][2*hf+1]);
                }

        if (c + 1 < nch) sstore((c + 1) & 1);   // opposite stage; ordered by next sync
    }

    // ---- epilogue
    float* smemf = (float*)smem;   // BN x 128 fp32 staging (pitch 132), spatial only
    if (XCh) __syncthreads();      // all ldmatrix reads of final stage complete

    const int lr = lane >> 2, lc = (lane & 3) * 2;
    #pragma unroll
    for (int mi = 0; mi < 2; mi++) {
        #pragma unroll
        for (int na = 0; na < 2*NP; na++) {
            int gr0 = row0 + wm*32 + mi*16 + lr;
            int gc0l = wn*WN + na*8 + lc;
            #pragma unroll
            for (int e = 0; e < 4; e++) {
                int gr = gr0 + (e >> 1) * 8;
                int gcl = gc0l + (e & 1);
                int gc = col0 + gcl;
                if (gc >= Nout) continue;
                float v = acc[mi][na][e];
                size_t ci = (size_t)gr * ldc + gc;
                if (flags & FLAG_T2)
                    v = 2.f*v - (__half2float(Xh[ci]) + __half2float(Xl[ci]));
                if (flags & FLAG_BIAS) v += bias[gc];
                if (flags & FLAG_RELU) v = fmaxf(v, 0.f);
                if (Cf) Cf[ci] = v;
                if (Ch) Ch[ci] = __float2half_rn(v);
                if (XCh) smemf[gcl*132 + (gr - row0)] = v;
            }
        }
    }

    if (XCh) {
        __syncthreads();
        for (int i = tid; i < BN*128; i += 256) {
            int gcl = i >> 7, grl = i & 127;
            int n = col0 + gcl;
            if (n >= Nout) continue;
            float v = smemf[gcl*132 + grl];
            int gr = row0 + grl;
            int bt = gr / DD, d = gr - bt*DD;
            size_t idx = ((size_t)bt*NN + n)*XK + xoff + d;
            XCh[idx] = __float2half_rn(v);
        }
    }
}

// ------------------------- graph learning -------------------------
__global__ void gk1(const float* __restrict__ w1, const float* __restrict__ w2,
                    const float* __restrict__ beta, const float* __restrict__ cw,
                    const float* __restrict__ cb, const float* __restrict__ adj) {
    int r = blockIdx.x, br = blockIdx.y;
    __shared__ float w1r[DD], w2r[DD];
    __shared__ float red[256];
    const float* W1 = w1 + (size_t)br*NN*DD;
    const float* W2 = w2 + (size_t)br*NN*DD;
    for (int i = threadIdx.x; i < DD; i += blockDim.x) { w1r[i] = W1[r*DD+i]; w2r[i] = W2[r*DD+i]; }
    __syncthreads();
    float cw0 = cw[br*2+0], cw1 = cw[br*2+1], cbv = cb[br];
    float mysum = 0.f;
    for (int c = threadIdx.x; c < NN; c += blockDim.x) {
        const float* w1c = W1 + c*DD;
        const float* w2c = W2 + c*DD;
        float d1 = 0.f, d2 = 0.f;
        for (int e = 0; e < DD; e++) { d1 += w1r[e]*w2c[e]; d2 += w2r[e]*w1c[e]; }
        float nw = d1 - d2;
        if (r == c) nw += beta[br*NN + r];
        nw = fmaxf(nw, 0.f);
        float ad = adj[r*NN + c];
        float gate = 1.f / (1.f + expf(-(cw0*nw + cw1*ad + cbv)));
        float a = gate*nw + (1.f - gate)*ad;
        g_A[(size_t)br*NN*NN + (size_t)r*NN + c] = a;
        mysum += a;
    }
    red[threadIdx.x] = mysum; __syncthreads();
    for (int s = 128; s > 0; s >>= 1) { if (threadIdx.x < s) red[threadIdx.x] += red[threadIdx.x+s]; __syncthreads(); }
    if (threadIdx.x == 0) g_rs0[br*NN + r] = red[0];
}
__global__ void gk2() {
    int r = blockIdx.x, br = blockIdx.y;
    __shared__ float red[256];
    float dr = rsqrtf(g_rs0[br*NN + r]);
    const float eps = 0.5f / (float)NN;
    float mysum = 0.f;
    for (int c = threadIdx.x; c < NN; c += blockDim.x) {
        float dc = rsqrtf(g_rs0[br*NN + c]);
        size_t idx = (size_t)br*NN*NN + (size_t)r*NN + c;
        float a = fmaxf(dr * g_A[idx] * dc - eps, 0.f);
        g_A[idx] = a; mysum += a;
    }
    red[threadIdx.x] = mysum; __syncthreads();
    for (int s = 128; s > 0; s >>= 1) { if (threadIdx.x < s) red[threadIdx.x] += red[threadIdx.x+s]; __syncthreads(); }
    if (threadIdx.x == 0) g_rs1[br*NN + r] = red[0];
}
__global__ void gk3() {
    int r = blockIdx.x, br = blockIdx.y;
    __shared__ float red[256];
    float dr = rsqrtf(g_rs1[br*NN + r]);
    float mysum = 0.f;
    for (int c = threadIdx.x; c < NN; c += blockDim.x) {
        float dc = rsqrtf(g_rs1[br*NN + c]);
        size_t idx = (size_t)br*NN*NN + (size_t)r*NN + c;
        float g = dr * g_A[idx] * dc;
        g_A[idx] = g; mysum += g;
    }
    red[threadIdx.x] = mysum; __syncthreads();
    for (int s = 128; s > 0; s >>= 1) { if (threadIdx.x < s) red[threadIdx.x] += red[threadIdx.x+s]; __syncthreads(); }
    if (threadIdx.x == 0) g_rs0[br*NN + r] = red[0];
}
__global__ void gk4() {
    int r = blockIdx.x, br = blockIdx.y;
    float er = rsqrtf(g_rs0[br*NN + r]);
    for (int c = threadIdx.x; c < NKP; c += blockDim.x) {
        float L = 0.f;
        if (c < NN) {
            float ec = rsqrtf(g_rs0[br*NN + c]);
            L = ((r == c) ? 1.f : 0.f) - er * g_A[(size_t)br*NN*NN + (size_t)r*NN + c] * ec;
        }
        __half h, l; hsplit(L, h, l);
        size_t idx = (size_t)br*NROWP*NKP + (size_t)r*NKP + c;
        g_Lh[idx] = h; g_Ll[idx] = l;
    }
}

// ------------------------- layout / split kernels -------------------------
__global__ void xsplitT(const float* __restrict__ x) {
    __shared__ float s[64*121];
    int bt = blockIdx.x;
    for (int n0 = 0; n0 < NN; n0 += 64) {
        int nrows = (NN - n0 < 64) ? (NN - n0) : 64;
        for (int i = threadIdx.x; i < nrows*DD; i += 256) {
            int nn = i / DD, d = i - nn*DD;
            s[nn*121 + d] = x[((size_t)bt*NN + n0 + nn)*DD + d];
        }
        __syncthreads();
        for (int i = threadIdx.x; i < DD*64; i += 256) {
            int d = i >> 6, nn = i & 63;
            int n = n0 + nn;
            if (nn < nrows) {
                __half h, l; hsplit(s[nn*121 + d], h, l);
                size_t idx = ((size_t)bt*DD + d)*NKP + n;
                g_xth[idx] = h; g_xtl[idx] = l;
            }
        }
        __syncthreads();
    }
}
// x -> cols [0,120) of all three branch xcat buffers (hi only)
__global__ void pack_x(const float* __restrict__ x) {
    size_t r = blockIdx.x;
    int d = threadIdx.x;
    if (d < DD) {
        __half h = __float2half_rn(x[r*DD + d]);
        #pragma unroll
        for (int br = 0; br < 3; br++)
            g_xcath[(size_t)br*MTOK*XK + r*XK + d] = h;
    }
}
__global__ void wsplit(const float* __restrict__ src, __half* __restrict__ dh,
                       __half* __restrict__ dl, int K, int N, int ldk,
                       long src_bstride, long dst_bstride) {
    int n = blockIdx.x;
    int br = blockIdx.y;
    src += (size_t)br * src_bstride;
    dh  += (size_t)br * dst_bstride;
    dl  += (size_t)br * dst_bstride;
    for (int k = threadIdx.x; k < K; k += blockDim.x) {
        __half h, l; hsplit(src[(size_t)k*N + n], h, l);
        dh[(size_t)n*ldk + k] = h;
        dl[(size_t)n*ldk + k] = l;
    }
}

// ------------------------- attention -------------------------
__global__ void attn_kernel(const float* __restrict__ q, const float* __restrict__ k,
                            const float* __restrict__ v) {
    int bn = blockIdx.x;
    int b = bn / NN, n = bn % NN;
    __shared__ float qs[TT][DD], ks[TT][DD], vs[TT][DD];
    for (int i = threadIdx.x; i < TT*DD; i += blockDim.x) {
        int t = i / DD, d = i % DD;
        size_t gi = (((size_t)(b*TT + t))*NN + n)*DD + d;
        qs[t][d] = q[gi]; ks[t][d] = k[gi]; vs[t][d] = v[gi];
    }
    __syncthreads();
    int tid = threadIdx.x;
    if (tid < HH*TT) {
        int h = tid / TT, qi = tid % TT;
        const float scale = rsqrtf((float)HD);
        float s[TT]; float mx = -1e30f;
        #pragma unroll
        for (int j = 0; j < TT; j++) {
            float acc = 0.f;
            #pragma unroll
            for (int e = 0; e < HD; e++) acc += qs[qi][h*HD+e] * ks[j][h*HD+e];
            acc *= scale; s[j] = acc; mx = fmaxf(mx, acc);
        }
        float sum = 0.f;
        #pragma unroll
        for (int j = 0; j < TT; j++) { s[j] = expf(s[j]-mx); sum += s[j]; }
        float inv = 1.f / sum;
        size_t orow = ((size_t)(b*TT + qi))*NN + n;
        #pragma unroll
        for (int e = 0; e < HD; e++) {
            float acc = 0.f;
            #pragma unroll
            for (int j = 0; j < TT; j++) acc += s[j] * vs[j][h*HD+e];
            g_oah[orow*128 + h*HD + e] = __float2half_rn(acc * inv);
        }
    }
}

// ------------------------- residual + layernorm -------------------------
__global__ void ln_kernel(const float* __restrict__ xa, const float* __restrict__ xb,
                          const float* __restrict__ gg, const float* __restrict__ bb,
                          float* __restrict__ outp, __half* __restrict__ oh) {
    int warp = threadIdx.x >> 5, lane = threadIdx.x & 31;
    size_t m = (size_t)blockIdx.x * 4 + warp;
    if (m >= MTOK) return;
    size_t ia = m * DD;
    float v[4]; float s = 0.f;
    #pragma unroll
    for (int i = 0; i < 4; i++) {
        int d = lane + 32*i;
        float val = (d < DD) ? (xa[ia+d] + xb[ia+d]) : 0.f;
        v[i] = val; s += val;
    }
    #pragma unroll
    for (int o = 16; o > 0; o >>= 1) s += __shfl_xor_sync(0xffffffffu, s, o);
    float mean = s * (1.f / DD);
    float vsum = 0.f;
    #pragma unroll
    for (int i = 0; i < 4; i++) {
        int d = lane + 32*i;
        if (d < DD) { float df = v[i]-mean; vsum += df*df; }
    }
    #pragma unroll
    for (int o = 16; o > 0; o >>= 1) vsum += __shfl_xor_sync(0xffffffffu, vsum, o);
    float inv = rsqrtf(vsum * (1.f / DD) + 1e-5f);
    #pragma unroll
    for (int i = 0; i < 4; i++) {
        int d = lane + 32*i;
        if (d < DD) {
            float o = (v[i]-mean)*inv*gg[d] + bb[d];
            if (outp) outp[ia + d] = o;
            if (oh) oh[m*128 + d] = __float2half_rn(o);
        }
    }
}

// ------------------------- launch -------------------------
extern "C" void kernel_launch(void* const* d_in, const int* in_sizes, int n_in,
                              void* d_out, int out_size) {
    const float* x       = (const float*)d_in[0];
    const float* adj     = (const float*)d_in[1];
    const float* gl_beta = (const float*)d_in[2];
    const float* gl_w1   = (const float*)d_in[3];
    const float* gl_w2   = (const float*)d_in[4];
    const float* gl_cw   = (const float*)d_in[5];
    const float* gl_cb   = (const float*)d_in[6];
    const float* cheb_w  = (const float*)d_in[7];
    const float* cheb_b  = (const float*)d_in[8];
    const float* out_w   = (const float*)d_in[9];
    const float* out_b   = (const float*)d_in[10];
    const float* ff_w1   = (const float*)d_in[11];
    const float* ff_b1   = (const float*)d_in[12];
    const float* ff_w2   = (const float*)d_in[13];
    const float* ff_b2   = (const float*)d_in[14];
    const float* ln1_g   = (const float*)d_in[15];
    const float* ln1_b   = (const float*)d_in[16];
    const float* ln2_g   = (const float*)d_in[17];
    const float* ln2_b   = (const float*)d_in[18];
    float* outp = (float*)d_out;

    const int SMEM128 = 2 * ((128*3) + 2*(128*3)) * 16;   // 36864
    const int SMEM64  = 36864;   // stage 2x12288=24576; fp32 scatter staging needs 33792
    cudaFuncSetAttribute(hmma_fp16<128>, cudaFuncAttributeMaxDynamicSharedMemorySize, SMEM128);
    cudaFuncSetAttribute(hmma_fp16<64>,  cudaFuncAttributeMaxDynamicSharedMemorySize, SMEM64);

    __half *pLh, *pLl, *pxth, *pxtl, *pt1h;
    __half *pxch, *poah, *po1h, *phh;
    __half *pwqh, *pwql, *powh, *powl, *pw1h, *pw1l, *pw2h, *pw2l;
    float *pqkv, *poproj, *pout1f, *pffnf;
    cudaGetSymbolAddress((void**)&pLh, g_Lh);   cudaGetSymbolAddress((void**)&pLl, g_Ll);
    cudaGetSymbolAddress((void**)&pxth, g_xth); cudaGetSymbolAddress((void**)&pxtl, g_xtl);
    cudaGetSymbolAddress((void**)&pt1h, g_t1h);
    cudaGetSymbolAddress((void**)&pxch, g_xcath);
    cudaGetSymbolAddress((void**)&poah, g_oah);
    cudaGetSymbolAddress((void**)&po1h, g_o1h);
    cudaGetSymbolAddress((void**)&phh, g_hidh);
    cudaGetSymbolAddress((void**)&pwqh, g_wqh); cudaGetSymbolAddress((void**)&pwql, g_wql);
    cudaGetSymbolAddress((void**)&powh, g_owh); cudaGetSymbolAddress((void**)&powl, g_owl);
    cudaGetSymbolAddress((void**)&pw1h, g_w1h); cudaGetSymbolAddress((void**)&pw1l, g_w1l);
    cudaGetSymbolAddress((void**)&pw2h, g_w2h); cudaGetSymbolAddress((void**)&pw2l, g_w2l);
    cudaGetSymbolAddress((void**)&pqkv, g_qkv); cudaGetSymbolAddress((void**)&poproj, g_oproj);
    cudaGetSymbolAddress((void**)&pout1f, g_out1f); cudaGetSymbolAddress((void**)&pffnf, g_ffnf);

    // graph learning
    dim3 gG(NN, 3);
    gk1<<<gG, 256>>>(gl_w1, gl_w2, gl_beta, gl_cw, gl_cb, adj);
    gk2<<<gG, 256>>>();
    gk3<<<gG, 256>>>();
    gk4<<<gG, 256>>>();

    // layout + weight prep
    xsplitT<<<BT, 256>>>(x);
    pack_x<<<MTOK, 128>>>(x);
    wsplit<<<dim3(120,3), 256>>>(cheb_w, pwqh, pwql, 360, 120, XK, (long)360*120, (long)128*XK);
    wsplit<<<dim3(120,1), 256>>>(out_w, powh, powl, 120, 120, 128, 0, 0);
    wsplit<<<dim3(FF,1),  256>>>(ff_w1, pw1h, pw1l, 120, FF, 128, 0, 0);
    wsplit<<<dim3(120,1), 256>>>(ff_w2, pw2h, pw2l, FF, 120, FF, 0, 0);

    const long t1s = (long)MSP*NKP;
    const long xcs = (long)MTOK*XK;
    const long Ls  = (long)NROWP*NKP;

    // batched spatial t1 = L_br @ x -> t1_br (hi) + xcat_br[120..239]
    dim3 gsp(MSP/128, 3, 3);
    hmma_fp16<64><<<gsp, 256, SMEM64>>>(pxth, NKP, pLh, pLl, NKP, NKP,
                                        nullptr, pt1h, NKP, NN,
                                        nullptr, 0, nullptr, nullptr,
                                        pxch, 120,
                                        0, Ls, t1s, 0, xcs, 0);
    // batched spatial t2 = 2*(L_br @ t1_br) - x -> xcat_br[240..359]
    hmma_fp16<64><<<gsp, 256, SMEM64>>>(pt1h, NKP, pLh, pLl, NKP, NKP,
                                        nullptr, nullptr, NKP, NN,
                                        nullptr, FLAG_T2, pxth, pxtl,
                                        pxch, 240,
                                        t1s, Ls, 0, 0, xcs, 0);

    // batched QKV: relu(xcat_br @ W_br + b_br)
    dim3 gqkv(MTOK/128, 1, 3);
    hmma_fp16<128><<<gqkv, 256, SMEM128>>>(pxch, XK, pwqh, pwql, XK, XK,
                                           pqkv, nullptr, DD, DD,
                                           cheb_b, FLAG_BIAS | FLAG_RELU,
                                           nullptr, nullptr, nullptr, 0,
                                           xcs, (long)128*XK, (long)MTOK*DD, DD, 0, 0);

    attn_kernel<<<BB*NN, 128>>>(pqkv, pqkv + (size_t)MTOK*DD, pqkv + (size_t)2*MTOK*DD);

    dim3 gch(MTOK/128, 1, 1);
    // output projection
    hmma_fp16<128><<<gch, 256, SMEM128>>>(poah, 128, powh, powl, 128, 128,
                                          poproj, nullptr, DD, DD,
                                          out_b, FLAG_BIAS, nullptr, nullptr,
                                          nullptr, 0, 0, 0, 0, 0, 0, 0);
    // LN1 (fp32 out + fp16 hi)
    ln_kernel<<<MTOK/4, 128>>>(x, poproj, ln1_g, ln1_b, pout1f, po1h);

    // FFN1 -> hidden fp16 hi; swapped grid for A reuse
    dim3 gf1(FF/128, MTOK/128, 1);
    hmma_fp16<128><<<gf1, 256, SMEM128>>>(po1h, 128, pw1h, pw1l, 128, 128,
                                          nullptr, phh, FF, FF,
                                          ff_b1, FLAG_BIAS | FLAG_RELU, nullptr, nullptr,
                                          nullptr, 0, 0, 0, 0, 0, 0, 1);
    // FFN2
    hmma_fp16<128><<<gch, 256, SMEM128>>>(phh, FF, pw2h, pw2l, FF, FF,
                                          pffnf, nullptr, DD, DD,
                                          ff_b2, FLAG_BIAS, nullptr, nullptr,
                                          nullptr, 0, 0, 0, 0, 0, 0, 0);
    // LN2 -> output
    ln_kernel<<<MTOK/4, 128>>>(pout1f, pffnf, ln2_g, ln2_b, outp, nullptr);
}

// round 14
// speedup vs baseline: 1.7728x; 1.1324x over previous
#include <cuda_runtime.h>
#include <cuda_fp16.h>
#include <math.h>
#include <stdint.h>

#define NN 170
#define NKP 176            // padded node dim (K of spatial GEMM, multiple of 16)
#define NROWP 192          // padded L rows (3 x 64 col tiles)
#define TT 12
#define BB 32
#define DD 120
#define HH 8
#define HD 15
#define FF 2048
#define BT (BB*TT)          // 384
#define MTOK (BB*TT*NN)     // 65280 = 510*128
#define MSP (BT*DD)         // 46080 = 360*128
#define XK 368              // padded xcat K (360 -> 368)

#define FLAG_BIAS  1
#define FLAG_RELU  2
#define FLAG_T2    4        // epilogue: v = 2*acc - (Xh+Xl)

// ------------------------- static device scratch (zero-initialized) --------
__device__ float g_A[3*NN*NN];
__device__ float g_rs0[3*NN];
__device__ float g_rs1[3*NN];

__device__ __align__(16) __half g_Lh[3*NROWP*NKP];
__device__ __align__(16) __half g_Ll[3*NROWP*NKP];
__device__ __align__(16) __half g_xth[(size_t)MSP*NKP];
__device__ __align__(16) __half g_xtl[(size_t)MSP*NKP];     // only for T2 fp32 reconstruction
__device__ __align__(16) __half g_t1h[(size_t)3*MSP*NKP];   // per-branch, hi only
__device__ __align__(16) __half g_xcath[(size_t)3*MTOK*XK]; // per-branch, hi only
__device__ __align__(16) __half g_oah[(size_t)MTOK*128];    // hi only
__device__ __align__(16) __half g_o1h[(size_t)MTOK*128];    // hi only
__device__ __align__(16) __half g_hidh[(size_t)MTOK*FF];    // hi only
// B-operand weights, rows padded to tile boundary
__device__ __align__(16) __half g_wqh[3*128*XK];
__device__ __align__(16) __half g_wql[3*128*XK];
__device__ __align__(16) __half g_owh[128*128];
__device__ __align__(16) __half g_owl[128*128];
__device__ __align__(16) __half g_w1h[(size_t)FF*128];      // hi only (1-pass FFN1)
__device__ __align__(16) __half g_w2h[(size_t)128*FF];      // hi only (1-pass FFN2)
__device__ float g_qkv[(size_t)3*MTOK*DD];
__device__ float g_oproj[(size_t)MTOK*DD];
__device__ float g_out1f[(size_t)MTOK*DD];
__device__ float g_ffnf[(size_t)MTOK*DD];

// ------------------------- helpers -------------------------
__device__ __forceinline__ void hsplit(float v, __half &h, __half &l) {
    h = __float2half_rn(v);
    l = __float2half_rn(v - __half2float(h));
}
__device__ __forceinline__ uint32_t smem_u32(const void* p) {
    uint32_t a;
    asm("{ .reg .u64 t; cvta.to.shared.u64 t, %1; cvt.u32.u64 %0, t; }" : "=r"(a) : "l"(p));
    return a;
}
__device__ __forceinline__ void ldm4(uint32_t (&d)[4], uint32_t addr) {
    asm volatile("ldmatrix.sync.aligned.m8n8.x4.shared.b16 {%0,%1,%2,%3}, [%4];"
                 : "=r"(d[0]), "=r"(d[1]), "=r"(d[2]), "=r"(d[3]) : "r"(addr));
}
__device__ __forceinline__ void mma16816(float (&c)[4], const uint32_t (&a)[4],
                                         uint32_t b0, uint32_t b1) {
    asm volatile("mma.sync.aligned.m16n8k16.row.col.f32.f16.f16.f32 "
                 "{%0,%1,%2,%3}, {%4,%5,%6,%7}, {%8,%9}, {%0,%1,%2,%3};"
                 : "+f"(c[0]), "+f"(c[1]), "+f"(c[2]), "+f"(c[3])
                 : "r"(a[0]), "r"(a[1]), "r"(a[2]), "r"(a[3]), "r"(b0), "r"(b1));
}

// ------------------------- HMMA fp16 GEMM ------------------------------
// D[M,N] = sum_k A[m,k]*B[n,k]; A hi-only (M x K, lda).
// NPASS=2: Ah*Bh + Ah*Bl (B hi+lo). NPASS=1: Ah*Bh only (Bl unused).
// K%16==0, M%128==0. Batched over blockIdx.z via strides (0 = shared).
template<int BN, int NPASS>
__global__ __launch_bounds__(256) void hmma_fp16(
        const __half* __restrict__ Ah, int lda,
        const __half* __restrict__ Bh, const __half* __restrict__ Bl, int ldb,
        int K,
        float* __restrict__ Cf, __half* __restrict__ Ch,
        int ldc, int Nout,
        const float* __restrict__ bias, int flags,
        const __half* __restrict__ Xh, const __half* __restrict__ Xl,
        __half* __restrict__ XCh, int xoff,
        long astride, long bstride, long cstride, int biasstride, long xcstride,
        int swapxy)
{
    constexpr int A16 = 128*3;              // 16B units for A (48B row pitch)
    constexpr int B16 = BN*3;
    constexpr int STAGE_BYTES = (A16 + NPASS*B16) * 16;
    constexpr int NB = (BN*2*NPASS)/256;    // B 16B transfers per thread
    constexpr int WN = BN / 2;
    constexpr int NP = WN / 16;
    constexpr int BH = BN * 2;

    extern __shared__ __align__(16) char smem[];
    const uint32_t sbase = smem_u32(smem);
    const int tid = threadIdx.x;
    const int lane = tid & 31;
    const int wid = tid >> 5;
    const int wm = wid & 3, wn = wid >> 2;
    const int row0 = (swapxy ? blockIdx.y : blockIdx.x) * 128;
    const int col0 = (swapxy ? blockIdx.x : blockIdx.y) * BN;
    {   // batch offsets
        const int bz = blockIdx.z;
        Ah += (size_t)bz * astride;
        Bh += (size_t)bz * bstride;
        if (NPASS == 2) Bl += (size_t)bz * bstride;
        if (Cf) Cf += (size_t)bz * cstride;
        if (Ch) Ch += (size_t)bz * cstride;
        if (bias) bias += bz * biasstride;
        if (XCh) XCh += (size_t)bz * xcstride;
    }

    float acc[2][2*NP][4];
    #pragma unroll
    for (int i = 0; i < 2; i++)
        #pragma unroll
        for (int j = 0; j < 2*NP; j++)
            #pragma unroll
            for (int e = 0; e < 4; e++) acc[i][j][e] = 0.f;

    const int arow = wm*32 + (lane & 15);
    const int akc  = lane >> 4;
    const uint32_t aoff = (uint32_t)(arow*3 + akc) * 16;
    const int brow = wn*WN + (lane & 7) + ((lane >> 4) & 1)*8;
    const int bkc  = (lane >> 3) & 1;
    const uint32_t boff = (uint32_t)(A16 + brow*3 + bkc) * 16;

    uint4 ra, rb[NB];

    auto gload = [&](int c) {
        const int k0 = c * 16;
        {
            int u = tid, r = u >> 1, kc = u & 1;
            ra = *(const uint4*)(Ah + (size_t)(row0 + r)*lda + k0 + kc*8);
        }
        #pragma unroll
        for (int t = 0; t < NB; t++) {
            int i = tid + t*256;
            int mat = i / BH, u = i % BH, r = u >> 1, kc = u & 1;
            rb[t] = *(const uint4*)((mat ? Bl : Bh) + (size_t)(col0 + r)*ldb + k0 + kc*8);
        }
    };
    auto sstore = [&](int st) {
        char* sb = smem + st * STAGE_BYTES;
        {
            int u = tid, r = u >> 1, kc = u & 1;
            *(uint4*)(sb + (uint32_t)(r*3 + kc)*16) = ra;
        }
        #pragma unroll
        for (int t = 0; t < NB; t++) {
            int i = tid + t*256;
            int mat = i / BH, u = i % BH, r = u >> 1, kc = u & 1;
            *(uint4*)(sb + (uint32_t)(A16 + mat*B16 + r*3 + kc)*16) = rb[t];
        }
    };

    const int nch = K >> 4;
    gload(0);
    sstore(0);

    for (int c = 0; c < nch; c++) {
        if (c + 1 < nch) gload(c + 1);   // prefetch into regs
        __syncthreads();                 // stage (c&1) stores visible; prev compute done

        const uint32_t sb = sbase + (uint32_t)(c & 1) * STAGE_BYTES;
        uint32_t ahf[2][4];
        #pragma unroll
        for (int mi = 0; mi < 2; mi++)
            ldm4(ahf[mi], sb + aoff + (uint32_t)mi * 768);
        uint32_t bhf[NP][4], blf[NP][4];
        #pragma unroll
        for (int np = 0; np < NP; np++) {
            uint32_t bd = sb + boff + (uint32_t)np * 768;
            ldm4(bhf[np], bd);
            if (NPASS == 2) ldm4(blf[np], bd + B16*16);
        }
        #pragma unroll
        for (int mi = 0; mi < 2; mi++)
            #pragma unroll
            for (int np = 0; np < NP; np++)
                #pragma unroll
                for (int hf = 0; hf < 2; hf++) {
                    int na = np*2 + hf;
                    mma16816(acc[mi][na], ahf[mi], bhf[np][2*hf], bhf[np][2*hf+1]);
                    if (NPASS == 2)
                        mma16816(acc[mi][na], ahf[mi], blf[np][2*hf], blf[np][2*hf+1]);
                }

        if (c + 1 < nch) sstore((c + 1) & 1);   // opposite stage; ordered by next sync
    }

    // ---- epilogue
    float* smemf = (float*)smem;   // BN x 128 fp32 staging (pitch 132), spatial only
    if (XCh) __syncthreads();      // all ldmatrix reads of final stage complete

    const int lr = lane >> 2, lc = (lane & 3) * 2;
    #pragma unroll
    for (int mi = 0; mi < 2; mi++) {
        #pragma unroll
        for (int na = 0; na < 2*NP; na++) {
            int gr0 = row0 + wm*32 + mi*16 + lr;
            int gc0l = wn*WN + na*8 + lc;
            #pragma unroll
            for (int e = 0; e < 4; e++) {
                int gr = gr0 + (e >> 1) * 8;
                int gcl = gc0l + (e & 1);
                int gc = col0 + gcl;
                if (gc >= Nout) continue;
                float v = acc[mi][na][e];
                size_t ci = (size_t)gr * ldc + gc;
                if (flags & FLAG_T2)
                    v = 2.f*v - (__half2float(Xh[ci]) + __half2float(Xl[ci]));
                if (flags & FLAG_BIAS) v += bias[gc];
                if (flags & FLAG_RELU) v = fmaxf(v, 0.f);
                if (Cf) Cf[ci] = v;
                if (Ch) Ch[ci] = __float2half_rn(v);
                if (XCh) smemf[gcl*132 + (gr - row0)] = v;
            }
        }
    }

    if (XCh) {
        __syncthreads();
        for (int i = tid; i < BN*128; i += 256) {
            int gcl = i >> 7, grl = i & 127;
            int n = col0 + gcl;
            if (n >= Nout) continue;
            float v = smemf[gcl*132 + grl];
            int gr = row0 + grl;
            int bt = gr / DD, d = gr - bt*DD;
            size_t idx = ((size_t)bt*NN + n)*XK + xoff + d;
            XCh[idx] = __float2half_rn(v);
        }
    }
}

// ------------------------- graph learning -------------------------
__global__ void gk1(const float* __restrict__ w1, const float* __restrict__ w2,
                    const float* __restrict__ beta, const float* __restrict__ cw,
                    const float* __restrict__ cb, const float* __restrict__ adj) {
    int r = blockIdx.x, br = blockIdx.y;
    __shared__ float w1r[DD], w2r[DD];
    __shared__ float red[256];
    const float* W1 = w1 + (size_t)br*NN*DD;
    const float* W2 = w2 + (size_t)br*NN*DD;
    for (int i = threadIdx.x; i < DD; i += blockDim.x) { w1r[i] = W1[r*DD+i]; w2r[i] = W2[r*DD+i]; }
    __syncthreads();
    float cw0 = cw[br*2+0], cw1 = cw[br*2+1], cbv = cb[br];
    float mysum = 0.f;
    for (int c = threadIdx.x; c < NN; c += blockDim.x) {
        const float* w1c = W1 + c*DD;
        const float* w2c = W2 + c*DD;
        float d1 = 0.f, d2 = 0.f;
        for (int e = 0; e < DD; e++) { d1 += w1r[e]*w2c[e]; d2 += w2r[e]*w1c[e]; }
        float nw = d1 - d2;
        if (r == c) nw += beta[br*NN + r];
        nw = fmaxf(nw, 0.f);
        float ad = adj[r*NN + c];
        float gate = 1.f / (1.f + expf(-(cw0*nw + cw1*ad + cbv)));
        float a = gate*nw + (1.f - gate)*ad;
        g_A[(size_t)br*NN*NN + (size_t)r*NN + c] = a;
        mysum += a;
    }
    red[threadIdx.x] = mysum; __syncthreads();
    for (int s = 128; s > 0; s >>= 1) { if (threadIdx.x < s) red[threadIdx.x] += red[threadIdx.x+s]; __syncthreads(); }
    if (threadIdx.x == 0) g_rs0[br*NN + r] = red[0];
}
__global__ void gk2() {
    int r = blockIdx.x, br = blockIdx.y;
    __shared__ float red[256];
    float dr = rsqrtf(g_rs0[br*NN + r]);
    const float eps = 0.5f / (float)NN;
    float mysum = 0.f;
    for (int c = threadIdx.x; c < NN; c += blockDim.x) {
        float dc = rsqrtf(g_rs0[br*NN + c]);
        size_t idx = (size_t)br*NN*NN + (size_t)r*NN + c;
        float a = fmaxf(dr * g_A[idx] * dc - eps, 0.f);
        g_A[idx] = a; mysum += a;
    }
    red[threadIdx.x] = mysum; __syncthreads();
    for (int s = 128; s > 0; s >>= 1) { if (threadIdx.x < s) red[threadIdx.x] += red[threadIdx.x+s]; __syncthreads(); }
    if (threadIdx.x == 0) g_rs1[br*NN + r] = red[0];
}
__global__ void gk3() {
    int r = blockIdx.x, br = blockIdx.y;
    __shared__ float red[256];
    float dr = rsqrtf(g_rs1[br*NN + r]);
    float mysum = 0.f;
    for (int c = threadIdx.x; c < NN; c += blockDim.x) {
        float dc = rsqrtf(g_rs1[br*NN + c]);
        size_t idx = (size_t)br*NN*NN + (size_t)r*NN + c;
        float g = dr * g_A[idx] * dc;
        g_A[idx] = g; mysum += g;
    }
    red[threadIdx.x] = mysum; __syncthreads();
    for (int s = 128; s > 0; s >>= 1) { if (threadIdx.x < s) red[threadIdx.x] += red[threadIdx.x+s]; __syncthreads(); }
    if (threadIdx.x == 0) g_rs0[br*NN + r] = red[0];
}
__global__ void gk4() {
    int r = blockIdx.x, br = blockIdx.y;
    float er = rsqrtf(g_rs0[br*NN + r]);
    for (int c = threadIdx.x; c < NKP; c += blockDim.x) {
        float L = 0.f;
        if (c < NN) {
            float ec = rsqrtf(g_rs0[br*NN + c]);
            L = ((r == c) ? 1.f : 0.f) - er * g_A[(size_t)br*NN*NN + (size_t)r*NN + c] * ec;
        }
        __half h, l; hsplit(L, h, l);
        size_t idx = (size_t)br*NROWP*NKP + (size_t)r*NKP + c;
        g_Lh[idx] = h; g_Ll[idx] = l;
    }
}

// ------------------------- layout / split kernels -------------------------
__global__ void xsplitT(const float* __restrict__ x) {
    __shared__ float s[64*121];
    int bt = blockIdx.x;
    for (int n0 = 0; n0 < NN; n0 += 64) {
        int nrows = (NN - n0 < 64) ? (NN - n0) : 64;
        for (int i = threadIdx.x; i < nrows*DD; i += 256) {
            int nn = i / DD, d = i - nn*DD;
            s[nn*121 + d] = x[((size_t)bt*NN + n0 + nn)*DD + d];
        }
        __syncthreads();
        for (int i = threadIdx.x; i < DD*64; i += 256) {
            int d = i >> 6, nn = i & 63;
            int n = n0 + nn;
            if (nn < nrows) {
                __half h, l; hsplit(s[nn*121 + d], h, l);
                size_t idx = ((size_t)bt*DD + d)*NKP + n;
                g_xth[idx] = h; g_xtl[idx] = l;
            }
        }
        __syncthreads();
    }
}
// x -> cols [0,120) of all three branch xcat buffers (hi only)
__global__ void pack_x(const float* __restrict__ x) {
    size_t r = blockIdx.x;
    int d = threadIdx.x;
    if (d < DD) {
        __half h = __float2half_rn(x[r*DD + d]);
        #pragma unroll
        for (int br = 0; br < 3; br++)
            g_xcath[(size_t)br*MTOK*XK + r*XK + d] = h;
    }
}
// transpose+split; dl==nullptr -> hi only
__global__ void wsplit(const float* __restrict__ src, __half* __restrict__ dh,
                       __half* __restrict__ dl, int K, int N, int ldk,
                       long src_bstride, long dst_bstride) {
    int n = blockIdx.x;
    int br = blockIdx.y;
    src += (size_t)br * src_bstride;
    dh  += (size_t)br * dst_bstride;
    if (dl) dl += (size_t)br * dst_bstride;
    for (int k = threadIdx.x; k < K; k += blockDim.x) {
        __half h, l; hsplit(src[(size_t)k*N + n], h, l);
        dh[(size_t)n*ldk + k] = h;
        if (dl) dl[(size_t)n*ldk + k] = l;
    }
}

// ------------------------- attention -------------------------
__global__ void attn_kernel(const float* __restrict__ q, const float* __restrict__ k,
                            const float* __restrict__ v) {
    int bn = blockIdx.x;
    int b = bn / NN, n = bn % NN;
    __shared__ float qs[TT][DD], ks[TT][DD], vs[TT][DD];
    for (int i = threadIdx.x; i < TT*DD; i += blockDim.x) {
        int t = i / DD, d = i % DD;
        size_t gi = (((size_t)(b*TT + t))*NN + n)*DD + d;
        qs[t][d] = q[gi]; ks[t][d] = k[gi]; vs[t][d] = v[gi];
    }
    __syncthreads();
    int tid = threadIdx.x;
    if (tid < HH*TT) {
        int h = tid / TT, qi = tid % TT;
        const float scale = rsqrtf((float)HD);
        float s[TT]; float mx = -1e30f;
        #pragma unroll
        for (int j = 0; j < TT; j++) {
            float acc = 0.f;
            #pragma unroll
            for (int e = 0; e < HD; e++) acc += qs[qi][h*HD+e] * ks[j][h*HD+e];
            acc *= scale; s[j] = acc; mx = fmaxf(mx, acc);
        }
        float sum = 0.f;
        #pragma unroll
        for (int j = 0; j < TT; j++) { s[j] = expf(s[j]-mx); sum += s[j]; }
        float inv = 1.f / sum;
        size_t orow = ((size_t)(b*TT + qi))*NN + n;
        #pragma unroll
        for (int e = 0; e < HD; e++) {
            float acc = 0.f;
            #pragma unroll
            for (int j = 0; j < TT; j++) acc += s[j] * vs[j][h*HD+e];
            g_oah[orow*128 + h*HD + e] = __float2half_rn(acc * inv);
        }
    }
}

// ------------------------- residual + layernorm -------------------------
__global__ void ln_kernel(const float* __restrict__ xa, const float* __restrict__ xb,
                          const float* __restrict__ gg, const float* __restrict__ bb,
                          float* __restrict__ outp, __half* __restrict__ oh) {
    int warp = threadIdx.x >> 5, lane = threadIdx.x & 31;
    size_t m = (size_t)blockIdx.x * 4 + warp;
    if (m >= MTOK) return;
    size_t ia = m * DD;
    float v[4]; float s = 0.f;
    #pragma unroll
    for (int i = 0; i < 4; i++) {
        int d = lane + 32*i;
        float val = (d < DD) ? (xa[ia+d] + xb[ia+d]) : 0.f;
        v[i] = val; s += val;
    }
    #pragma unroll
    for (int o = 16; o > 0; o >>= 1) s += __shfl_xor_sync(0xffffffffu, s, o);
    float mean = s * (1.f / DD);
    float vsum = 0.f;
    #pragma unroll
    for (int i = 0; i < 4; i++) {
        int d = lane + 32*i;
        if (d < DD) { float df = v[i]-mean; vsum += df*df; }
    }
    #pragma unroll
    for (int o = 16; o > 0; o >>= 1) vsum += __shfl_xor_sync(0xffffffffu, vsum, o);
    float inv = rsqrtf(vsum * (1.f / DD) + 1e-5f);
    #pragma unroll
    for (int i = 0; i < 4; i++) {
        int d = lane + 32*i;
        if (d < DD) {
            float o = (v[i]-mean)*inv*gg[d] + bb[d];
            if (outp) outp[ia + d] = o;
            if (oh) oh[m*128 + d] = __float2half_rn(o);
        }
    }
}

// ------------------------- launch -------------------------
extern "C" void kernel_launch(void* const* d_in, const int* in_sizes, int n_in,
                              void* d_out, int out_size) {
    const float* x       = (const float*)d_in[0];
    const float* adj     = (const float*)d_in[1];
    const float* gl_beta = (const float*)d_in[2];
    const float* gl_w1   = (const float*)d_in[3];
    const float* gl_w2   = (const float*)d_in[4];
    const float* gl_cw   = (const float*)d_in[5];
    const float* gl_cb   = (const float*)d_in[6];
    const float* cheb_w  = (const float*)d_in[7];
    const float* cheb_b  = (const float*)d_in[8];
    const float* out_w   = (const float*)d_in[9];
    const float* out_b   = (const float*)d_in[10];
    const float* ff_w1   = (const float*)d_in[11];
    const float* ff_b1   = (const float*)d_in[12];
    const float* ff_w2   = (const float*)d_in[13];
    const float* ff_b2   = (const float*)d_in[14];
    const float* ln1_g   = (const float*)d_in[15];
    const float* ln1_b   = (const float*)d_in[16];
    const float* ln2_g   = (const float*)d_in[17];
    const float* ln2_b   = (const float*)d_in[18];
    float* outp = (float*)d_out;

    const int SMEM128_2 = 2 * ((128*3) + 2*(128*3)) * 16;   // 36864
    const int SMEM128_1 = 2 * ((128*3) + 1*(128*3)) * 16;   // 24576
    const int SMEM64_2  = 36864;   // stage 2x12288; fp32 scatter staging needs 33792
    cudaFuncSetAttribute(hmma_fp16<128,2>, cudaFuncAttributeMaxDynamicSharedMemorySize, SMEM128_2);
    cudaFuncSetAttribute(hmma_fp16<128,1>, cudaFuncAttributeMaxDynamicSharedMemorySize, SMEM128_1);
    cudaFuncSetAttribute(hmma_fp16<64,2>,  cudaFuncAttributeMaxDynamicSharedMemorySize, SMEM64_2);

    __half *pLh, *pLl, *pxth, *pxtl, *pt1h;
    __half *pxch, *poah, *po1h, *phh;
    __half *pwqh, *pwql, *powh, *powl, *pw1h, *pw2h;
    float *pqkv, *poproj, *pout1f, *pffnf;
    cudaGetSymbolAddress((void**)&pLh, g_Lh);   cudaGetSymbolAddress((void**)&pLl, g_Ll);
    cudaGetSymbolAddress((void**)&pxth, g_xth); cudaGetSymbolAddress((void**)&pxtl, g_xtl);
    cudaGetSymbolAddress((void**)&pt1h, g_t1h);
    cudaGetSymbolAddress((void**)&pxch, g_xcath);
    cudaGetSymbolAddress((void**)&poah, g_oah);
    cudaGetSymbolAddress((void**)&po1h, g_o1h);
    cudaGetSymbolAddress((void**)&phh, g_hidh);
    cudaGetSymbolAddress((void**)&pwqh, g_wqh); cudaGetSymbolAddress((void**)&pwql, g_wql);
    cudaGetSymbolAddress((void**)&powh, g_owh); cudaGetSymbolAddress((void**)&powl, g_owl);
    cudaGetSymbolAddress((void**)&pw1h, g_w1h);
    cudaGetSymbolAddress((void**)&pw2h, g_w2h);
    cudaGetSymbolAddress((void**)&pqkv, g_qkv); cudaGetSymbolAddress((void**)&poproj, g_oproj);
    cudaGetSymbolAddress((void**)&pout1f, g_out1f); cudaGetSymbolAddress((void**)&pffnf, g_ffnf);

    // graph learning
    dim3 gG(NN, 3);
    gk1<<<gG, 256>>>(gl_w1, gl_w2, gl_beta, gl_cw, gl_cb, adj);
    gk2<<<gG, 256>>>();
    gk3<<<gG, 256>>>();
    gk4<<<gG, 256>>>();

    // layout + weight prep
    xsplitT<<<BT, 256>>>(x);
    pack_x<<<MTOK, 128>>>(x);
    wsplit<<<dim3(120,3), 256>>>(cheb_w, pwqh, pwql, 360, 120, XK, (long)360*120, (long)128*XK);
    wsplit<<<dim3(120,1), 256>>>(out_w, powh, powl, 120, 120, 128, 0, 0);
    wsplit<<<dim3(FF,1),  256>>>(ff_w1, pw1h, nullptr, 120, FF, 128, 0, 0);
    wsplit<<<dim3(120,1), 256>>>(ff_w2, pw2h, nullptr, FF, 120, FF, 0, 0);

    const long t1s = (long)MSP*NKP;
    const long xcs = (long)MTOK*XK;
    const long Ls  = (long)NROWP*NKP;

    // batched spatial t1 = L_br @ x (2-pass) -> t1_br (hi) + xcat_br[120..239]
    dim3 gsp(MSP/128, 3, 3);
    hmma_fp16<64,2><<<gsp, 256, SMEM64_2>>>(pxth, NKP, pLh, pLl, NKP, NKP,
                                            nullptr, pt1h, NKP, NN,
                                            nullptr, 0, nullptr, nullptr,
                                            pxch, 120,
                                            0, Ls, t1s, 0, xcs, 0);
    // batched spatial t2 = 2*(L_br @ t1_br) - x (2-pass) -> xcat_br[240..359]
    hmma_fp16<64,2><<<gsp, 256, SMEM64_2>>>(pt1h, NKP, pLh, pLl, NKP, NKP,
                                            nullptr, nullptr, NKP, NN,
                                            nullptr, FLAG_T2, pxth, pxtl,
                                            pxch, 240,
                                            t1s, Ls, 0, 0, xcs, 0);

    // batched QKV (2-pass): relu(xcat_br @ W_br + b_br)
    dim3 gqkv(MTOK/128, 1, 3);
    hmma_fp16<128,2><<<gqkv, 256, SMEM128_2>>>(pxch, XK, pwqh, pwql, XK, XK,
                                               pqkv, nullptr, DD, DD,
                                               cheb_b, FLAG_BIAS | FLAG_RELU,
                                               nullptr, nullptr, nullptr, 0,
                                               xcs, (long)128*XK, (long)MTOK*DD, DD, 0, 0);

    attn_kernel<<<BB*NN, 128>>>(pqkv, pqkv + (size_t)MTOK*DD, pqkv + (size_t)2*MTOK*DD);

    dim3 gch(MTOK/128, 1, 1);
    // output projection (2-pass)
    hmma_fp16<128,2><<<gch, 256, SMEM128_2>>>(poah, 128, powh, powl, 128, 128,
                                              poproj, nullptr, DD, DD,
                                              out_b, FLAG_BIAS, nullptr, nullptr,
                                              nullptr, 0, 0, 0, 0, 0, 0, 0);
    // LN1 (fp32 out + fp16 hi)
    ln_kernel<<<MTOK/4, 128>>>(x, poproj, ln1_g, ln1_b, pout1f, po1h);

    // FFN1 (1-pass) -> hidden fp16 hi; swapped grid for A reuse
    dim3 gf1(FF/128, MTOK/128, 1);
    hmma_fp16<128,1><<<gf1, 256, SMEM128_1>>>(po1h, 128, pw1h, nullptr, 128, 128,
                                              nullptr, phh, FF, FF,
                                              ff_b1, FLAG_BIAS | FLAG_RELU, nullptr, nullptr,
                                              nullptr, 0, 0, 0, 0, 0, 0, 1);
    // FFN2 (1-pass)
    hmma_fp16<128,1><<<gch, 256, SMEM128_1>>>(phh, FF, pw2h, nullptr, FF, FF,
                                              pffnf, nullptr, DD, DD,
                                              ff_b2, FLAG_BIAS, nullptr, nullptr,
                                              nullptr, 0, 0, 0, 0, 0, 0, 0);
    // LN2 -> output
    ln_kernel<<<MTOK/4, 128>>>(pout1f, pffnf, ln2_g, ln2_b, outp, nullptr);
}

// round 15
// speedup vs baseline: 1.9159x; 1.0807x over previous
#include <cuda_runtime.h>
#include <cuda_fp16.h>
#include <math.h>
#include <stdint.h>

#define NN 170
#define NKP 176            // padded node dim (K of spatial GEMM, multiple of 16)
#define NROWP 192          // padded L rows (3 x 64 col tiles)
#define TT 12
#define BB 32
#define DD 120
#define HH 8
#define HD 15
#define FF 2048
#define BT (BB*TT)          // 384
#define MTOK (BB*TT*NN)     // 65280 = 510*128
#define MSP (BT*DD)         // 46080 = 360*128
#define XK 384              // padded xcat K (360 -> 384, multiple of 32)

#define FLAG_BIAS  1
#define FLAG_RELU  2
#define FLAG_T2    4        // epilogue: v = 2*acc - (Xh+Xl)

// ------------------------- static device scratch (zero-initialized) --------
__device__ float g_A[3*NN*NN];
__device__ float g_rs0[3*NN];
__device__ float g_rs1[3*NN];

__device__ __align__(16) __half g_Lh[3*NROWP*NKP];
__device__ __align__(16) __half g_Ll[3*NROWP*NKP];
__device__ __align__(16) __half g_xth[(size_t)MSP*NKP];
__device__ __align__(16) __half g_xtl[(size_t)MSP*NKP];     // only for T2 fp32 reconstruction
__device__ __align__(16) __half g_t1h[(size_t)3*MSP*NKP];   // per-branch, hi only
__device__ __align__(16) __half g_xcath[(size_t)3*MTOK*XK]; // per-branch, hi only; cols 360..383 zero
__device__ __align__(16) __half g_oah[(size_t)MTOK*128];    // hi only
__device__ __align__(16) __half g_o1h[(size_t)MTOK*128];    // hi only
__device__ __align__(16) __half g_hidh[(size_t)MTOK*FF];    // hi only
// B-operand weights, rows padded to tile boundary
__device__ __align__(16) __half g_wqh[3*128*XK];            // hi only (1-pass QKV)
__device__ __align__(16) __half g_owh[128*128];
__device__ __align__(16) __half g_owl[128*128];
__device__ __align__(16) __half g_w1h[(size_t)FF*128];      // hi only
__device__ __align__(16) __half g_w2h[(size_t)128*FF];      // hi only
__device__ float g_qkv[(size_t)3*MTOK*DD];
__device__ float g_oproj[(size_t)MTOK*DD];
__device__ float g_out1f[(size_t)MTOK*DD];
__device__ float g_ffnf[(size_t)MTOK*DD];

// ------------------------- helpers -------------------------
__device__ __forceinline__ void hsplit(float v, __half &h, __half &l) {
    h = __float2half_rn(v);
    l = __float2half_rn(v - __half2float(h));
}
__device__ __forceinline__ uint32_t smem_u32(const void* p) {
    uint32_t a;
    asm("{ .reg .u64 t; cvta.to.shared.u64 t, %1; cvt.u32.u64 %0, t; }" : "=r"(a) : "l"(p));
    return a;
}
__device__ __forceinline__ void ldm4(uint32_t (&d)[4], uint32_t addr) {
    asm volatile("ldmatrix.sync.aligned.m8n8.x4.shared.b16 {%0,%1,%2,%3}, [%4];"
                 : "=r"(d[0]), "=r"(d[1]), "=r"(d[2]), "=r"(d[3]) : "r"(addr));
}
__device__ __forceinline__ void mma16816(float (&c)[4], const uint32_t (&a)[4],
                                         uint32_t b0, uint32_t b1) {
    asm volatile("mma.sync.aligned.m16n8k16.row.col.f32.f16.f16.f32 "
                 "{%0,%1,%2,%3}, {%4,%5,%6,%7}, {%8,%9}, {%0,%1,%2,%3};"
                 : "+f"(c[0]), "+f"(c[1]), "+f"(c[2]), "+f"(c[3])
                 : "r"(a[0]), "r"(a[1]), "r"(a[2]), "r"(a[3]), "r"(b0), "r"(b1));
}

// ------------------------- HMMA fp16 GEMM ------------------------------
// D[M,N] = sum_k A[m,k]*B[n,k]; A hi-only (M x K, lda).
// NPASS=2: Ah*Bh + Ah*Bl. NPASS=1: Ah*Bh only (Bl unused, may be null).
// BK in {16,32}: K-chunk per barrier. K%BK==0, M%128==0.
// Batched over blockIdx.z via strides (0 = shared).
template<int BN, int NPASS, int BK>
__global__ __launch_bounds__(256) void hmma_fp16(
        const __half* __restrict__ Ah, int lda,
        const __half* __restrict__ Bh, const __half* __restrict__ Bl, int ldb,
        int K,
        float* __restrict__ Cf, __half* __restrict__ Ch,
        int ldc, int Nout,
        const float* __restrict__ bias, int flags,
        const __half* __restrict__ Xh, const __half* __restrict__ Xl,
        __half* __restrict__ XCh, int xoff,
        long astride, long bstride, long cstride, int biasstride, long xcstride,
        int swapxy)
{
    constexpr int KR = BK / 16;             // ldmatrix k-steps per chunk
    constexpr int RU = 2*KR + 1;            // 16B units per smem row (padded pitch)
    constexpr int A16u = 128*RU;
    constexpr int B16u = BN*RU;
    constexpr int STAGE_BYTES = (A16u + NPASS*B16u) * 16;
    constexpr int NBA = KR;                 // A 16B transfers per thread
    constexpr int NBB = (BN*2*KR*NPASS)/256;
    constexpr int WN = BN / 2;
    constexpr int NP = WN / 16;
    constexpr int BU = BN*2*KR;             // B transfers per matrix

    extern __shared__ __align__(16) char smem[];
    const uint32_t sbase = smem_u32(smem);
    const int tid = threadIdx.x;
    const int lane = tid & 31;
    const int wid = tid >> 5;
    const int wm = wid & 3, wn = wid >> 2;
    const int row0 = (swapxy ? blockIdx.y : blockIdx.x) * 128;
    const int col0 = (swapxy ? blockIdx.x : blockIdx.y) * BN;
    {   // batch offsets
        const int bz = blockIdx.z;
        Ah += (size_t)bz * astride;
        Bh += (size_t)bz * bstride;
        if (NPASS == 2) Bl += (size_t)bz * bstride;
        if (Cf) Cf += (size_t)bz * cstride;
        if (Ch) Ch += (size_t)bz * cstride;
        if (bias) bias += bz * biasstride;
        if (XCh) XCh += (size_t)bz * xcstride;
    }

    float acc[2][2*NP][4];
    #pragma unroll
    for (int i = 0; i < 2; i++)
        #pragma unroll
        for (int j = 0; j < 2*NP; j++)
            #pragma unroll
            for (int e = 0; e < 4; e++) acc[i][j][e] = 0.f;

    const int arow = wm*32 + (lane & 15);
    const uint32_t aoff = (uint32_t)arow*(RU*16) + ((lane >> 4) ? 16u : 0u);
    const int brow = wn*WN + (lane & 7) + ((lane >> 4) & 1)*8;
    const uint32_t boff = (uint32_t)(A16u*16) + (uint32_t)brow*(RU*16)
                          + (((lane >> 3) & 1) ? 16u : 0u);

    uint4 ra[NBA], rb[NBB];

    auto gload = [&](int c) {
        const int k0 = c * BK;
        #pragma unroll
        for (int t = 0; t < NBA; t++) {
            int i = tid + t*256;
            int r = i / (2*KR), kc = i % (2*KR);
            ra[t] = *(const uint4*)(Ah + (size_t)(row0 + r)*lda + k0 + kc*8);
        }
        #pragma unroll
        for (int t = 0; t < NBB; t++) {
            int i = tid + t*256;
            int mat = i / BU, u = i % BU, r = u / (2*KR), kc = u % (2*KR);
            rb[t] = *(const uint4*)((mat ? Bl : Bh) + (size_t)(col0 + r)*ldb + k0 + kc*8);
        }
    };
    auto sstore = [&](int st) {
        char* sb = smem + st * STAGE_BYTES;
        #pragma unroll
        for (int t = 0; t < NBA; t++) {
            int i = tid + t*256;
            int r = i / (2*KR), kc = i % (2*KR);
            *(uint4*)(sb + (uint32_t)(r*RU + kc)*16) = ra[t];
        }
        #pragma unroll
        for (int t = 0; t < NBB; t++) {
            int i = tid + t*256;
            int mat = i / BU, u = i % BU, r = u / (2*KR), kc = u % (2*KR);
            *(uint4*)(sb + (uint32_t)(A16u + mat*B16u + r*RU + kc)*16) = rb[t];
        }
    };

    const int nch = K / BK;
    gload(0);
    sstore(0);

    for (int c = 0; c < nch; c++) {
        if (c + 1 < nch) gload(c + 1);   // prefetch into regs
        __syncthreads();                 // stage (c&1) stores visible; prev compute done

        const uint32_t sb = sbase + (uint32_t)(c & 1) * STAGE_BYTES;
        #pragma unroll
        for (int ks = 0; ks < KR; ks++) {
            uint32_t ahf[2][4];
            #pragma unroll
            for (int mi = 0; mi < 2; mi++)
                ldm4(ahf[mi], sb + aoff + ks*32 + (uint32_t)mi * (16*RU*16));
            uint32_t bhf[NP][4], blf[NP][4];
            #pragma unroll
            for (int np = 0; np < NP; np++) {
                uint32_t bd = sb + boff + ks*32 + (uint32_t)np * (16*RU*16);
                ldm4(bhf[np], bd);
                if (NPASS == 2) ldm4(blf[np], bd + B16u*16);
            }
            #pragma unroll
            for (int mi = 0; mi < 2; mi++)
                #pragma unroll
                for (int np = 0; np < NP; np++)
                    #pragma unroll
                    for (int hf = 0; hf < 2; hf++) {
                        int na = np*2 + hf;
                        mma16816(acc[mi][na], ahf[mi], bhf[np][2*hf], bhf[np][2*hf+1]);
                        if (NPASS == 2)
                            mma16816(acc[mi][na], ahf[mi], blf[np][2*hf], blf[np][2*hf+1]);
                    }
        }

        if (c + 1 < nch) sstore((c + 1) & 1);   // opposite stage; ordered by next sync
    }

    // ---- epilogue
    float* smemf = (float*)smem;   // BN x 128 fp32 staging (pitch 132), spatial only
    if (XCh) __syncthreads();      // all ldmatrix reads of final stage complete

    const int lr = lane >> 2, lc = (lane & 3) * 2;
    #pragma unroll
    for (int mi = 0; mi < 2; mi++) {
        #pragma unroll
        for (int na = 0; na < 2*NP; na++) {
            int gr0 = row0 + wm*32 + mi*16 + lr;
            int gc0l = wn*WN + na*8 + lc;
            #pragma unroll
            for (int e = 0; e < 4; e++) {
                int gr = gr0 + (e >> 1) * 8;
                int gcl = gc0l + (e & 1);
                int gc = col0 + gcl;
                if (gc >= Nout) continue;
                float v = acc[mi][na][e];
                size_t ci = (size_t)gr * ldc + gc;
                if (flags & FLAG_T2)
                    v = 2.f*v - (__half2float(Xh[ci]) + __half2float(Xl[ci]));
                if (flags & FLAG_BIAS) v += bias[gc];
                if (flags & FLAG_RELU) v = fmaxf(v, 0.f);
                if (Cf) Cf[ci] = v;
                if (Ch) Ch[ci] = __float2half_rn(v);
                if (XCh) smemf[gcl*132 + (gr - row0)] = v;
            }
        }
    }

    if (XCh) {
        __syncthreads();
        for (int i = tid; i < BN*128; i += 256) {
            int gcl = i >> 7, grl = i & 127;
            int n = col0 + gcl;
            if (n >= Nout) continue;
            float v = smemf[gcl*132 + grl];
            int gr = row0 + grl;
            int bt = gr / DD, d = gr - bt*DD;
            size_t idx = ((size_t)bt*NN + n)*XK + xoff + d;
            XCh[idx] = __float2half_rn(v);
        }
    }
}

// ------------------------- graph learning -------------------------
__global__ void gk1(const float* __restrict__ w1, const float* __restrict__ w2,
                    const float* __restrict__ beta, const float* __restrict__ cw,
                    const float* __restrict__ cb, const float* __restrict__ adj) {
    int r = blockIdx.x, br = blockIdx.y;
    __shared__ float w1r[DD], w2r[DD];
    __shared__ float red[256];
    const float* W1 = w1 + (size_t)br*NN*DD;
    const float* W2 = w2 + (size_t)br*NN*DD;
    for (int i = threadIdx.x; i < DD; i += blockDim.x) { w1r[i] = W1[r*DD+i]; w2r[i] = W2[r*DD+i]; }
    __syncthreads();
    float cw0 = cw[br*2+0], cw1 = cw[br*2+1], cbv = cb[br];
    float mysum = 0.f;
    for (int c = threadIdx.x; c < NN; c += blockDim.x) {
        const float* w1c = W1 + c*DD;
        const float* w2c = W2 + c*DD;
        float d1 = 0.f, d2 = 0.f;
        for (int e = 0; e < DD; e++) { d1 += w1r[e]*w2c[e]; d2 += w2r[e]*w1c[e]; }
        float nw = d1 - d2;
        if (r == c) nw += beta[br*NN + r];
        nw = fmaxf(nw, 0.f);
        float ad = adj[r*NN + c];
        float gate = 1.f / (1.f + expf(-(cw0*nw + cw1*ad + cbv)));
        float a = gate*nw + (1.f - gate)*ad;
        g_A[(size_t)br*NN*NN + (size_t)r*NN + c] = a;
        mysum += a;
    }
    red[threadIdx.x] = mysum; __syncthreads();
    for (int s = 128; s > 0; s >>= 1) { if (threadIdx.x < s) red[threadIdx.x] += red[threadIdx.x+s]; __syncthreads(); }
    if (threadIdx.x == 0) g_rs0[br*NN + r] = red[0];
}
__global__ void gk2() {
    int r = blockIdx.x, br = blockIdx.y;
    __shared__ float red[256];
    float dr = rsqrtf(g_rs0[br*NN + r]);
    const float eps = 0.5f / (float)NN;
    float mysum = 0.f;
    for (int c = threadIdx.x; c < NN; c += blockDim.x) {
        float dc = rsqrtf(g_rs0[br*NN + c]);
        size_t idx = (size_t)br*NN*NN + (size_t)r*NN + c;
        float a = fmaxf(dr * g_A[idx] * dc - eps, 0.f);
        g_A[idx] = a; mysum += a;
    }
    red[threadIdx.x] = mysum; __syncthreads();
    for (int s = 128; s > 0; s >>= 1) { if (threadIdx.x < s) red[threadIdx.x] += red[threadIdx.x+s]; __syncthreads(); }
    if (threadIdx.x == 0) g_rs1[br*NN + r] = red[0];
}
__global__ void gk3() {
    int r = blockIdx.x, br = blockIdx.y;
    __shared__ float red[256];
    float dr = rsqrtf(g_rs1[br*NN + r]);
    float mysum = 0.f;
    for (int c = threadIdx.x; c < NN; c += blockDim.x) {
        float dc = rsqrtf(g_rs1[br*NN + c]);
        size_t idx = (size_t)br*NN*NN + (size_t)r*NN + c;
        float g = dr * g_A[idx] * dc;
        g_A[idx] = g; mysum += g;
    }
    red[threadIdx.x] = mysum; __syncthreads();
    for (int s = 128; s > 0; s >>= 1) { if (threadIdx.x < s) red[threadIdx.x] += red[threadIdx.x+s]; __syncthreads(); }
    if (threadIdx.x == 0) g_rs0[br*NN + r] = red[0];
}
__global__ void gk4() {
    int r = blockIdx.x, br = blockIdx.y;
    float er = rsqrtf(g_rs0[br*NN + r]);
    for (int c = threadIdx.x; c < NKP; c += blockDim.x) {
        float L = 0.f;
        if (c < NN) {
            float ec = rsqrtf(g_rs0[br*NN + c]);
            L = ((r == c) ? 1.f : 0.f) - er * g_A[(size_t)br*NN*NN + (size_t)r*NN + c] * ec;
        }
        __half h, l; hsplit(L, h, l);
        size_t idx = (size_t)br*NROWP*NKP + (size_t)r*NKP + c;
        g_Lh[idx] = h; g_Ll[idx] = l;
    }
}

// ------------------------- layout / split kernels -------------------------
__global__ void xsplitT(const float* __restrict__ x) {
    __shared__ float s[64*121];
    int bt = blockIdx.x;
    for (int n0 = 0; n0 < NN; n0 += 64) {
        int nrows = (NN - n0 < 64) ? (NN - n0) : 64;
        for (int i = threadIdx.x; i < nrows*DD; i += 256) {
            int nn = i / DD, d = i - nn*DD;
            s[nn*121 + d] = x[((size_t)bt*NN + n0 + nn)*DD + d];
        }
        __syncthreads();
        for (int i = threadIdx.x; i < DD*64; i += 256) {
            int d = i >> 6, nn = i & 63;
            int n = n0 + nn;
            if (nn < nrows) {
                __half h, l; hsplit(s[nn*121 + d], h, l);
                size_t idx = ((size_t)bt*DD + d)*NKP + n;
                g_xth[idx] = h; g_xtl[idx] = l;
            }
        }
        __syncthreads();
    }
}
// x -> cols [0,120) of all three branch xcat buffers (hi only)
__global__ void pack_x(const float* __restrict__ x) {
    size_t r = blockIdx.x;
    int d = threadIdx.x;
    if (d < DD) {
        __half h = __float2half_rn(x[r*DD + d]);
        #pragma unroll
        for (int br = 0; br < 3; br++)
            g_xcath[(size_t)br*MTOK*XK + r*XK + d] = h;
    }
}
// transpose+split; dl==nullptr -> hi only
__global__ void wsplit(const float* __restrict__ src, __half* __restrict__ dh,
                       __half* __restrict__ dl, int K, int N, int ldk,
                       long src_bstride, long dst_bstride) {
    int n = blockIdx.x;
    int br = blockIdx.y;
    src += (size_t)br * src_bstride;
    dh  += (size_t)br * dst_bstride;
    if (dl) dl += (size_t)br * dst_bstride;
    for (int k = threadIdx.x; k < K; k += blockDim.x) {
        __half h, l; hsplit(src[(size_t)k*N + n], h, l);
        dh[(size_t)n*ldk + k] = h;
        if (dl) dl[(size_t)n*ldk + k] = l;
    }
}

// ------------------------- attention -------------------------
__global__ void attn_kernel(const float* __restrict__ q, const float* __restrict__ k,
                            const float* __restrict__ v) {
    int bn = blockIdx.x;
    int b = bn / NN, n = bn % NN;
    __shared__ float qs[TT][DD], ks[TT][DD], vs[TT][DD];
    for (int i = threadIdx.x; i < TT*DD; i += blockDim.x) {
        int t = i / DD, d = i % DD;
        size_t gi = (((size_t)(b*TT + t))*NN + n)*DD + d;
        qs[t][d] = q[gi]; ks[t][d] = k[gi]; vs[t][d] = v[gi];
    }
    __syncthreads();
    int tid = threadIdx.x;
    if (tid < HH*TT) {
        int h = tid / TT, qi = tid % TT;
        const float scale = rsqrtf((float)HD);
        float s[TT]; float mx = -1e30f;
        #pragma unroll
        for (int j = 0; j < TT; j++) {
            float acc = 0.f;
            #pragma unroll
            for (int e = 0; e < HD; e++) acc += qs[qi][h*HD+e] * ks[j][h*HD+e];
            acc *= scale; s[j] = acc; mx = fmaxf(mx, acc);
        }
        float sum = 0.f;
        #pragma unroll
        for (int j = 0; j < TT; j++) { s[j] = expf(s[j]-mx); sum += s[j]; }
        float inv = 1.f / sum;
        size_t orow = ((size_t)(b*TT + qi))*NN + n;
        #pragma unroll
        for (int e = 0; e < HD; e++) {
            float acc = 0.f;
            #pragma unroll
            for (int j = 0; j < TT; j++) acc += s[j] * vs[j][h*HD+e];
            g_oah[orow*128 + h*HD + e] = __float2half_rn(acc * inv);
        }
    }
}

// ------------------------- residual + layernorm -------------------------
__global__ void ln_kernel(const float* __restrict__ xa, const float* __restrict__ xb,
                          const float* __restrict__ gg, const float* __restrict__ bb,
                          float* __restrict__ outp, __half* __restrict__ oh) {
    int warp = threadIdx.x >> 5, lane = threadIdx.x & 31;
    size_t m = (size_t)blockIdx.x * 4 + warp;
    if (m >= MTOK) return;
    size_t ia = m * DD;
    float v[4]; float s = 0.f;
    #pragma unroll
    for (int i = 0; i < 4; i++) {
        int d = lane + 32*i;
        float val = (d < DD) ? (xa[ia+d] + xb[ia+d]) : 0.f;
        v[i] = val; s += val;
    }
    #pragma unroll
    for (int o = 16; o > 0; o >>= 1) s += __shfl_xor_sync(0xffffffffu, s, o);
    float mean = s * (1.f / DD);
    float vsum = 0.f;
    #pragma unroll
    for (int i = 0; i < 4; i++) {
        int d = lane + 32*i;
        if (d < DD) { float df = v[i]-mean; vsum += df*df; }
    }
    #pragma unroll
    for (int o = 16; o > 0; o >>= 1) vsum += __shfl_xor_sync(0xffffffffu, vsum, o);
    float inv = rsqrtf(vsum * (1.f / DD) + 1e-5f);
    #pragma unroll
    for (int i = 0; i < 4; i++) {
        int d = lane + 32*i;
        if (d < DD) {
            float o = (v[i]-mean)*inv*gg[d] + bb[d];
            if (outp) outp[ia + d] = o;
            if (oh) oh[m*128 + d] = __float2half_rn(o);
        }
    }
}

// ------------------------- launch -------------------------
extern "C" void kernel_launch(void* const* d_in, const int* in_sizes, int n_in,
                              void* d_out, int out_size) {
    const float* x       = (const float*)d_in[0];
    const float* adj     = (const float*)d_in[1];
    const float* gl_beta = (const float*)d_in[2];
    const float* gl_w1   = (const float*)d_in[3];
    const float* gl_w2   = (const float*)d_in[4];
    const float* gl_cw   = (const float*)d_in[5];
    const float* gl_cb   = (const float*)d_in[6];
    const float* cheb_w  = (const float*)d_in[7];
    const float* cheb_b  = (const float*)d_in[8];
    const float* out_w   = (const float*)d_in[9];
    const float* out_b   = (const float*)d_in[10];
    const float* ff_w1   = (const float*)d_in[11];
    const float* ff_b1   = (const float*)d_in[12];
    const float* ff_w2   = (const float*)d_in[13];
    const float* ff_b2   = (const float*)d_in[14];
    const float* ln1_g   = (const float*)d_in[15];
    const float* ln1_b   = (const float*)d_in[16];
    const float* ln2_g   = (const float*)d_in[17];
    const float* ln2_b   = (const float*)d_in[18];
    float* outp = (float*)d_out;

    const int SMEM128_2_16 = 2 * ((128*3) + 2*(128*3)) * 16;  // 36864 (oproj)
    const int SMEM128_1_32 = 2 * ((128*5) + 1*(128*5)) * 16;  // 40960 (QKV/FFN)
    const int SMEM64_2_16  = 36864;   // stage 2x12288; fp32 scatter staging needs 33792
    cudaFuncSetAttribute(hmma_fp16<128,2,16>, cudaFuncAttributeMaxDynamicSharedMemorySize, SMEM128_2_16);
    cudaFuncSetAttribute(hmma_fp16<128,1,32>, cudaFuncAttributeMaxDynamicSharedMemorySize, SMEM128_1_32);
    cudaFuncSetAttribute(hmma_fp16<64,2,16>,  cudaFuncAttributeMaxDynamicSharedMemorySize, SMEM64_2_16);

    __half *pLh, *pLl, *pxth, *pxtl, *pt1h;
    __half *pxch, *poah, *po1h, *phh;
    __half *pwqh, *powh, *powl, *pw1h, *pw2h;
    float *pqkv, *poproj, *pout1f, *pffnf;
    cudaGetSymbolAddress((void**)&pLh, g_Lh);   cudaGetSymbolAddress((void**)&pLl, g_Ll);
    cudaGetSymbolAddress((void**)&pxth, g_xth); cudaGetSymbolAddress((void**)&pxtl, g_xtl);
    cudaGetSymbolAddress((void**)&pt1h, g_t1h);
    cudaGetSymbolAddress((void**)&pxch, g_xcath);
    cudaGetSymbolAddress((void**)&poah, g_oah);
    cudaGetSymbolAddress((void**)&po1h, g_o1h);
    cudaGetSymbolAddress((void**)&phh, g_hidh);
    cudaGetSymbolAddress((void**)&pwqh, g_wqh);
    cudaGetSymbolAddress((void**)&powh, g_owh); cudaGetSymbolAddress((void**)&powl, g_owl);
    cudaGetSymbolAddress((void**)&pw1h, g_w1h);
    cudaGetSymbolAddress((void**)&pw2h, g_w2h);
    cudaGetSymbolAddress((void**)&pqkv, g_qkv); cudaGetSymbolAddress((void**)&poproj, g_oproj);
    cudaGetSymbolAddress((void**)&pout1f, g_out1f); cudaGetSymbolAddress((void**)&pffnf, g_ffnf);

    // graph learning
    dim3 gG(NN, 3);
    gk1<<<gG, 256>>>(gl_w1, gl_w2, gl_beta, gl_cw, gl_cb, adj);
    gk2<<<gG, 256>>>();
    gk3<<<gG, 256>>>();
    gk4<<<gG, 256>>>();

    // layout + weight prep
    xsplitT<<<BT, 256>>>(x);
    pack_x<<<MTOK, 128>>>(x);
    wsplit<<<dim3(120,3), 256>>>(cheb_w, pwqh, nullptr, 360, 120, XK, (long)360*120, (long)128*XK);
    wsplit<<<dim3(120,1), 256>>>(out_w, powh, powl, 120, 120, 128, 0, 0);
    wsplit<<<dim3(FF,1),  256>>>(ff_w1, pw1h, nullptr, 120, FF, 128, 0, 0);
    wsplit<<<dim3(120,1), 256>>>(ff_w2, pw2h, nullptr, FF, 120, FF, 0, 0);

    const long t1s = (long)MSP*NKP;
    const long xcs = (long)MTOK*XK;
    const long Ls  = (long)NROWP*NKP;

    // batched spatial t1 = L_br @ x (2-pass) -> t1_br (hi) + xcat_br[120..239]
    dim3 gsp(MSP/128, 3, 3);
    hmma_fp16<64,2,16><<<gsp, 256, SMEM64_2_16>>>(pxth, NKP, pLh, pLl, NKP, NKP,
                                                  nullptr, pt1h, NKP, NN,
                                                  nullptr, 0, nullptr, nullptr,
                                                  pxch, 120,
                                                  0, Ls, t1s, 0, xcs, 0);
    // batched spatial t2 = 2*(L_br @ t1_br) - x (2-pass) -> xcat_br[240..359]
    hmma_fp16<64,2,16><<<gsp, 256, SMEM64_2_16>>>(pt1h, NKP, pLh, pLl, NKP, NKP,
                                                  nullptr, nullptr, NKP, NN,
                                                  nullptr, FLAG_T2, pxth, pxtl,
                                                  pxch, 240,
                                                  t1s, Ls, 0, 0, xcs, 0);

    // batched QKV (1-pass, BK=32): relu(xcat_br @ Wh_br + b_br), K=384
    dim3 gqkv(MTOK/128, 1, 3);
    hmma_fp16<128,1,32><<<gqkv, 256, SMEM128_1_32>>>(pxch, XK, pwqh, nullptr, XK, XK,
                                                     pqkv, nullptr, DD, DD,
                                                     cheb_b, FLAG_BIAS | FLAG_RELU,
                                                     nullptr, nullptr, nullptr, 0,
                                                     xcs, (long)128*XK, (long)MTOK*DD, DD, 0, 0);

    attn_kernel<<<BB*NN, 128>>>(pqkv, pqkv + (size_t)MTOK*DD, pqkv + (size_t)2*MTOK*DD);

    dim3 gch(MTOK/128, 1, 1);
    // output projection (2-pass, BK=16)
    hmma_fp16<128,2,16><<<gch, 256, SMEM128_2_16>>>(poah, 128, powh, powl, 128, 128,
                                                    poproj, nullptr, DD, DD,
                                                    out_b, FLAG_BIAS, nullptr, nullptr,
                                                    nullptr, 0, 0, 0, 0, 0, 0, 0);
    // LN1 (fp32 out + fp16 hi)
    ln_kernel<<<MTOK/4, 128>>>(x, poproj, ln1_g, ln1_b, pout1f, po1h);

    // FFN1 (1-pass, BK=32) -> hidden fp16 hi; swapped grid for A reuse
    dim3 gf1(FF/128, MTOK/128, 1);
    hmma_fp16<128,1,32><<<gf1, 256, SMEM128_1_32>>>(po1h, 128, pw1h, nullptr, 128, 128,
                                                    nullptr, phh, FF, FF,
                                                    ff_b1, FLAG_BIAS | FLAG_RELU, nullptr, nullptr,
                                                    nullptr, 0, 0, 0, 0, 0, 0, 1);
    // FFN2 (1-pass, BK=32)
    hmma_fp16<128,1,32><<<gch, 256, SMEM128_1_32>>>(phh, FF, pw2h, nullptr, FF, FF,
                                                    pffnf, nullptr, DD, DD,
                                                    ff_b2, FLAG_BIAS, nullptr, nullptr,
                                                    nullptr, 0, 0, 0, 0, 0, 0, 0);
    // LN2 -> output
    ln_kernel<<<MTOK/4, 128>>>(pout1f, pffnf, ln2_g, ln2_b, outp, nullptr);
}

// round 16
// speedup vs baseline: 1.9597x; 1.0229x over previous
#include <cuda_runtime.h>
#include <cuda_fp16.h>
#include <math.h>
#include <stdint.h>

#define NN 170
#define NKP 192            // padded node dim (K of spatial GEMM, multiple of 32)
#define TT 12
#define BB 32
#define DD 120
#define HH 8
#define HD 15
#define FF 2048
#define BT (BB*TT)          // 384
#define MTOK (BB*TT*NN)     // 65280 = 510*128
#define MSP (BT*DD)         // 46080 = 360*128
#define XK 384              // padded xcat K (360 -> 384, multiple of 32)

#define FLAG_BIAS  1
#define FLAG_RELU  2
#define FLAG_T2    4        // epilogue: v = 2*acc - (Xh+Xl)

// ------------------------- static device scratch (zero-initialized) --------
__device__ float g_A[3*NN*NN];
__device__ float g_rs0[3*NN];
__device__ float g_rs1[3*NN];

__device__ __align__(16) __half g_Lh[3*NKP*NKP];            // rows/cols padded, hi only
__device__ __align__(16) __half g_xth[(size_t)MSP*NKP];
__device__ __align__(16) __half g_xtl[(size_t)MSP*NKP];     // only for T2 fp32 reconstruction
__device__ __align__(16) __half g_t1h[(size_t)3*MSP*NKP];   // per-branch, hi only
__device__ __align__(16) __half g_xcath[(size_t)3*MTOK*XK]; // per-branch, hi only; cols 360..383 zero
__device__ __align__(16) __half g_oah[(size_t)MTOK*128];    // hi only
__device__ __align__(16) __half g_o1h[(size_t)MTOK*128];    // hi only
__device__ __align__(16) __half g_hidh[(size_t)MTOK*FF];    // hi only
// B-operand weights, rows padded to tile boundary
__device__ __align__(16) __half g_wqh[3*128*XK];            // hi only
__device__ __align__(16) __half g_owh[128*128];
__device__ __align__(16) __half g_owl[128*128];
__device__ __align__(16) __half g_w1h[(size_t)FF*128];      // hi only
__device__ __align__(16) __half g_w2h[(size_t)128*FF];      // hi only
__device__ float g_qkv[(size_t)3*MTOK*DD];
__device__ float g_oproj[(size_t)MTOK*DD];
__device__ float g_out1f[(size_t)MTOK*DD];
__device__ float g_ffnf[(size_t)MTOK*DD];

// ------------------------- helpers -------------------------
__device__ __forceinline__ void hsplit(float v, __half &h, __half &l) {
    h = __float2half_rn(v);
    l = __float2half_rn(v - __half2float(h));
}
__device__ __forceinline__ uint32_t smem_u32(const void* p) {
    uint32_t a;
    asm("{ .reg .u64 t; cvta.to.shared.u64 t, %1; cvt.u32.u64 %0, t; }" : "=r"(a) : "l"(p));
    return a;
}
__device__ __forceinline__ void ldm4(uint32_t (&d)[4], uint32_t addr) {
    asm volatile("ldmatrix.sync.aligned.m8n8.x4.shared.b16 {%0,%1,%2,%3}, [%4];"
                 : "=r"(d[0]), "=r"(d[1]), "=r"(d[2]), "=r"(d[3]) : "r"(addr));
}
__device__ __forceinline__ void mma16816(float (&c)[4], const uint32_t (&a)[4],
                                         uint32_t b0, uint32_t b1) {
    asm volatile("mma.sync.aligned.m16n8k16.row.col.f32.f16.f16.f32 "
                 "{%0,%1,%2,%3}, {%4,%5,%6,%7}, {%8,%9}, {%0,%1,%2,%3};"
                 : "+f"(c[0]), "+f"(c[1]), "+f"(c[2]), "+f"(c[3])
                 : "r"(a[0]), "r"(a[1]), "r"(a[2]), "r"(a[3]), "r"(b0), "r"(b1));
}

// ------------------------- HMMA fp16 GEMM ------------------------------
// D[M,N] = sum_k A[m,k]*B[n,k]; A hi-only (M x K, lda).
// NPASS=2: Ah*Bh + Ah*Bl. NPASS=1: Ah*Bh only (Bl unused, may be null).
// BK in {16,32}: K-chunk per barrier. K%BK==0, M%128==0.
// Batched over blockIdx.z via strides (0 = shared).
template<int BN, int NPASS, int BK>
__global__ __launch_bounds__(256) void hmma_fp16(
        const __half* __restrict__ Ah, int lda,
        const __half* __restrict__ Bh, const __half* __restrict__ Bl, int ldb,
        int K,
        float* __restrict__ Cf, __half* __restrict__ Ch,
        int ldc, int Nout,
        const float* __restrict__ bias, int flags,
        const __half* __restrict__ Xh, const __half* __restrict__ Xl,
        __half* __restrict__ XCh, int xoff,
        long astride, long bstride, long cstride, int biasstride, long xcstride,
        int swapxy)
{
    constexpr int KR = BK / 16;             // ldmatrix k-steps per chunk
    constexpr int RU = 2*KR + 1;            // 16B units per smem row (padded pitch)
    constexpr int A16u = 128*RU;
    constexpr int B16u = BN*RU;
    constexpr int STAGE_BYTES = (A16u + NPASS*B16u) * 16;
    constexpr int NBA = KR;                 // A 16B transfers per thread
    constexpr int NBB = (BN*2*KR*NPASS)/256;
    constexpr int WN = BN / 2;
    constexpr int NP = WN / 16;
    constexpr int BU = BN*2*KR;             // B transfers per matrix

    extern __shared__ __align__(16) char smem[];
    const uint32_t sbase = smem_u32(smem);
    const int tid = threadIdx.x;
    const int lane = tid & 31;
    const int wid = tid >> 5;
    const int wm = wid & 3, wn = wid >> 2;
    const int row0 = (swapxy ? blockIdx.y : blockIdx.x) * 128;
    const int col0 = (swapxy ? blockIdx.x : blockIdx.y) * BN;
    {   // batch offsets
        const int bz = blockIdx.z;
        Ah += (size_t)bz * astride;
        Bh += (size_t)bz * bstride;
        if (NPASS == 2) Bl += (size_t)bz * bstride;
        if (Cf) Cf += (size_t)bz * cstride;
        if (Ch) Ch += (size_t)bz * cstride;
        if (bias) bias += bz * biasstride;
        if (XCh) XCh += (size_t)bz * xcstride;
    }

    float acc[2][2*NP][4];
    #pragma unroll
    for (int i = 0; i < 2; i++)
        #pragma unroll
        for (int j = 0; j < 2*NP; j++)
            #pragma unroll
            for (int e = 0; e < 4; e++) acc[i][j][e] = 0.f;

    const int arow = wm*32 + (lane & 15);
    const uint32_t aoff = (uint32_t)arow*(RU*16) + ((lane >> 4) ? 16u : 0u);
    const int brow = wn*WN + (lane & 7) + ((lane >> 4) & 1)*8;
    const uint32_t boff = (uint32_t)(A16u*16) + (uint32_t)brow*(RU*16)
                          + (((lane >> 3) & 1) ? 16u : 0u);

    uint4 ra[NBA], rb[NBB];

    auto gload = [&](int c) {
        const int k0 = c * BK;
        #pragma unroll
        for (int t = 0; t < NBA; t++) {
            int i = tid + t*256;
            int r = i / (2*KR), kc = i % (2*KR);
            ra[t] = *(const uint4*)(Ah + (size_t)(row0 + r)*lda + k0 + kc*8);
        }
        #pragma unroll
        for (int t = 0; t < NBB; t++) {
            int i = tid + t*256;
            int mat = i / BU, u = i % BU, r = u / (2*KR), kc = u % (2*KR);
            rb[t] = *(const uint4*)((mat ? Bl : Bh) + (size_t)(col0 + r)*ldb + k0 + kc*8);
        }
    };
    auto sstore = [&](int st) {
        char* sb = smem + st * STAGE_BYTES;
        #pragma unroll
        for (int t = 0; t < NBA; t++) {
            int i = tid + t*256;
            int r = i / (2*KR), kc = i % (2*KR);
            *(uint4*)(sb + (uint32_t)(r*RU + kc)*16) = ra[t];
        }
        #pragma unroll
        for (int t = 0; t < NBB; t++) {
            int i = tid + t*256;
            int mat = i / BU, u = i % BU, r = u / (2*KR), kc = u % (2*KR);
            *(uint4*)(sb + (uint32_t)(A16u + mat*B16u + r*RU + kc)*16) = rb[t];
        }
    };

    const int nch = K / BK;
    gload(0);
    sstore(0);

    for (int c = 0; c < nch; c++) {
        if (c + 1 < nch) gload(c + 1);   // prefetch into regs
        __syncthreads();                 // stage (c&1) stores visible; prev compute done

        const uint32_t sb = sbase + (uint32_t)(c & 1) * STAGE_BYTES;
        #pragma unroll
        for (int ks = 0; ks < KR; ks++) {
            uint32_t ahf[2][4];
            #pragma unroll
            for (int mi = 0; mi < 2; mi++)
                ldm4(ahf[mi], sb + aoff + ks*32 + (uint32_t)mi * (16*RU*16));
            uint32_t bhf[NP][4], blf[NP][4];
            #pragma unroll
            for (int np = 0; np < NP; np++) {
                uint32_t bd = sb + boff + ks*32 + (uint32_t)np * (16*RU*16);
                ldm4(bhf[np], bd);
                if (NPASS == 2) ldm4(blf[np], bd + B16u*16);
            }
            #pragma unroll
            for (int mi = 0; mi < 2; mi++)
                #pragma unroll
                for (int np = 0; np < NP; np++)
                    #pragma unroll
                    for (int hf = 0; hf < 2; hf++) {
                        int na = np*2 + hf;
                        mma16816(acc[mi][na], ahf[mi], bhf[np][2*hf], bhf[np][2*hf+1]);
                        if (NPASS == 2)
                            mma16816(acc[mi][na], ahf[mi], blf[np][2*hf], blf[np][2*hf+1]);
                    }
        }

        if (c + 1 < nch) sstore((c + 1) & 1);   // opposite stage; ordered by next sync
    }

    // ---- epilogue
    float* smemf = (float*)smem;   // BN x 128 fp32 staging (pitch 132), spatial only
    if (XCh) __syncthreads();      // all ldmatrix reads of final stage complete

    const int lr = lane >> 2, lc = (lane & 3) * 2;
    #pragma unroll
    for (int mi = 0; mi < 2; mi++) {
        #pragma unroll
        for (int na = 0; na < 2*NP; na++) {
            int gr0 = row0 + wm*32 + mi*16 + lr;
            int gc0l = wn*WN + na*8 + lc;
            #pragma unroll
            for (int e = 0; e < 4; e++) {
                int gr = gr0 + (e >> 1) * 8;
                int gcl = gc0l + (e & 1);
                int gc = col0 + gcl;
                if (gc >= Nout) continue;
                float v = acc[mi][na][e];
                size_t ci = (size_t)gr * ldc + gc;
                if (flags & FLAG_T2)
                    v = 2.f*v - (__half2float(Xh[ci]) + __half2float(Xl[ci]));
                if (flags & FLAG_BIAS) v += bias[gc];
                if (flags & FLAG_RELU) v = fmaxf(v, 0.f);
                if (Cf) Cf[ci] = v;
                if (Ch) Ch[ci] = __float2half_rn(v);
                if (XCh) smemf[gcl*132 + (gr - row0)] = v;
            }
        }
    }

    if (XCh) {
        __syncthreads();
        for (int i = tid; i < BN*128; i += 256) {
            int gcl = i >> 7, grl = i & 127;
            int n = col0 + gcl;
            if (n >= Nout) continue;
            float v = smemf[gcl*132 + grl];
            int gr = row0 + grl;
            int bt = gr / DD, d = gr - bt*DD;
            size_t idx = ((size_t)bt*NN + n)*XK + xoff + d;
            XCh[idx] = __float2half_rn(v);
        }
    }
}

// ------------------------- graph learning -------------------------
__global__ void gk1(const float* __restrict__ w1, const float* __restrict__ w2,
                    const float* __restrict__ beta, const float* __restrict__ cw,
                    const float* __restrict__ cb, const float* __restrict__ adj) {
    int r = blockIdx.x, br = blockIdx.y;
    __shared__ float w1r[DD], w2r[DD];
    __shared__ float red[256];
    const float* W1 = w1 + (size_t)br*NN*DD;
    const float* W2 = w2 + (size_t)br*NN*DD;
    for (int i = threadIdx.x; i < DD; i += blockDim.x) { w1r[i] = W1[r*DD+i]; w2r[i] = W2[r*DD+i]; }
    __syncthreads();
    float cw0 = cw[br*2+0], cw1 = cw[br*2+1], cbv = cb[br];
    float mysum = 0.f;
    for (int c = threadIdx.x; c < NN; c += blockDim.x) {
        const float* w1c = W1 + c*DD;
        const float* w2c = W2 + c*DD;
        float d1 = 0.f, d2 = 0.f;
        for (int e = 0; e < DD; e++) { d1 += w1r[e]*w2c[e]; d2 += w2r[e]*w1c[e]; }
        float nw = d1 - d2;
        if (r == c) nw += beta[br*NN + r];
        nw = fmaxf(nw, 0.f);
        float ad = adj[r*NN + c];
        float gate = 1.f / (1.f + expf(-(cw0*nw + cw1*ad + cbv)));
        float a = gate*nw + (1.f - gate)*ad;
        g_A[(size_t)br*NN*NN + (size_t)r*NN + c] = a;
        mysum += a;
    }
    red[threadIdx.x] = mysum; __syncthreads();
    for (int s = 128; s > 0; s >>= 1) { if (threadIdx.x < s) red[threadIdx.x] += red[threadIdx.x+s]; __syncthreads(); }
    if (threadIdx.x == 0) g_rs0[br*NN + r] = red[0];
}
__global__ void gk2() {
    int r = blockIdx.x, br = blockIdx.y;
    __shared__ float red[256];
    float dr = rsqrtf(g_rs0[br*NN + r]);
    const float eps = 0.5f / (float)NN;
    float mysum = 0.f;
    for (int c = threadIdx.x; c < NN; c += blockDim.x) {
        float dc = rsqrtf(g_rs0[br*NN + c]);
        size_t idx = (size_t)br*NN*NN + (size_t)r*NN + c;
        float a = fmaxf(dr * g_A[idx] * dc - eps, 0.f);
        g_A[idx] = a; mysum += a;
    }
    red[threadIdx.x] = mysum; __syncthreads();
    for (int s = 128; s > 0; s >>= 1) { if (threadIdx.x < s) red[threadIdx.x] += red[threadIdx.x+s]; __syncthreads(); }
    if (threadIdx.x == 0) g_rs1[br*NN + r] = red[0];
}
__global__ void gk3() {
    int r = blockIdx.x, br = blockIdx.y;
    __shared__ float red[256];
    float dr = rsqrtf(g_rs1[br*NN + r]);
    float mysum = 0.f;
    for (int c = threadIdx.x; c < NN; c += blockDim.x) {
        float dc = rsqrtf(g_rs1[br*NN + c]);
        size_t idx = (size_t)br*NN*NN + (size_t)r*NN + c;
        float g = dr * g_A[idx] * dc;
        g_A[idx] = g; mysum += g;
    }
    red[threadIdx.x] = mysum; __syncthreads();
    for (int s = 128; s > 0; s >>= 1) { if (threadIdx.x < s) red[threadIdx.x] += red[threadIdx.x+s]; __syncthreads(); }
    if (threadIdx.x == 0) g_rs0[br*NN + r] = red[0];
}
__global__ void gk4() {
    int r = blockIdx.x, br = blockIdx.y;
    float er = rsqrtf(g_rs0[br*NN + r]);
    for (int c = threadIdx.x; c < NKP; c += blockDim.x) {
        float L = 0.f;
        if (c < NN) {
            float ec = rsqrtf(g_rs0[br*NN + c]);
            L = ((r == c) ? 1.f : 0.f) - er * g_A[(size_t)br*NN*NN + (size_t)r*NN + c] * ec;
        }
        g_Lh[(size_t)br*NKP*NKP + (size_t)r*NKP + c] = __float2half_rn(L);
    }
}

// ------------------------- layout / split kernels -------------------------
__global__ void xsplitT(const float* __restrict__ x) {
    __shared__ float s[64*121];
    int bt = blockIdx.x;
    for (int n0 = 0; n0 < NN; n0 += 64) {
        int nrows = (NN - n0 < 64) ? (NN - n0) : 64;
        for (int i = threadIdx.x; i < nrows*DD; i += 256) {
            int nn = i / DD, d = i - nn*DD;
            s[nn*121 + d] = x[((size_t)bt*NN + n0 + nn)*DD + d];
        }
        __syncthreads();
        for (int i = threadIdx.x; i < DD*64; i += 256) {
            int d = i >> 6, nn = i & 63;
            int n = n0 + nn;
            if (nn < nrows) {
                __half h, l; hsplit(s[nn*121 + d], h, l);
                size_t idx = ((size_t)bt*DD + d)*NKP + n;
                g_xth[idx] = h; g_xtl[idx] = l;
            }
        }
        __syncthreads();
    }
}
// x -> cols [0,120) of all three branch xcat buffers (hi only)
__global__ void pack_x(const float* __restrict__ x) {
    size_t r = blockIdx.x;
    int d = threadIdx.x;
    if (d < DD) {
        __half h = __float2half_rn(x[r*DD + d]);
        #pragma unroll
        for (int br = 0; br < 3; br++)
            g_xcath[(size_t)br*MTOK*XK + r*XK + d] = h;
    }
}
// transpose+split; dl==nullptr -> hi only
__global__ void wsplit(const float* __restrict__ src, __half* __restrict__ dh,
                       __half* __restrict__ dl, int K, int N, int ldk,
                       long src_bstride, long dst_bstride) {
    int n = blockIdx.x;
    int br = blockIdx.y;
    src += (size_t)br * src_bstride;
    dh  += (size_t)br * dst_bstride;
    if (dl) dl += (size_t)br * dst_bstride;
    for (int k = threadIdx.x; k < K; k += blockDim.x) {
        __half h, l; hsplit(src[(size_t)k*N + n], h, l);
        dh[(size_t)n*ldk + k] = h;
        if (dl) dl[(size_t)n*ldk + k] = l;
    }
}

// ------------------------- attention -------------------------
__global__ void attn_kernel(const float* __restrict__ q, const float* __restrict__ k,
                            const float* __restrict__ v) {
    int bn = blockIdx.x;
    int b = bn / NN, n = bn % NN;
    __shared__ float qs[TT][DD], ks[TT][DD], vs[TT][DD];
    for (int i = threadIdx.x; i < TT*DD; i += blockDim.x) {
        int t = i / DD, d = i % DD;
        size_t gi = (((size_t)(b*TT + t))*NN + n)*DD + d;
        qs[t][d] = q[gi]; ks[t][d] = k[gi]; vs[t][d] = v[gi];
    }
    __syncthreads();
    int tid = threadIdx.x;
    if (tid < HH*TT) {
        int h = tid / TT, qi = tid % TT;
        const float scale = rsqrtf((float)HD);
        float s[TT]; float mx = -1e30f;
        #pragma unroll
        for (int j = 0; j < TT; j++) {
            float acc = 0.f;
            #pragma unroll
            for (int e = 0; e < HD; e++) acc += qs[qi][h*HD+e] * ks[j][h*HD+e];
            acc *= scale; s[j] = acc; mx = fmaxf(mx, acc);
        }
        float sum = 0.f;
        #pragma unroll
        for (int j = 0; j < TT; j++) { s[j] = expf(s[j]-mx); sum += s[j]; }
        float inv = 1.f / sum;
        size_t orow = ((size_t)(b*TT + qi))*NN + n;
        #pragma unroll
        for (int e = 0; e < HD; e++) {
            float acc = 0.f;
            #pragma unroll
            for (int j = 0; j < TT; j++) acc += s[j] * vs[j][h*HD+e];
            g_oah[orow*128 + h*HD + e] = __float2half_rn(acc * inv);
        }
    }
}

// ------------------------- residual + layernorm -------------------------
__global__ void ln_kernel(const float* __restrict__ xa, const float* __restrict__ xb,
                          const float* __restrict__ gg, const float* __restrict__ bb,
                          float* __restrict__ outp, __half* __restrict__ oh) {
    int warp = threadIdx.x >> 5, lane = threadIdx.x & 31;
    size_t m = (size_t)blockIdx.x * 4 + warp;
    if (m >= MTOK) return;
    size_t ia = m * DD;
    float v[4]; float s = 0.f;
    #pragma unroll
    for (int i = 0; i < 4; i++) {
        int d = lane + 32*i;
        float val = (d < DD) ? (xa[ia+d] + xb[ia+d]) : 0.f;
        v[i] = val; s += val;
    }
    #pragma unroll
    for (int o = 16; o > 0; o >>= 1) s += __shfl_xor_sync(0xffffffffu, s, o);
    float mean = s * (1.f / DD);
    float vsum = 0.f;
    #pragma unroll
    for (int i = 0; i < 4; i++) {
        int d = lane + 32*i;
        if (d < DD) { float df = v[i]-mean; vsum += df*df; }
    }
    #pragma unroll
    for (int o = 16; o > 0; o >>= 1) vsum += __shfl_xor_sync(0xffffffffu, vsum, o);
    float inv = rsqrtf(vsum * (1.f / DD) + 1e-5f);
    #pragma unroll
    for (int i = 0; i < 4; i++) {
        int d = lane + 32*i;
        if (d < DD) {
            float o = (v[i]-mean)*inv*gg[d] + bb[d];
            if (outp) outp[ia + d] = o;
            if (oh) oh[m*128 + d] = __float2half_rn(o);
        }
    }
}

// ------------------------- launch -------------------------
extern "C" void kernel_launch(void* const* d_in, const int* in_sizes, int n_in,
                              void* d_out, int out_size) {
    const float* x       = (const float*)d_in[0];
    const float* adj     = (const float*)d_in[1];
    const float* gl_beta = (const float*)d_in[2];
    const float* gl_w1   = (const float*)d_in[3];
    const float* gl_w2   = (const float*)d_in[4];
    const float* gl_cw   = (const float*)d_in[5];
    const float* gl_cb   = (const float*)d_in[6];
    const float* cheb_w  = (const float*)d_in[7];
    const float* cheb_b  = (const float*)d_in[8];
    const float* out_w   = (const float*)d_in[9];
    const float* out_b   = (const float*)d_in[10];
    const float* ff_w1   = (const float*)d_in[11];
    const float* ff_b1   = (const float*)d_in[12];
    const float* ff_w2   = (const float*)d_in[13];
    const float* ff_b2   = (const float*)d_in[14];
    const float* ln1_g   = (const float*)d_in[15];
    const float* ln1_b   = (const float*)d_in[16];
    const float* ln2_g   = (const float*)d_in[17];
    const float* ln2_b   = (const float*)d_in[18];
    float* outp = (float*)d_out;

    const int SMEM128_2_32 = 2 * ((128*5) + 2*(128*5)) * 16;  // 61440 (oproj)
    const int SMEM128_1_32 = 2 * ((128*5) + 1*(128*5)) * 16;  // 40960 (QKV/FFN)
    const int SMEM64_1_32  = 33792;   // stages 2x15360=30720; fp32 scatter needs 33792
    cudaFuncSetAttribute(hmma_fp16<128,2,32>, cudaFuncAttributeMaxDynamicSharedMemorySize, SMEM128_2_32);
    cudaFuncSetAttribute(hmma_fp16<128,1,32>, cudaFuncAttributeMaxDynamicSharedMemorySize, SMEM128_1_32);
    cudaFuncSetAttribute(hmma_fp16<64,1,32>,  cudaFuncAttributeMaxDynamicSharedMemorySize, SMEM64_1_32);

    __half *pLh, *pxth, *pxtl, *pt1h;
    __half *pxch, *poah, *po1h, *phh;
    __half *pwqh, *powh, *powl, *pw1h, *pw2h;
    float *pqkv, *poproj, *pout1f, *pffnf;
    cudaGetSymbolAddress((void**)&pLh, g_Lh);
    cudaGetSymbolAddress((void**)&pxth, g_xth); cudaGetSymbolAddress((void**)&pxtl, g_xtl);
    cudaGetSymbolAddress((void**)&pt1h, g_t1h);
    cudaGetSymbolAddress((void**)&pxch, g_xcath);
    cudaGetSymbolAddress((void**)&poah, g_oah);
    cudaGetSymbolAddress((void**)&po1h, g_o1h);
    cudaGetSymbolAddress((void**)&phh, g_hidh);
    cudaGetSymbolAddress((void**)&pwqh, g_wqh);
    cudaGetSymbolAddress((void**)&powh, g_owh); cudaGetSymbolAddress((void**)&powl, g_owl);
    cudaGetSymbolAddress((void**)&pw1h, g_w1h);
    cudaGetSymbolAddress((void**)&pw2h, g_w2h);
    cudaGetSymbolAddress((void**)&pqkv, g_qkv); cudaGetSymbolAddress((void**)&poproj, g_oproj);
    cudaGetSymbolAddress((void**)&pout1f, g_out1f); cudaGetSymbolAddress((void**)&pffnf, g_ffnf);

    // graph learning
    dim3 gG(NN, 3);
    gk1<<<gG, 256>>>(gl_w1, gl_w2, gl_beta, gl_cw, gl_cb, adj);
    gk2<<<gG, 256>>>();
    gk3<<<gG, 256>>>();
    gk4<<<gG, 256>>>();

    // layout + weight prep
    xsplitT<<<BT, 256>>>(x);
    pack_x<<<MTOK, 128>>>(x);
    wsplit<<<dim3(120,3), 256>>>(cheb_w, pwqh, nullptr, 360, 120, XK, (long)360*120, (long)128*XK);
    wsplit<<<dim3(120,1), 256>>>(out_w, powh, powl, 120, 120, 128, 0, 0);
    wsplit<<<dim3(FF,1),  256>>>(ff_w1, pw1h, nullptr, 120, FF, 128, 0, 0);
    wsplit<<<dim3(120,1), 256>>>(ff_w2, pw2h, nullptr, FF, 120, FF, 0, 0);

    const long t1s = (long)MSP*NKP;
    const long xcs = (long)MTOK*XK;
    const long Ls  = (long)NKP*NKP;

    // batched spatial t1 = L_br @ x (1-pass, BK=32) -> t1_br (hi) + xcat_br[120..239]
    dim3 gsp(MSP/128, 3, 3);
    hmma_fp16<64,1,32><<<gsp, 256, SMEM64_1_32>>>(pxth, NKP, pLh, nullptr, NKP, NKP,
                                                  nullptr, pt1h, NKP, NN,
                                                  nullptr, 0, nullptr, nullptr,
                                                  pxch, 120,
                                                  0, Ls, t1s, 0, xcs, 0);
    // batched spatial t2 = 2*(L_br @ t1_br) - x (1-pass, BK=32) -> xcat_br[240..359]
    hmma_fp16<64,1,32><<<gsp, 256, SMEM64_1_32>>>(pt1h, NKP, pLh, nullptr, NKP, NKP,
                                                  nullptr, nullptr, NKP, NN,
                                                  nullptr, FLAG_T2, pxth, pxtl,
                                                  pxch, 240,
                                                  t1s, Ls, 0, 0, xcs, 0);

    // batched QKV (1-pass, BK=32): relu(xcat_br @ Wh_br + b_br), K=384
    dim3 gqkv(MTOK/128, 1, 3);
    hmma_fp16<128,1,32><<<gqkv, 256, SMEM128_1_32>>>(pxch, XK, pwqh, nullptr, XK, XK,
                                                     pqkv, nullptr, DD, DD,
                                                     cheb_b, FLAG_BIAS | FLAG_RELU,
                                                     nullptr, nullptr, nullptr, 0,
                                                     xcs, (long)128*XK, (long)MTOK*DD, DD, 0, 0);

    attn_kernel<<<BB*NN, 128>>>(pqkv, pqkv + (size_t)MTOK*DD, pqkv + (size_t)2*MTOK*DD);

    dim3 gch(MTOK/128, 1, 1);
    // output projection (2-pass, BK=32)
    hmma_fp16<128,2,32><<<gch, 256, SMEM128_2_32>>>(poah, 128, powh, powl, 128, 128,
                                                    poproj, nullptr, DD, DD,
                                                    out_b, FLAG_BIAS, nullptr, nullptr,
                                                    nullptr, 0, 0, 0, 0, 0, 0, 0);
    // LN1 (fp32 out + fp16 hi)
    ln_kernel<<<MTOK/4, 128>>>(x, poproj, ln1_g, ln1_b, pout1f, po1h);

    // FFN1 (1-pass, BK=32) -> hidden fp16 hi; swapped grid for A reuse
    dim3 gf1(FF/128, MTOK/128, 1);
    hmma_fp16<128,1,32><<<gf1, 256, SMEM128_1_32>>>(po1h, 128, pw1h, nullptr, 128, 128,
                                                    nullptr, phh, FF, FF,
                                                    ff_b1, FLAG_BIAS | FLAG_RELU, nullptr, nullptr,
                                                    nullptr, 0, 0, 0, 0, 0, 0, 1);
    // FFN2 (1-pass, BK=32)
    hmma_fp16<128,1,32><<<gch, 256, SMEM128_1_32>>>(phh, FF, pw2h, nullptr, FF, FF,
                                                    pffnf, nullptr, DD, DD,
                                                    ff_b2, FLAG_BIAS, nullptr, nullptr,
                                                    nullptr, 0, 0, 0, 0, 0, 0, 0);
    // LN2 -> output
    ln_kernel<<<MTOK/4, 128>>>(pout1f, pffnf, ln2_g, ln2_b, outp, nullptr);
}